// round 7
// baseline (speedup 1.0000x reference)
#include <cuda_runtime.h>
#include <cuda_bf16.h>
#include <cstdint>

#define Bn 8
#define Cc 256
#define Hh 128
#define Wn 128
#define HWn (Hh*Wn)

// Packed-split bf16 convention: uint32 = (lo<<16)|hi, value = hi + lo.
__device__ uint32_t g_Wp[320*256];               // [q32;k32;v256] rows, packed
__device__ float    g_bs[320];
__device__ uint32_t g_qhw[(size_t)Bn*HWn*32];    // [b][h][w][o] packed q
__device__ uint32_t g_qwh[(size_t)Bn*HWn*32];    // [b][w][h][o]
__device__ uint32_t g_khw[(size_t)Bn*HWn*32];
__device__ uint32_t g_kwh[(size_t)Bn*HWn*32];
__device__ float    g_va[(size_t)Bn*Cc*HWn];     // [b][c][h][w] fp32 v
__device__ float    g_vb[(size_t)Bn*Cc*HWn];     // [b][c][w][h]
__device__ float    g_eH[(size_t)Bn*HWn*Hh];     // [b][w][h][g]
__device__ float    g_eW[(size_t)Bn*HWn*Wn];     // [b][h][w][g]
__device__ float    g_oH[(size_t)Bn*HWn*Cc];     // [b][w][h][c]

__device__ __forceinline__ float neg_inf_f() { return __int_as_float(0xff800000); }
__device__ __forceinline__ float tf32r(float f) {
    uint32_t u; asm("cvt.rna.tf32.f32 %0, %1;" : "=r"(u) : "f"(f));
    return __uint_as_float(u);
}
__device__ __forceinline__ uint32_t splitf(float f) {
    __nv_bfloat16 h = __float2bfloat16(f);
    __nv_bfloat16 l = __float2bfloat16(f - __bfloat162float(h));
    return (uint32_t)__bfloat16_as_ushort(h) | ((uint32_t)__bfloat16_as_ushort(l) << 16);
}
// Two packed elems (k,k+1) -> hi-pair word, lo-pair word.
__device__ __forceinline__ void unzip(uint2 p, uint32_t& hi, uint32_t& lo) {
    asm("prmt.b32 %0, %1, %2, 0x5410;" : "=r"(hi) : "r"(p.x), "r"(p.y));
    asm("prmt.b32 %0, %1, %2, 0x7632;" : "=r"(lo) : "r"(p.x), "r"(p.y));
}
__device__ __forceinline__ void mma16(float* d, uint32_t a0, uint32_t a1, uint32_t a2,
                                      uint32_t a3, uint32_t b0, uint32_t b1) {
    asm volatile("mma.sync.aligned.m16n8k16.row.col.f32.bf16.bf16.f32 "
                 "{%0,%1,%2,%3},{%4,%5,%6,%7},{%8,%9},{%0,%1,%2,%3};"
                 : "+f"(d[0]), "+f"(d[1]), "+f"(d[2]), "+f"(d[3])
                 : "r"(a0), "r"(a1), "r"(a2), "r"(a3), "r"(b0), "r"(b1));
}
__device__ __forceinline__ void mma8(float* d, const float* a, const float* b) {
    asm volatile("mma.sync.aligned.m16n8k8.row.col.f32.tf32.tf32.f32 "
                 "{%0,%1,%2,%3},{%4,%5,%6,%7},{%8,%9},{%0,%1,%2,%3};"
                 : "+f"(d[0]), "+f"(d[1]), "+f"(d[2]), "+f"(d[3])
                 : "r"(__float_as_uint(a[0])), "r"(__float_as_uint(a[1])),
                   "r"(__float_as_uint(a[2])), "r"(__float_as_uint(a[3])),
                   "r"(__float_as_uint(b[0])), "r"(__float_as_uint(b[1])));
}

// 3-pass split product into acc.
#define MMA3(acc, ah, al, bh, bl) do { \
    mma16(acc, ah[0], ah[1], ah[2], ah[3], bh##0, bh##1); \
    mma16(acc, ah[0], ah[1], ah[2], ah[3], bl##0, bl##1); \
    mma16(acc, al[0], al[1], al[2], al[3], bh##0, bh##1); } while (0)

// prep: pack W rows [Wq;Wk;Wv]. grid 320, block 256.
__global__ __launch_bounds__(256) void prep_kernel(
    const float* __restrict__ Wq, const float* __restrict__ bq,
    const float* __restrict__ Wk, const float* __restrict__ bk,
    const float* __restrict__ Wv, const float* __restrict__ bv)
{
    const int r = blockIdx.x, t = threadIdx.x;
    const float* src; const float* bsrc; int o;
    if (r < 32)      { src = Wq; bsrc = bq; o = r; }
    else if (r < 64) { src = Wk; bsrc = bk; o = r - 32; }
    else             { src = Wv; bsrc = bv; o = r - 64; }
    g_Wp[r*256 + t] = splitf(src[o*256 + t]);
    if (t == 0) g_bs[r] = bsrc[o];
}

// proj: per (b,h,mt): D[64 oc x 128 px(w)] = W_mt(64x256) @ x(256x128).
// A = W packed rows; B = x fp32, split in loader. grid (640, 8): mt fastest.
__global__ __launch_bounds__(256) void proj_mma(const float* __restrict__ x)
{
    __shared__ __align__(16) uint32_t sm[8704];  // As[64][36]@0, Bs[128][34]@2304; tb[128][68]@0
    __shared__ float s_bias[64];
    const int t = threadIdx.x, wid = t >> 5, lane = t & 31;
    const int g8 = lane >> 2, tig = lane & 3;
    const int warp_m = wid & 1, warp_n = wid >> 1;
    const int mt = blockIdx.x % 5, h = blockIdx.x / 5, b = blockIdx.y;
    if (t < 64) s_bias[t] = g_bs[mt*64 + t];

    float acc[2][4][4] = {};
    for (int kc = 0; kc < 8; kc++) {
        uint4 aR[2]; float4 bR[4];
        #pragma unroll
        for (int i = 0; i < 2; i++) {
            const int idx = i*256 + t, r = idx >> 3, kq = (idx & 7)*4;
            aR[i] = *(const uint4*)(g_Wp + (size_t)(mt*64 + r)*256 + kc*32 + kq);
        }
        #pragma unroll
        for (int i = 0; i < 4; i++) {
            const int idx = i*256 + t, r = idx >> 5, p4 = (idx & 31)*4;
            bR[i] = *(const float4*)(x + ((size_t)(b*Cc + kc*32 + r))*HWn + h*128 + p4);
        }
        __syncthreads();
        #pragma unroll
        for (int i = 0; i < 2; i++) {
            const int idx = i*256 + t, r = idx >> 3, kq = (idx & 7)*4;
            *(uint4*)&sm[r*36 + kq] = aR[i];
        }
        #pragma unroll
        for (int i = 0; i < 4; i++) {
            const int idx = i*256 + t, r = idx >> 5, p4 = (idx & 31)*4;
            sm[2304 + (p4+0)*34 + r] = splitf(bR[i].x);
            sm[2304 + (p4+1)*34 + r] = splitf(bR[i].y);
            sm[2304 + (p4+2)*34 + r] = splitf(bR[i].z);
            sm[2304 + (p4+3)*34 + r] = splitf(bR[i].w);
        }
        __syncthreads();
        #pragma unroll
        for (int ks = 0; ks < 2; ks++) {
            const int k0 = ks*16;
            uint32_t ah[2][4], al[2][4];
            #pragma unroll
            for (int mi = 0; mi < 2; mi++) {
                const int m = warp_m*32 + mi*16;
                unzip(*(uint2*)&sm[(m+g8  )*36 + k0 + 2*tig],     ah[mi][0], al[mi][0]);
                unzip(*(uint2*)&sm[(m+g8+8)*36 + k0 + 2*tig],     ah[mi][1], al[mi][1]);
                unzip(*(uint2*)&sm[(m+g8  )*36 + k0 + 8 + 2*tig], ah[mi][2], al[mi][2]);
                unzip(*(uint2*)&sm[(m+g8+8)*36 + k0 + 8 + 2*tig], ah[mi][3], al[mi][3]);
            }
            #pragma unroll
            for (int ni = 0; ni < 4; ni++) {
                const int n = warp_n*32 + ni*8 + g8;
                uint32_t bh0, bl0, bh1, bl1;
                unzip(*(uint2*)&sm[2304 + n*34 + k0 + 2*tig],     bh0, bl0);
                unzip(*(uint2*)&sm[2304 + n*34 + k0 + 8 + 2*tig], bh1, bl1);
                #pragma unroll
                for (int mi = 0; mi < 2; mi++) MMA3(acc[mi][ni], ah[mi], al[mi], bh, bl);
            }
        }
        __syncthreads();
    }

    if (mt == 0) {
        // q/k: pack + smem transpose -> [px][o] packed dual layouts.
        #pragma unroll
        for (int mi = 0; mi < 2; mi++)
            #pragma unroll
            for (int ni = 0; ni < 4; ni++) {
                const int oc = warp_m*32 + mi*16 + g8;
                const int n  = warp_n*32 + ni*8 + tig*2;
                const float b0 = s_bias[oc], b8 = s_bias[oc+8];
                sm[n*68 + oc]        = splitf(acc[mi][ni][0] + b0);
                sm[(n+1)*68 + oc]    = splitf(acc[mi][ni][1] + b0);
                sm[n*68 + oc + 8]    = splitf(acc[mi][ni][2] + b8);
                sm[(n+1)*68 + oc + 8]= splitf(acc[mi][ni][3] + b8);
            }
        __syncthreads();
        const int px = t >> 1, half = t & 1;
        uint32_t* dhw = (half ? g_khw : g_qhw) + ((size_t)(b*Hh + h)*Wn + px)*32;
        uint32_t* dwh = (half ? g_kwh : g_qwh) + ((size_t)(b*Wn + px)*Hh + h)*32;
        #pragma unroll
        for (int j = 0; j < 8; j++) {
            uint4 v = *(uint4*)&sm[px*68 + half*32 + j*4];
            *(uint4*)(dhw + j*4) = v;
            *(uint4*)(dwh + j*4) = v;
        }
    } else {
        // v: direct fp32 [c][px] stores (rows of g_va, 32B sectors per quad).
        const int cbase = mt*64 - 64;
        #pragma unroll
        for (int mi = 0; mi < 2; mi++)
            #pragma unroll
            for (int ni = 0; ni < 4; ni++) {
                const int oc = warp_m*32 + mi*16 + g8;
                const int n  = warp_n*32 + ni*8 + tig*2;
                const float b0 = s_bias[oc], b8 = s_bias[oc+8];
                float* r0 = g_va + ((size_t)(b*Cc + cbase + oc))*HWn + h*128 + n;
                float* r8 = r0 + 8*HWn;
                *(float2*)r0 = make_float2(acc[mi][ni][0] + b0, acc[mi][ni][1] + b0);
                *(float2*)r8 = make_float2(acc[mi][ni][2] + b8, acc[mi][ni][3] + b8);
            }
    }
}

// vb: g_va[b][c][h][w] -> g_vb[b][c][w][h]. grid (4,4,2048), block 256.
__global__ __launch_bounds__(256) void vb_kernel()
{
    __shared__ float tl[32][33];
    const int bc = blockIdx.z, w0 = blockIdx.x*32, h0 = blockIdx.y*32;
    const int tx = threadIdx.x & 31, ty = threadIdx.x >> 5;
    #pragma unroll
    for (int i = 0; i < 4; i++)
        tl[ty + i*8][tx] = g_va[((size_t)bc*Hh + h0 + ty + i*8)*Wn + w0 + tx];
    __syncthreads();
    #pragma unroll
    for (int i = 0; i < 4; i++)
        g_vb[((size_t)bc*Wn + w0 + ty + i*8)*Hh + h0 + tx] = tl[tx][ty + i*8];
}

// score<ISH>: D[128 x 128] = Q @ K^T (K=32), bf16 3-pass. grid 1024, block 256.
template <bool ISH>
__global__ __launch_bounds__(256) void score_mma()
{
    __shared__ __align__(16) uint32_t Qs[128][36], Ks[128][36];
    const int bs = blockIdx.x, t = threadIdx.x;
    const int wid = t >> 5, lane = t & 31, g8 = lane >> 2, tig = lane & 3;
    const int warp_m = wid & 3, warp_n = wid >> 2;
    const uint32_t* Q = (ISH ? g_qwh : g_qhw) + (size_t)bs*128*32;
    const uint32_t* K = (ISH ? g_kwh : g_khw) + (size_t)bs*128*32;
    float* O = (ISH ? g_eH : g_eW) + (size_t)bs*128*128;

    #pragma unroll
    for (int i = 0; i < 4; i++) {
        const int idx = i*256 + t, r = idx >> 3, kq = (idx & 7)*4;
        *(uint4*)&Qs[r][kq] = *(const uint4*)(Q + (size_t)r*32 + kq);
        *(uint4*)&Ks[r][kq] = *(const uint4*)(K + (size_t)r*32 + kq);
    }
    __syncthreads();

    float acc[2][8][4] = {};
    #pragma unroll
    for (int ks = 0; ks < 2; ks++) {
        const int k0 = ks*16;
        uint32_t ah[2][4], al[2][4];
        #pragma unroll
        for (int mi = 0; mi < 2; mi++) {
            const int m = warp_m*32 + mi*16;
            unzip(*(uint2*)&Qs[m+g8  ][k0 + 2*tig],     ah[mi][0], al[mi][0]);
            unzip(*(uint2*)&Qs[m+g8+8][k0 + 2*tig],     ah[mi][1], al[mi][1]);
            unzip(*(uint2*)&Qs[m+g8  ][k0 + 8 + 2*tig], ah[mi][2], al[mi][2]);
            unzip(*(uint2*)&Qs[m+g8+8][k0 + 8 + 2*tig], ah[mi][3], al[mi][3]);
        }
        #pragma unroll
        for (int ni = 0; ni < 8; ni++) {
            const int n = warp_n*64 + ni*8 + g8;
            uint32_t bh0, bl0, bh1, bl1;
            unzip(*(uint2*)&Ks[n][k0 + 2*tig],     bh0, bl0);
            unzip(*(uint2*)&Ks[n][k0 + 8 + 2*tig], bh1, bl1);
            #pragma unroll
            for (int mi = 0; mi < 2; mi++) MMA3(acc[mi][ni], ah[mi], al[mi], bh, bl);
        }
    }
    #pragma unroll
    for (int mi = 0; mi < 2; mi++)
        #pragma unroll
        for (int ni = 0; ni < 8; ni++) {
            const int n = warp_n*64 + ni*8 + tig*2;
            #pragma unroll
            for (int half = 0; half < 2; half++) {
                const int m = warp_m*32 + mi*16 + g8 + half*8;
                float d0 = acc[mi][ni][half*2], d1 = acc[mi][ni][half*2+1];
                if (ISH) { if (n == m) d0 = neg_inf_f(); if (n+1 == m) d1 = neg_inf_f(); }
                *(float2*)(O + (size_t)m*128 + n) = make_float2(d0, d1);
            }
        }
}

// softmax: joint 256-way per pixel, in place. grid 16384, block 256.
__global__ __launch_bounds__(256) void softmax_kernel()
{
    const int wid = blockIdx.x*8 + (threadIdx.x >> 5), lane = threadIdx.x & 31;
    const int b = wid >> 14, hw = wid & 16383, h = hw >> 7, w = hw & 127;
    float* pH = g_eH + ((size_t)(b*Wn + w)*Hh + h)*Hh;
    float* pW = g_eW + ((size_t)(b*Hh + h)*Wn + w)*Wn;
    float4 vh = *(float4*)(pH + lane*4);
    float4 vw = *(float4*)(pW + lane*4);
    float m = fmaxf(fmaxf(fmaxf(vh.x,vh.y),fmaxf(vh.z,vh.w)),
                    fmaxf(fmaxf(vw.x,vw.y),fmaxf(vw.z,vw.w)));
    #pragma unroll
    for (int off = 16; off; off >>= 1) m = fmaxf(m, __shfl_xor_sync(~0u, m, off));
    vh.x=__expf(vh.x-m); vh.y=__expf(vh.y-m); vh.z=__expf(vh.z-m); vh.w=__expf(vh.w-m);
    vw.x=__expf(vw.x-m); vw.y=__expf(vw.y-m); vw.z=__expf(vw.z-m); vw.w=__expf(vw.w-m);
    float s = vh.x+vh.y+vh.z+vh.w+vw.x+vw.y+vw.z+vw.w;
    #pragma unroll
    for (int off = 16; off; off >>= 1) s += __shfl_xor_sync(~0u, s, off);
    const float inv = 1.f/s;
    vh.x*=inv; vh.y*=inv; vh.z*=inv; vh.w*=inv;
    vw.x*=inv; vw.y*=inv; vw.z*=inv; vw.w*=inv;
    *(float4*)(pH + lane*4) = vh;
    *(float4*)(pW + lane*4) = vw;
}

// out<ISH>: per (b,s,chalf): D[128 spatial x 128 c] = att @ v^T (tf32 1-pass).
// ISH: write g_oH. !ISH: fused gamma*(D + oH) + x -> out. grid (2,1024), block 256.
template <bool ISH>
__global__ __launch_bounds__(256) void out_mma(const float* __restrict__ x,
                                               const float* __restrict__ gamma,
                                               float* __restrict__ out)
{
    __shared__ __align__(16) float pool[9216];   // As2[128][36]@0, Bs2@4608; tb[64][132] union
    const int t = threadIdx.x, wid = t >> 5, lane = t & 31;
    const int g8 = lane >> 2, tig = lane & 3;
    const int warp_m = wid & 3, warp_n = wid >> 2;
    const int bs = blockIdx.y, b = bs >> 7, s = bs & 127;
    const int c0 = blockIdx.x * 128;
    const float* A = (ISH ? g_eH : g_eW) + (size_t)bs*16384;
    const float* V = (ISH ? g_vb : g_va) + (size_t)b*Cc*HWn + (size_t)s*Wn;

    float acc[2][8][4] = {};
    const int ar = t >> 1, akq = (t & 1)*16;
    for (int kc = 0; kc < 4; kc++) {
        float4 av[4], bv[4];
        #pragma unroll
        for (int i = 0; i < 4; i++) {
            av[i] = *(const float4*)(A + (size_t)ar*128 + kc*32 + akq + i*4);
            bv[i] = *(const float4*)(V + (size_t)(c0 + ar)*HWn + kc*32 + akq + i*4);
        }
        __syncthreads();
        #pragma unroll
        for (int i = 0; i < 4; i++) {
            float* As2 = pool + ar*36 + akq + i*4;
            float* Bs2 = pool + 4608 + ar*36 + akq + i*4;
            As2[0]=tf32r(av[i].x); As2[1]=tf32r(av[i].y); As2[2]=tf32r(av[i].z); As2[3]=tf32r(av[i].w);
            Bs2[0]=tf32r(bv[i].x); Bs2[1]=tf32r(bv[i].y); Bs2[2]=tf32r(bv[i].z); Bs2[3]=tf32r(bv[i].w);
        }
        __syncthreads();
        #pragma unroll
        for (int kk = 0; kk < 4; kk++) {
            const int k0 = kk*8;
            float a[2][4];
            #pragma unroll
            for (int mi = 0; mi < 2; mi++) {
                const int m0 = warp_m*32 + mi*16;
                a[mi][0] = pool[(m0+g8  )*36 + k0+tig];
                a[mi][1] = pool[(m0+g8+8)*36 + k0+tig];
                a[mi][2] = pool[(m0+g8  )*36 + k0+tig+4];
                a[mi][3] = pool[(m0+g8+8)*36 + k0+tig+4];
            }
            #pragma unroll
            for (int ni = 0; ni < 8; ni++) {
                const int nn = warp_n*64 + ni*8 + g8;
                float bf[2] = {pool[4608 + nn*36 + k0+tig], pool[4608 + nn*36 + k0+tig+4]};
                #pragma unroll
                for (int mi = 0; mi < 2; mi++) mma8(acc[mi][ni], a[mi], bf);
            }
        }
    }

    if (ISH) {
        float* O = g_oH + (size_t)bs*128*Cc;
        #pragma unroll
        for (int mi = 0; mi < 2; mi++)
            #pragma unroll
            for (int ni = 0; ni < 8; ni++) {
                const int m = warp_m*32 + mi*16 + g8;
                const int n = c0 + warp_n*64 + ni*8 + tig*2;
                *(float2*)(O + (size_t)m*Cc + n)     = make_float2(acc[mi][ni][0], acc[mi][ni][1]);
                *(float2*)(O + (size_t)(m+8)*Cc + n) = make_float2(acc[mi][ni][2], acc[mi][ni][3]);
            }
    } else {
        // fused: out[b][c][h=s][w] = gm*(D[w][c] + oH[b][w][s][c]) + x
        const float gm = gamma[0];
        #pragma unroll
        for (int ch = 0; ch < 2; ch++) {
            __syncthreads();
            if (warp_n == ch) {
                #pragma unroll
                for (int mi = 0; mi < 2; mi++)
                    #pragma unroll
                    for (int ni = 0; ni < 8; ni++) {
                        const int m  = warp_m*32 + mi*16 + g8;
                        const int nl = ni*8 + tig*2;
                        const int ng = c0 + ch*64 + nl;
                        float2 o1 = *(const float2*)(g_oH + ((size_t)(b*Wn + m)*Hh + s)*Cc + ng);
                        float2 o2 = *(const float2*)(g_oH + ((size_t)(b*Wn + m+8)*Hh + s)*Cc + ng);
                        pool[nl*132 + m]       = acc[mi][ni][0] + o1.x;
                        pool[(nl+1)*132 + m]   = acc[mi][ni][1] + o1.y;
                        pool[nl*132 + m+8]     = acc[mi][ni][2] + o2.x;
                        pool[(nl+1)*132 + m+8] = acc[mi][ni][3] + o2.y;
                    }
            }
            __syncthreads();
            const int c = t >> 2, w4 = (t & 3)*32;
            const size_t oidx = ((size_t)(b*Cc + c0 + ch*64 + c)*Hh + s)*Wn + w4;
            #pragma unroll
            for (int i = 0; i < 32; i += 4) {
                float4 xr = *(const float4*)(x + oidx + i);
                float4 r;
                r.x = gm*pool[c*132 + w4+i  ] + xr.x;
                r.y = gm*pool[c*132 + w4+i+1] + xr.y;
                r.z = gm*pool[c*132 + w4+i+2] + xr.z;
                r.w = gm*pool[c*132 + w4+i+3] + xr.w;
                *(float4*)(out + oidx + i) = r;
            }
        }
    }
}

extern "C" void kernel_launch(void* const* d_in, const int* in_sizes, int n_in,
                              void* d_out, int out_size)
{
    const float* x     = (const float*)d_in[0];
    const float* Wq    = (const float*)d_in[1];
    const float* bq    = (const float*)d_in[2];
    const float* Wk    = (const float*)d_in[3];
    const float* bk    = (const float*)d_in[4];
    const float* Wv    = (const float*)d_in[5];
    const float* bv    = (const float*)d_in[6];
    const float* gamma = (const float*)d_in[7];
    float* out = (float*)d_out;

    prep_kernel<<<320, 256>>>(Wq, bq, Wk, bk, Wv, bv);
    proj_mma<<<dim3(640, Bn), 256>>>(x);
    vb_kernel<<<dim3(4, 4, 2048), 256>>>();
    score_mma<true ><<<1024, 256>>>();
    score_mma<false><<<1024, 256>>>();
    softmax_kernel<<<16384, 256>>>();
    out_mma<true ><<<dim3(2, 1024), 256>>>(x, gamma, out);
    out_mma<false><<<dim3(2, 1024), 256>>>(x, gamma, out);
}

// round 8
// speedup vs baseline: 1.1360x; 1.1360x over previous
#include <cuda_runtime.h>
#include <cuda_bf16.h>
#include <cstdint>

#define Bn 8
#define Cc 256
#define CQn 32
#define Hh 128
#define Wn 128
#define HWn (Hh*Wn)

__device__ __nv_bfloat16 g_Wh[320*256], g_Wl[320*256];   // split W rows: [q32;k32;v256]
__device__ float g_bs[320];
__device__ __nv_bfloat16 g_xh[(size_t)Bn*HWn*Cc], g_xl[(size_t)Bn*HWn*Cc]; // [b][p][c]
__device__ float g_q_hw[(size_t)Bn*HWn*CQn], g_q_wh[(size_t)Bn*HWn*CQn];
__device__ float g_k_hw[(size_t)Bn*HWn*CQn], g_k_wh[(size_t)Bn*HWn*CQn];
__device__ float g_va[(size_t)Bn*Cc*HWn];   // [b][c][h][w]
__device__ float g_vb[(size_t)Bn*Cc*HWn];   // [b][c][w][h]
__device__ float g_eH[(size_t)Bn*Wn*Hh*Hh]; // [b][w][h][g]
__device__ float g_eW[(size_t)Bn*Hh*Wn*Wn]; // [b][h][w][g]
__device__ float g_oH[(size_t)Bn*HWn*Cc];   // [b][w][h][c]

__device__ __forceinline__ float neg_inf_f() { return __int_as_float(0xff800000); }
__device__ __forceinline__ float tf32r(float f) {
    uint32_t u; asm("cvt.rna.tf32.f32 %0, %1;" : "=r"(u) : "f"(f));
    return __uint_as_float(u);
}
__device__ __forceinline__ uint32_t splitf(float f) {
    __nv_bfloat16 h = __float2bfloat16(f);
    __nv_bfloat16 l = __float2bfloat16(f - __bfloat162float(h));
    return (uint32_t)__bfloat16_as_ushort(h) | ((uint32_t)__bfloat16_as_ushort(l) << 16);
}
__device__ __forceinline__ void unzip(uint2 p, uint32_t& hi, uint32_t& lo) {
    asm("prmt.b32 %0, %1, %2, 0x5410;" : "=r"(hi) : "r"(p.x), "r"(p.y));
    asm("prmt.b32 %0, %1, %2, 0x7632;" : "=r"(lo) : "r"(p.x), "r"(p.y));
}
__device__ __forceinline__ void mma16(float* d, uint32_t a0, uint32_t a1, uint32_t a2,
                                      uint32_t a3, uint32_t b0, uint32_t b1) {
    asm volatile("mma.sync.aligned.m16n8k16.row.col.f32.bf16.bf16.f32 "
                 "{%0,%1,%2,%3},{%4,%5,%6,%7},{%8,%9},{%0,%1,%2,%3};"
                 : "+f"(d[0]), "+f"(d[1]), "+f"(d[2]), "+f"(d[3])
                 : "r"(a0), "r"(a1), "r"(a2), "r"(a3), "r"(b0), "r"(b1));
}
__device__ __forceinline__ void mma8(float* d, const float* a, const float* b) {
    asm volatile("mma.sync.aligned.m16n8k8.row.col.f32.tf32.tf32.f32 "
                 "{%0,%1,%2,%3},{%4,%5,%6,%7},{%8,%9},{%0,%1,%2,%3};"
                 : "+f"(d[0]), "+f"(d[1]), "+f"(d[2]), "+f"(d[3])
                 : "r"(__float_as_uint(a[0])), "r"(__float_as_uint(a[1])),
                   "r"(__float_as_uint(a[2])), "r"(__float_as_uint(a[3])),
                   "r"(__float_as_uint(b[0])), "r"(__float_as_uint(b[1])));
}
#define MMA3(acc, ah, al, bh, bl) do { \
    mma16(acc, ah[0], ah[1], ah[2], ah[3], bh##0, bh##1); \
    mma16(acc, ah[0], ah[1], ah[2], ah[3], bl##0, bl##1); \
    mma16(acc, al[0], al[1], al[2], al[3], bh##0, bh##1); } while (0)

// prep: split W rows [Wq;Wk;Wv] into bf16 hi/lo planes. grid 320, block 256.
__global__ __launch_bounds__(256) void prep_kernel(
    const float* __restrict__ Wq, const float* __restrict__ bq,
    const float* __restrict__ Wk, const float* __restrict__ bk,
    const float* __restrict__ Wv, const float* __restrict__ bv)
{
    const int r = blockIdx.x, t = threadIdx.x;
    const float* src; const float* bsrc; int o;
    if (r < 32)      { src = Wq; bsrc = bq; o = r; }
    else if (r < 64) { src = Wk; bsrc = bk; o = r - 32; }
    else             { src = Wv; bsrc = bv; o = r - 64; }
    float v = src[o*256 + t];
    __nv_bfloat16 h = __float2bfloat16(v);
    g_Wh[r*256 + t] = h;
    g_Wl[r*256 + t] = __float2bfloat16(v - __bfloat162float(h));
    if (t == 0) g_bs[r] = bsrc[o];
}

// xt: x[b][c][p] -> split bf16 [b][p][c]. grid (512,8,8), block 256.
__global__ __launch_bounds__(256) void xt_kernel(const float* __restrict__ x)
{
    __shared__ float tl[32][33];
    const int b = blockIdx.z, c0 = blockIdx.y*32, p0 = blockIdx.x*32;
    const int tx = threadIdx.x & 31, ty = threadIdx.x >> 5;
    #pragma unroll
    for (int i = 0; i < 4; i++) {
        int c = ty + i*8;
        tl[c][tx] = x[((size_t)(b*Cc + c0 + c))*HWn + p0 + tx];
    }
    __syncthreads();
    #pragma unroll
    for (int i = 0; i < 4; i++) {
        int p = ty + i*8;
        float v = tl[tx][p];
        __nv_bfloat16 h = __float2bfloat16(v);
        size_t idx = ((size_t)b*HWn + p0 + p)*Cc + c0 + tx;
        g_xh[idx] = h;
        g_xl[idx] = __float2bfloat16(v - __bfloat162float(h));
    }
}

// proj: per (b,h,mt): D[128 px x 64 oc] = x(128x256) @ W_mt^T, bf16 3-pass.
// grid (128, 5, 8), block 256 (8 warps 4m x 2n, warp tile 32x32).
__global__ __launch_bounds__(256) void proj_mma()
{
    __shared__ __align__(16) uint32_t pool[8448];  // AHI@0 ALO@2560 BHI@5120 BLO@6400 (stride 20w)
    __shared__ float s_bias[64];
    const int t = threadIdx.x, wid = t >> 5, lane = t & 31;
    const int g8 = lane >> 2, tig = lane & 3;
    const int warp_m = wid & 3, warp_n = wid >> 2;
    const int h = blockIdx.x, mt = blockIdx.y, b = blockIdx.z;
    const int px0 = h * 128;
    if (t < 64) s_bias[t] = g_bs[mt*64 + t];

    const __nv_bfloat16* Xh = g_xh + ((size_t)b*HWn + px0)*Cc;
    const __nv_bfloat16* Xl = g_xl + ((size_t)b*HWn + px0)*Cc;
    const __nv_bfloat16* Wh = g_Wh + (size_t)mt*64*Cc;
    const __nv_bfloat16* Wl = g_Wl + (size_t)mt*64*Cc;

    float acc[2][4][4] = {};
    const int ar = t >> 1, aw = (t & 1)*8;
    const int br = t >> 2, bw = (t & 3)*4;

    for (int kc = 0; kc < 8; kc++) {
        const size_t ae = (size_t)ar*Cc + kc*32 + aw*2;
        const size_t be = (size_t)br*Cc + kc*32 + bw*2;
        uint4 ah0 = *(const uint4*)(Xh + ae), ah1 = *(const uint4*)(Xh + ae + 8);
        uint4 al0 = *(const uint4*)(Xl + ae), al1 = *(const uint4*)(Xl + ae + 8);
        uint4 bh  = *(const uint4*)(Wh + be), bl  = *(const uint4*)(Wl + be);
        __syncthreads();
        *(uint4*)&pool[ar*20 + aw]          = ah0;
        *(uint4*)&pool[ar*20 + aw + 4]      = ah1;
        *(uint4*)&pool[2560 + ar*20 + aw]   = al0;
        *(uint4*)&pool[2560 + ar*20 + aw+4] = al1;
        *(uint4*)&pool[5120 + br*20 + bw]   = bh;
        *(uint4*)&pool[6400 + br*20 + bw]   = bl;
        __syncthreads();
        #pragma unroll
        for (int ks = 0; ks < 2; ks++) {
            const int kw = ks*8;
            uint32_t ahf[2][4], alf[2][4];
            #pragma unroll
            for (int mi = 0; mi < 2; mi++) {
                const int m0 = warp_m*32 + mi*16;
                ahf[mi][0] = pool[(m0+g8  )*20 + kw + tig];
                ahf[mi][1] = pool[(m0+g8+8)*20 + kw + tig];
                ahf[mi][2] = pool[(m0+g8  )*20 + kw + tig + 4];
                ahf[mi][3] = pool[(m0+g8+8)*20 + kw + tig + 4];
                alf[mi][0] = pool[2560 + (m0+g8  )*20 + kw + tig];
                alf[mi][1] = pool[2560 + (m0+g8+8)*20 + kw + tig];
                alf[mi][2] = pool[2560 + (m0+g8  )*20 + kw + tig + 4];
                alf[mi][3] = pool[2560 + (m0+g8+8)*20 + kw + tig + 4];
            }
            #pragma unroll
            for (int ni = 0; ni < 4; ni++) {
                const int n = warp_n*32 + ni*8 + g8;
                uint32_t bh0 = pool[5120 + n*20 + kw + tig];
                uint32_t bh1 = pool[5120 + n*20 + kw + tig + 4];
                uint32_t bl0 = pool[6400 + n*20 + kw + tig];
                uint32_t bl1 = pool[6400 + n*20 + kw + tig + 4];
                #pragma unroll
                for (int mi = 0; mi < 2; mi++) {
                    mma16(acc[mi][ni], ahf[mi][0], ahf[mi][1], ahf[mi][2], ahf[mi][3], bh0, bh1);
                    mma16(acc[mi][ni], ahf[mi][0], ahf[mi][1], ahf[mi][2], ahf[mi][3], bl0, bl1);
                    mma16(acc[mi][ni], alf[mi][0], alf[mi][1], alf[mi][2], alf[mi][3], bh0, bh1);
                }
            }
        }
    }

    if (mt == 0) {
        #pragma unroll
        for (int mi = 0; mi < 2; mi++)
            #pragma unroll
            for (int ni = 0; ni < 4; ni++) {
                const int n = warp_n*32 + ni*8 + tig*2;
                const float b0 = s_bias[n], b1 = s_bias[n+1];
                float* hwp = (n < 32 ? g_q_hw : g_k_hw);
                float* whp = (n < 32 ? g_q_wh : g_k_wh);
                const int o = n & 31;
                #pragma unroll
                for (int hf = 0; hf < 2; hf++) {
                    const int w = warp_m*32 + mi*16 + g8 + hf*8;
                    float2 v = {acc[mi][ni][hf*2] + b0, acc[mi][ni][hf*2+1] + b1};
                    *(float2*)(hwp + ((size_t)(b*Hh + h)*Wn + w)*CQn + o) = v;
                    *(float2*)(whp + ((size_t)(b*Wn + w)*Hh + h)*CQn + o) = v;
                }
            }
    } else {
        float* tb = (float*)pool;   // [64 c][132 px]
        __syncthreads();
        #pragma unroll
        for (int mi = 0; mi < 2; mi++)
            #pragma unroll
            for (int ni = 0; ni < 4; ni++) {
                const int n = warp_n*32 + ni*8 + tig*2;
                const float b0 = s_bias[n], b1 = s_bias[n+1];
                #pragma unroll
                for (int hf = 0; hf < 2; hf++) {
                    const int w = warp_m*32 + mi*16 + g8 + hf*8;
                    tb[n*132 + w]     = acc[mi][ni][hf*2]   + b0;
                    tb[(n+1)*132 + w] = acc[mi][ni][hf*2+1] + b1;
                }
            }
        __syncthreads();
        const int c = t >> 2, p4 = (t & 3)*32;
        float* dst = g_va + ((size_t)(b*Cc + (mt-1)*64 + c))*HWn + px0 + p4;
        #pragma unroll
        for (int i = 0; i < 32; i += 4)
            *(float4*)(dst + i) = *(float4*)&tb[c*132 + p4 + i];
    }
}

// vb: g_va[b][c][h][w] -> g_vb[b][c][w][h]. grid (4,4,2048), block 256.
__global__ __launch_bounds__(256) void vb_kernel()
{
    __shared__ float tl[32][33];
    const int bc = blockIdx.z, w0 = blockIdx.x*32, h0 = blockIdx.y*32;
    const int tx = threadIdx.x & 31, ty = threadIdx.x >> 5;
    #pragma unroll
    for (int i = 0; i < 4; i++)
        tl[ty + i*8][tx] = g_va[((size_t)bc*Hh + h0 + ty + i*8)*Wn + w0 + tx];
    __syncthreads();
    #pragma unroll
    for (int i = 0; i < 4; i++)
        g_vb[((size_t)bc*Wn + w0 + ty + i*8)*Hh + h0 + tx] = tl[tx][ty + i*8];
}

// score<ISH>: D[128x128] = Q@K^T (K=32), bf16 3-pass; split in loader.
// grid 1024, block 256 (8 warps 4m x 2n, warp tile 32x64).
template <bool ISH>
__global__ __launch_bounds__(256) void score_mma()
{
    __shared__ __align__(16) uint32_t Qs[128][36], Ks[128][36];
    const int bs = blockIdx.x, t = threadIdx.x;
    const int wid = t >> 5, lane = t & 31, g8 = lane >> 2, tig = lane & 3;
    const int warp_m = wid & 3, warp_n = wid >> 2;
    const float* Q = (ISH ? g_q_wh : g_q_hw) + (size_t)bs*128*CQn;
    const float* K = (ISH ? g_k_wh : g_k_hw) + (size_t)bs*128*CQn;
    float* O = (ISH ? g_eH : g_eW) + (size_t)bs*128*128;

    #pragma unroll
    for (int i = 0; i < 4; i++) {
        const int idx = i*256 + t, r = idx >> 3, kq = (idx & 7)*4;
        float4 qv = *(const float4*)(Q + (size_t)r*CQn + kq);
        float4 kv = *(const float4*)(K + (size_t)r*CQn + kq);
        uint4 qp = {splitf(qv.x), splitf(qv.y), splitf(qv.z), splitf(qv.w)};
        uint4 kp = {splitf(kv.x), splitf(kv.y), splitf(kv.z), splitf(kv.w)};
        *(uint4*)&Qs[r][kq] = qp;
        *(uint4*)&Ks[r][kq] = kp;
    }
    __syncthreads();

    float acc[2][8][4] = {};
    #pragma unroll
    for (int ks = 0; ks < 2; ks++) {
        const int k0 = ks*16;
        uint32_t ah[2][4], al[2][4];
        #pragma unroll
        for (int mi = 0; mi < 2; mi++) {
            const int m = warp_m*32 + mi*16;
            unzip(*(uint2*)&Qs[m+g8  ][k0 + 2*tig],     ah[mi][0], al[mi][0]);
            unzip(*(uint2*)&Qs[m+g8+8][k0 + 2*tig],     ah[mi][1], al[mi][1]);
            unzip(*(uint2*)&Qs[m+g8  ][k0 + 8 + 2*tig], ah[mi][2], al[mi][2]);
            unzip(*(uint2*)&Qs[m+g8+8][k0 + 8 + 2*tig], ah[mi][3], al[mi][3]);
        }
        #pragma unroll
        for (int ni = 0; ni < 8; ni++) {
            const int n = warp_n*64 + ni*8 + g8;
            uint32_t bh0, bl0, bh1, bl1;
            unzip(*(uint2*)&Ks[n][k0 + 2*tig],     bh0, bl0);
            unzip(*(uint2*)&Ks[n][k0 + 8 + 2*tig], bh1, bl1);
            #pragma unroll
            for (int mi = 0; mi < 2; mi++) MMA3(acc[mi][ni], ah[mi], al[mi], bh, bl);
        }
    }
    #pragma unroll
    for (int mi = 0; mi < 2; mi++)
        #pragma unroll
        for (int ni = 0; ni < 8; ni++) {
            const int n = warp_n*64 + ni*8 + tig*2;
            #pragma unroll
            for (int hf = 0; hf < 2; hf++) {
                const int m = warp_m*32 + mi*16 + g8 + hf*8;
                float d0 = acc[mi][ni][hf*2], d1 = acc[mi][ni][hf*2+1];
                if (ISH) { if (n == m) d0 = neg_inf_f(); if (n+1 == m) d1 = neg_inf_f(); }
                *(float2*)(O + (size_t)m*128 + n) = make_float2(d0, d1);
            }
        }
}

// softmax: joint 256-way per pixel, in place. grid 16384, block 256.
__global__ __launch_bounds__(256) void softmax_kernel()
{
    const int wid = blockIdx.x*8 + (threadIdx.x >> 5), lane = threadIdx.x & 31;
    const int b = wid >> 14, hw = wid & 16383, h = hw >> 7, w = hw & 127;
    float* pH = g_eH + ((size_t)(b*Wn + w)*Hh + h)*Hh;
    float* pW = g_eW + ((size_t)(b*Hh + h)*Wn + w)*Wn;
    float4 vh = *(float4*)(pH + lane*4);
    float4 vw = *(float4*)(pW + lane*4);
    float m = fmaxf(fmaxf(fmaxf(vh.x,vh.y),fmaxf(vh.z,vh.w)),
                    fmaxf(fmaxf(vw.x,vw.y),fmaxf(vw.z,vw.w)));
    #pragma unroll
    for (int off = 16; off; off >>= 1) m = fmaxf(m, __shfl_xor_sync(~0u, m, off));
    vh.x=__expf(vh.x-m); vh.y=__expf(vh.y-m); vh.z=__expf(vh.z-m); vh.w=__expf(vh.w-m);
    vw.x=__expf(vw.x-m); vw.y=__expf(vw.y-m); vw.z=__expf(vw.z-m); vw.w=__expf(vw.w-m);
    float s = vh.x+vh.y+vh.z+vh.w+vw.x+vw.y+vw.z+vw.w;
    #pragma unroll
    for (int off = 16; off; off >>= 1) s += __shfl_xor_sync(~0u, s, off);
    const float inv = 1.f/s;
    vh.x*=inv; vh.y*=inv; vh.z*=inv; vh.w*=inv;
    vw.x*=inv; vw.y*=inv; vw.z*=inv; vw.w*=inv;
    *(float4*)(pH + lane*4) = vh;
    *(float4*)(pW + lane*4) = vw;
}

// out<ISH>: per (b,s,chalf): D[128 spatial x 128 c] = att @ v^T (tf32 1-pass).
// ISH: write g_oH. !ISH: fused gamma*(D + oH) + x -> out. grid (2,1024), block 256.
template <bool ISH>
__global__ __launch_bounds__(256) void out_mma(const float* __restrict__ x,
                                               const float* __restrict__ gamma,
                                               float* __restrict__ out)
{
    __shared__ __align__(16) float pool[9216];   // As2[128][36]@0, Bs2@4608; tb[64][132]
    const int t = threadIdx.x, wid = t >> 5, lane = t & 31;
    const int g8 = lane >> 2, tig = lane & 3;
    const int warp_m = wid & 3, warp_n = wid >> 2;
    const int bs = blockIdx.y, b = bs >> 7, s = bs & 127;
    const int c0 = blockIdx.x * 128;
    const float* A = (ISH ? g_eH : g_eW) + (size_t)bs*16384;
    const float* V = (ISH ? g_vb : g_va) + (size_t)b*Cc*HWn + (size_t)s*Wn;

    float acc[2][8][4] = {};
    const int ar = t >> 1, akq = (t & 1)*16;
    for (int kc = 0; kc < 4; kc++) {
        float4 av[4], bv[4];
        #pragma unroll
        for (int i = 0; i < 4; i++) {
            av[i] = *(const float4*)(A + (size_t)ar*128 + kc*32 + akq + i*4);
            bv[i] = *(const float4*)(V + (size_t)(c0 + ar)*HWn + kc*32 + akq + i*4);
        }
        __syncthreads();
        #pragma unroll
        for (int i = 0; i < 4; i++) {
            float* As2 = pool + ar*36 + akq + i*4;
            float* Bs2 = pool + 4608 + ar*36 + akq + i*4;
            As2[0]=tf32r(av[i].x); As2[1]=tf32r(av[i].y); As2[2]=tf32r(av[i].z); As2[3]=tf32r(av[i].w);
            Bs2[0]=tf32r(bv[i].x); Bs2[1]=tf32r(bv[i].y); Bs2[2]=tf32r(bv[i].z); Bs2[3]=tf32r(bv[i].w);
        }
        __syncthreads();
        #pragma unroll
        for (int kk = 0; kk < 4; kk++) {
            const int k0 = kk*8;
            float a[2][4];
            #pragma unroll
            for (int mi = 0; mi < 2; mi++) {
                const int m0 = warp_m*32 + mi*16;
                a[mi][0] = pool[(m0+g8  )*36 + k0+tig];
                a[mi][1] = pool[(m0+g8+8)*36 + k0+tig];
                a[mi][2] = pool[(m0+g8  )*36 + k0+tig+4];
                a[mi][3] = pool[(m0+g8+8)*36 + k0+tig+4];
            }
            #pragma unroll
            for (int ni = 0; ni < 8; ni++) {
                const int nn = warp_n*64 + ni*8 + g8;
                float bf[2] = {pool[4608 + nn*36 + k0+tig], pool[4608 + nn*36 + k0+tig+4]};
                #pragma unroll
                for (int mi = 0; mi < 2; mi++) mma8(acc[mi][ni], a[mi], bf);
            }
        }
    }

    if (ISH) {
        float* O = g_oH + (size_t)bs*128*Cc;
        #pragma unroll
        for (int mi = 0; mi < 2; mi++)
            #pragma unroll
            for (int ni = 0; ni < 8; ni++) {
                const int m = warp_m*32 + mi*16 + g8;
                const int n = c0 + warp_n*64 + ni*8 + tig*2;
                *(float2*)(O + (size_t)m*Cc + n)     = make_float2(acc[mi][ni][0], acc[mi][ni][1]);
                *(float2*)(O + (size_t)(m+8)*Cc + n) = make_float2(acc[mi][ni][2], acc[mi][ni][3]);
            }
    } else {
        // fused: out[b][c][h=s][w] = gm*(D[w][c] + oH[b][w][s][c]) + x
        const float gm = gamma[0];
        #pragma unroll
        for (int ch = 0; ch < 2; ch++) {
            __syncthreads();
            if (warp_n == ch) {
                #pragma unroll
                for (int mi = 0; mi < 2; mi++)
                    #pragma unroll
                    for (int ni = 0; ni < 8; ni++) {
                        const int m  = warp_m*32 + mi*16 + g8;
                        const int nl = ni*8 + tig*2;
                        const int ng = c0 + ch*64 + nl;
                        float2 o1 = *(const float2*)(g_oH + ((size_t)(b*Wn + m)*Hh + s)*Cc + ng);
                        float2 o2 = *(const float2*)(g_oH + ((size_t)(b*Wn + m+8)*Hh + s)*Cc + ng);
                        pool[nl*132 + m]       = acc[mi][ni][0] + o1.x;
                        pool[(nl+1)*132 + m]   = acc[mi][ni][1] + o1.y;
                        pool[nl*132 + m+8]     = acc[mi][ni][2] + o2.x;
                        pool[(nl+1)*132 + m+8] = acc[mi][ni][3] + o2.y;
                    }
            }
            __syncthreads();
            const int c = t >> 2, w4 = (t & 3)*32;
            const size_t oidx = ((size_t)(b*Cc + c0 + ch*64 + c)*Hh + s)*Wn + w4;
            #pragma unroll
            for (int i = 0; i < 32; i += 4) {
                float4 xr = *(const float4*)(x + oidx + i);
                float4 r;
                r.x = gm*pool[c*132 + w4+i  ] + xr.x;
                r.y = gm*pool[c*132 + w4+i+1] + xr.y;
                r.z = gm*pool[c*132 + w4+i+2] + xr.z;
                r.w = gm*pool[c*132 + w4+i+3] + xr.w;
                *(float4*)(out + oidx + i) = r;
            }
        }
    }
}

extern "C" void kernel_launch(void* const* d_in, const int* in_sizes, int n_in,
                              void* d_out, int out_size)
{
    const float* x     = (const float*)d_in[0];
    const float* Wq    = (const float*)d_in[1];
    const float* bq    = (const float*)d_in[2];
    const float* Wk    = (const float*)d_in[3];
    const float* bk    = (const float*)d_in[4];
    const float* Wv    = (const float*)d_in[5];
    const float* bv    = (const float*)d_in[6];
    const float* gamma = (const float*)d_in[7];
    float* out = (float*)d_out;

    prep_kernel<<<320, 256>>>(Wq, bq, Wk, bk, Wv, bv);
    xt_kernel<<<dim3(512, 8, 8), 256>>>(x);
    proj_mma<<<dim3(128, 5, 8), 256>>>();
    vb_kernel<<<dim3(4, 4, 2048), 256>>>();
    score_mma<true ><<<1024, 256>>>();
    score_mma<false><<<1024, 256>>>();
    softmax_kernel<<<16384, 256>>>();
    out_mma<true ><<<dim3(2, 1024), 256>>>(x, gamma, out);
    out_mma<false><<<dim3(2, 1024), 256>>>(x, gamma, out);
}

// round 9
// speedup vs baseline: 1.3801x; 1.2149x over previous
#include <cuda_runtime.h>
#include <cuda_bf16.h>
#include <cstdint>

#define Bn 8
#define Cc 256
#define CQn 32
#define Hh 128
#define Wn 128
#define HWn (Hh*Wn)

__device__ __nv_bfloat16 g_Wh[320*256], g_Wl[320*256];   // split W rows: [q32;k32;v256]
__device__ float g_bs[320];
__device__ __nv_bfloat16 g_xh[(size_t)Bn*HWn*Cc], g_xl[(size_t)Bn*HWn*Cc]; // [b][p][c]
__device__ float g_q_hw[(size_t)Bn*HWn*CQn], g_q_wh[(size_t)Bn*HWn*CQn];
__device__ float g_k_hw[(size_t)Bn*HWn*CQn], g_k_wh[(size_t)Bn*HWn*CQn];
__device__ float g_va[(size_t)Bn*Cc*HWn];   // [b][c][h][w]
__device__ float g_vb[(size_t)Bn*Cc*HWn];   // [b][c][w][h]
__device__ float g_eH[(size_t)Bn*Wn*Hh*Hh]; // [b][w][h][g]
__device__ float g_eW[(size_t)Bn*Hh*Wn*Wn]; // [b][h][w][g]
__device__ float g_oH[(size_t)Bn*HWn*Cc];   // [b][w][h][c]
__device__ float g_oW[(size_t)Bn*HWn*Cc];   // [b][h][w][c]

__device__ __forceinline__ float neg_inf_f() { return __int_as_float(0xff800000); }
__device__ __forceinline__ float tf32r(float f) {
    uint32_t u; asm("cvt.rna.tf32.f32 %0, %1;" : "=r"(u) : "f"(f));
    return __uint_as_float(u);
}
__device__ __forceinline__ uint32_t splitf(float f) {
    __nv_bfloat16 h = __float2bfloat16(f);
    __nv_bfloat16 l = __float2bfloat16(f - __bfloat162float(h));
    return (uint32_t)__bfloat16_as_ushort(h) | ((uint32_t)__bfloat16_as_ushort(l) << 16);
}
__device__ __forceinline__ void unzip(uint2 p, uint32_t& hi, uint32_t& lo) {
    asm("prmt.b32 %0, %1, %2, 0x5410;" : "=r"(hi) : "r"(p.x), "r"(p.y));
    asm("prmt.b32 %0, %1, %2, 0x7632;" : "=r"(lo) : "r"(p.x), "r"(p.y));
}
__device__ __forceinline__ void mma16(float* d, uint32_t a0, uint32_t a1, uint32_t a2,
                                      uint32_t a3, uint32_t b0, uint32_t b1) {
    asm volatile("mma.sync.aligned.m16n8k16.row.col.f32.bf16.bf16.f32 "
                 "{%0,%1,%2,%3},{%4,%5,%6,%7},{%8,%9},{%0,%1,%2,%3};"
                 : "+f"(d[0]), "+f"(d[1]), "+f"(d[2]), "+f"(d[3])
                 : "r"(a0), "r"(a1), "r"(a2), "r"(a3), "r"(b0), "r"(b1));
}
__device__ __forceinline__ void mma8(float* d, const float* a, const float* b) {
    asm volatile("mma.sync.aligned.m16n8k8.row.col.f32.tf32.tf32.f32 "
                 "{%0,%1,%2,%3},{%4,%5,%6,%7},{%8,%9},{%0,%1,%2,%3};"
                 : "+f"(d[0]), "+f"(d[1]), "+f"(d[2]), "+f"(d[3])
                 : "r"(__float_as_uint(a[0])), "r"(__float_as_uint(a[1])),
                   "r"(__float_as_uint(a[2])), "r"(__float_as_uint(a[3])),
                   "r"(__float_as_uint(b[0])), "r"(__float_as_uint(b[1])));
}
#define MMA3(acc, ah, al, bh, bl) do { \
    mma16(acc, ah[0], ah[1], ah[2], ah[3], bh##0, bh##1); \
    mma16(acc, ah[0], ah[1], ah[2], ah[3], bl##0, bl##1); \
    mma16(acc, al[0], al[1], al[2], al[3], bh##0, bh##1); } while (0)

// prep: split W rows [Wq;Wk;Wv] into bf16 hi/lo planes. grid 320, block 256.
__global__ __launch_bounds__(256) void prep_kernel(
    const float* __restrict__ Wq, const float* __restrict__ bq,
    const float* __restrict__ Wk, const float* __restrict__ bk,
    const float* __restrict__ Wv, const float* __restrict__ bv)
{
    const int r = blockIdx.x, t = threadIdx.x;
    const float* src; const float* bsrc; int o;
    if (r < 32)      { src = Wq; bsrc = bq; o = r; }
    else if (r < 64) { src = Wk; bsrc = bk; o = r - 32; }
    else             { src = Wv; bsrc = bv; o = r - 64; }
    float v = src[o*256 + t];
    __nv_bfloat16 h = __float2bfloat16(v);
    g_Wh[r*256 + t] = h;
    g_Wl[r*256 + t] = __float2bfloat16(v - __bfloat162float(h));
    if (t == 0) g_bs[r] = bsrc[o];
}

// xt: x[b][c][p] -> split bf16 [b][p][c]. grid (512,8,8), block 256.
__global__ __launch_bounds__(256) void xt_kernel(const float* __restrict__ x)
{
    __shared__ float tl[32][33];
    const int b = blockIdx.z, c0 = blockIdx.y*32, p0 = blockIdx.x*32;
    const int tx = threadIdx.x & 31, ty = threadIdx.x >> 5;
    #pragma unroll
    for (int i = 0; i < 4; i++) {
        int c = ty + i*8;
        tl[c][tx] = x[((size_t)(b*Cc + c0 + c))*HWn + p0 + tx];
    }
    __syncthreads();
    #pragma unroll
    for (int i = 0; i < 4; i++) {
        int p = ty + i*8;
        float v = tl[tx][p];
        __nv_bfloat16 h = __float2bfloat16(v);
        size_t idx = ((size_t)b*HWn + p0 + p)*Cc + c0 + tx;
        g_xh[idx] = h;
        g_xl[idx] = __float2bfloat16(v - __bfloat162float(h));
    }
}

// proj: per (b,h,mt): D[128 px x 64 oc] = x(128x256) @ W_mt^T.
// mt==0 (q,k): bf16 3-pass split. mt>=1 (v): bf16 1-pass (hi*hi only).
// grid (128, 5, 8), block 256 (8 warps 4m x 2n, warp tile 32x32).
__global__ __launch_bounds__(256) void proj_mma()
{
    __shared__ __align__(16) uint32_t pool[8448];  // AHI@0 ALO@2560 BHI@5120 BLO@6400 (stride 20w)
    __shared__ float s_bias[64];
    const int t = threadIdx.x, wid = t >> 5, lane = t & 31;
    const int g8 = lane >> 2, tig = lane & 3;
    const int warp_m = wid & 3, warp_n = wid >> 2;
    const int h = blockIdx.x, mt = blockIdx.y, b = blockIdx.z;
    const int px0 = h * 128;
    const bool hiPrec = (mt == 0);
    if (t < 64) s_bias[t] = g_bs[mt*64 + t];

    const __nv_bfloat16* Xh = g_xh + ((size_t)b*HWn + px0)*Cc;
    const __nv_bfloat16* Xl = g_xl + ((size_t)b*HWn + px0)*Cc;
    const __nv_bfloat16* Wh = g_Wh + (size_t)mt*64*Cc;
    const __nv_bfloat16* Wl = g_Wl + (size_t)mt*64*Cc;

    float acc[2][4][4] = {};
    const int ar = t >> 1, aw = (t & 1)*8;
    const int br = t >> 2, bw = (t & 3)*4;

    for (int kc = 0; kc < 8; kc++) {
        const size_t ae = (size_t)ar*Cc + kc*32 + aw*2;
        const size_t be = (size_t)br*Cc + kc*32 + bw*2;
        uint4 ah0 = *(const uint4*)(Xh + ae), ah1 = *(const uint4*)(Xh + ae + 8);
        uint4 bh  = *(const uint4*)(Wh + be);
        uint4 al0, al1, bl;
        if (hiPrec) {
            al0 = *(const uint4*)(Xl + ae); al1 = *(const uint4*)(Xl + ae + 8);
            bl  = *(const uint4*)(Wl + be);
        }
        __syncthreads();
        *(uint4*)&pool[ar*20 + aw]        = ah0;
        *(uint4*)&pool[ar*20 + aw + 4]    = ah1;
        *(uint4*)&pool[5120 + br*20 + bw] = bh;
        if (hiPrec) {
            *(uint4*)&pool[2560 + ar*20 + aw]   = al0;
            *(uint4*)&pool[2560 + ar*20 + aw+4] = al1;
            *(uint4*)&pool[6400 + br*20 + bw]   = bl;
        }
        __syncthreads();
        #pragma unroll
        for (int ks = 0; ks < 2; ks++) {
            const int kw = ks*8;
            uint32_t ahf[2][4], alf[2][4];
            #pragma unroll
            for (int mi = 0; mi < 2; mi++) {
                const int m0 = warp_m*32 + mi*16;
                ahf[mi][0] = pool[(m0+g8  )*20 + kw + tig];
                ahf[mi][1] = pool[(m0+g8+8)*20 + kw + tig];
                ahf[mi][2] = pool[(m0+g8  )*20 + kw + tig + 4];
                ahf[mi][3] = pool[(m0+g8+8)*20 + kw + tig + 4];
                if (hiPrec) {
                    alf[mi][0] = pool[2560 + (m0+g8  )*20 + kw + tig];
                    alf[mi][1] = pool[2560 + (m0+g8+8)*20 + kw + tig];
                    alf[mi][2] = pool[2560 + (m0+g8  )*20 + kw + tig + 4];
                    alf[mi][3] = pool[2560 + (m0+g8+8)*20 + kw + tig + 4];
                }
            }
            #pragma unroll
            for (int ni = 0; ni < 4; ni++) {
                const int n = warp_n*32 + ni*8 + g8;
                uint32_t bh0 = pool[5120 + n*20 + kw + tig];
                uint32_t bh1 = pool[5120 + n*20 + kw + tig + 4];
                if (hiPrec) {
                    uint32_t bl0 = pool[6400 + n*20 + kw + tig];
                    uint32_t bl1 = pool[6400 + n*20 + kw + tig + 4];
                    #pragma unroll
                    for (int mi = 0; mi < 2; mi++) {
                        mma16(acc[mi][ni], ahf[mi][0], ahf[mi][1], ahf[mi][2], ahf[mi][3], bh0, bh1);
                        mma16(acc[mi][ni], ahf[mi][0], ahf[mi][1], ahf[mi][2], ahf[mi][3], bl0, bl1);
                        mma16(acc[mi][ni], alf[mi][0], alf[mi][1], alf[mi][2], alf[mi][3], bh0, bh1);
                    }
                } else {
                    #pragma unroll
                    for (int mi = 0; mi < 2; mi++)
                        mma16(acc[mi][ni], ahf[mi][0], ahf[mi][1], ahf[mi][2], ahf[mi][3], bh0, bh1);
                }
            }
        }
    }

    if (mt == 0) {
        #pragma unroll
        for (int mi = 0; mi < 2; mi++)
            #pragma unroll
            for (int ni = 0; ni < 4; ni++) {
                const int n = warp_n*32 + ni*8 + tig*2;
                const float b0 = s_bias[n], b1 = s_bias[n+1];
                float* hwp = (n < 32 ? g_q_hw : g_k_hw);
                float* whp = (n < 32 ? g_q_wh : g_k_wh);
                const int o = n & 31;
                #pragma unroll
                for (int hf = 0; hf < 2; hf++) {
                    const int w = warp_m*32 + mi*16 + g8 + hf*8;
                    float2 v = {acc[mi][ni][hf*2] + b0, acc[mi][ni][hf*2+1] + b1};
                    *(float2*)(hwp + ((size_t)(b*Hh + h)*Wn + w)*CQn + o) = v;
                    *(float2*)(whp + ((size_t)(b*Wn + w)*Hh + h)*CQn + o) = v;
                }
            }
    } else {
        float* tb = (float*)pool;   // [64 c][132 px]
        __syncthreads();
        #pragma unroll
        for (int mi = 0; mi < 2; mi++)
            #pragma unroll
            for (int ni = 0; ni < 4; ni++) {
                const int n = warp_n*32 + ni*8 + tig*2;
                const float b0 = s_bias[n], b1 = s_bias[n+1];
                #pragma unroll
                for (int hf = 0; hf < 2; hf++) {
                    const int w = warp_m*32 + mi*16 + g8 + hf*8;
                    tb[n*132 + w]     = acc[mi][ni][hf*2]   + b0;
                    tb[(n+1)*132 + w] = acc[mi][ni][hf*2+1] + b1;
                }
            }
        __syncthreads();
        const int c = t >> 2, p4 = (t & 3)*32;
        float* dst = g_va + ((size_t)(b*Cc + (mt-1)*64 + c))*HWn + px0 + p4;
        #pragma unroll
        for (int i = 0; i < 32; i += 4)
            *(float4*)(dst + i) = *(float4*)&tb[c*132 + p4 + i];
    }
}

// vb: g_va[b][c][h][w] -> g_vb[b][c][w][h]. grid (4,4,2048), block 256.
__global__ __launch_bounds__(256) void vb_kernel()
{
    __shared__ float tl[32][33];
    const int bc = blockIdx.z, w0 = blockIdx.x*32, h0 = blockIdx.y*32;
    const int tx = threadIdx.x & 31, ty = threadIdx.x >> 5;
    #pragma unroll
    for (int i = 0; i < 4; i++)
        tl[ty + i*8][tx] = g_va[((size_t)bc*Hh + h0 + ty + i*8)*Wn + w0 + tx];
    __syncthreads();
    #pragma unroll
    for (int i = 0; i < 4; i++)
        g_vb[((size_t)bc*Wn + w0 + ty + i*8)*Hh + h0 + tx] = tl[tx][ty + i*8];
}

// score<ISH>: D[128x128] = Q@K^T (K=32), bf16 3-pass; split in loader.
// grid 1024, block 256 (8 warps 4m x 2n, warp tile 32x64).
template <bool ISH>
__global__ __launch_bounds__(256) void score_mma()
{
    __shared__ __align__(16) uint32_t Qs[128][36], Ks[128][36];
    const int bs = blockIdx.x, t = threadIdx.x;
    const int wid = t >> 5, lane = t & 31, g8 = lane >> 2, tig = lane & 3;
    const int warp_m = wid & 3, warp_n = wid >> 2;
    const float* Q = (ISH ? g_q_wh : g_q_hw) + (size_t)bs*128*CQn;
    const float* K = (ISH ? g_k_wh : g_k_hw) + (size_t)bs*128*CQn;
    float* O = (ISH ? g_eH : g_eW) + (size_t)bs*128*128;

    #pragma unroll
    for (int i = 0; i < 4; i++) {
        const int idx = i*256 + t, r = idx >> 3, kq = (idx & 7)*4;
        float4 qv = *(const float4*)(Q + (size_t)r*CQn + kq);
        float4 kv = *(const float4*)(K + (size_t)r*CQn + kq);
        uint4 qp = {splitf(qv.x), splitf(qv.y), splitf(qv.z), splitf(qv.w)};
        uint4 kp = {splitf(kv.x), splitf(kv.y), splitf(kv.z), splitf(kv.w)};
        *(uint4*)&Qs[r][kq] = qp;
        *(uint4*)&Ks[r][kq] = kp;
    }
    __syncthreads();

    float acc[2][8][4] = {};
    #pragma unroll
    for (int ks = 0; ks < 2; ks++) {
        const int k0 = ks*16;
        uint32_t ah[2][4], al[2][4];
        #pragma unroll
        for (int mi = 0; mi < 2; mi++) {
            const int m = warp_m*32 + mi*16;
            unzip(*(uint2*)&Qs[m+g8  ][k0 + 2*tig],     ah[mi][0], al[mi][0]);
            unzip(*(uint2*)&Qs[m+g8+8][k0 + 2*tig],     ah[mi][1], al[mi][1]);
            unzip(*(uint2*)&Qs[m+g8  ][k0 + 8 + 2*tig], ah[mi][2], al[mi][2]);
            unzip(*(uint2*)&Qs[m+g8+8][k0 + 8 + 2*tig], ah[mi][3], al[mi][3]);
        }
        #pragma unroll
        for (int ni = 0; ni < 8; ni++) {
            const int n = warp_n*64 + ni*8 + g8;
            uint32_t bh0, bl0, bh1, bl1;
            unzip(*(uint2*)&Ks[n][k0 + 2*tig],     bh0, bl0);
            unzip(*(uint2*)&Ks[n][k0 + 8 + 2*tig], bh1, bl1);
            #pragma unroll
            for (int mi = 0; mi < 2; mi++) MMA3(acc[mi][ni], ah[mi], al[mi], bh, bl);
        }
    }
    #pragma unroll
    for (int mi = 0; mi < 2; mi++)
        #pragma unroll
        for (int ni = 0; ni < 8; ni++) {
            const int n = warp_n*64 + ni*8 + tig*2;
            #pragma unroll
            for (int hf = 0; hf < 2; hf++) {
                const int m = warp_m*32 + mi*16 + g8 + hf*8;
                float d0 = acc[mi][ni][hf*2], d1 = acc[mi][ni][hf*2+1];
                if (ISH) { if (n == m) d0 = neg_inf_f(); if (n+1 == m) d1 = neg_inf_f(); }
                *(float2*)(O + (size_t)m*128 + n) = make_float2(d0, d1);
            }
        }
}

// softmax: joint 256-way per pixel, in place. grid 16384, block 256.
__global__ __launch_bounds__(256) void softmax_kernel()
{
    const int wid = blockIdx.x*8 + (threadIdx.x >> 5), lane = threadIdx.x & 31;
    const int b = wid >> 14, hw = wid & 16383, h = hw >> 7, w = hw & 127;
    float* pH = g_eH + ((size_t)(b*Wn + w)*Hh + h)*Hh;
    float* pW = g_eW + ((size_t)(b*Hh + h)*Wn + w)*Wn;
    float4 vh = *(float4*)(pH + lane*4);
    float4 vw = *(float4*)(pW + lane*4);
    float m = fmaxf(fmaxf(fmaxf(vh.x,vh.y),fmaxf(vh.z,vh.w)),
                    fmaxf(fmaxf(vw.x,vw.y),fmaxf(vw.z,vw.w)));
    #pragma unroll
    for (int off = 16; off; off >>= 1) m = fmaxf(m, __shfl_xor_sync(~0u, m, off));
    vh.x=__expf(vh.x-m); vh.y=__expf(vh.y-m); vh.z=__expf(vh.z-m); vh.w=__expf(vh.w-m);
    vw.x=__expf(vw.x-m); vw.y=__expf(vw.y-m); vw.z=__expf(vw.z-m); vw.w=__expf(vw.w-m);
    float s = vh.x+vh.y+vh.z+vh.w+vw.x+vw.y+vw.z+vw.w;
    #pragma unroll
    for (int off = 16; off; off >>= 1) s += __shfl_xor_sync(~0u, s, off);
    const float inv = 1.f/s;
    vh.x*=inv; vh.y*=inv; vh.z*=inv; vh.w*=inv;
    vw.x*=inv; vw.y*=inv; vw.z*=inv; vw.w*=inv;
    *(float4*)(pH + lane*4) = vh;
    *(float4*)(pW + lane*4) = vw;
}

// out<ISH>: per (b,s,chalf): D[128 spatial x 128 c] = att @ v^T (tf32 1-pass).
// grid (2,1024), block 256.
template <bool ISH>
__global__ __launch_bounds__(256) void out_mma()
{
    __shared__ __align__(16) float pool[9216];   // As2[128][36]@0, Bs2@4608
    const int t = threadIdx.x, wid = t >> 5, lane = t & 31;
    const int g8 = lane >> 2, tig = lane & 3;
    const int warp_m = wid & 3, warp_n = wid >> 2;
    const int bs = blockIdx.y, b = bs >> 7, s = bs & 127;
    const int c0 = blockIdx.x * 128;
    const float* A = (ISH ? g_eH : g_eW) + (size_t)bs*16384;
    const float* V = (ISH ? g_vb : g_va) + (size_t)b*Cc*HWn + (size_t)s*Wn;
    float* O       = (ISH ? g_oH : g_oW) + (size_t)bs*128*Cc;

    float acc[2][8][4] = {};
    const int ar = t >> 1, akq = (t & 1)*16;
    for (int kc = 0; kc < 4; kc++) {
        float4 av[4], bv[4];
        #pragma unroll
        for (int i = 0; i < 4; i++) {
            av[i] = *(const float4*)(A + (size_t)ar*128 + kc*32 + akq + i*4);
            bv[i] = *(const float4*)(V + (size_t)(c0 + ar)*HWn + kc*32 + akq + i*4);
        }
        __syncthreads();
        #pragma unroll
        for (int i = 0; i < 4; i++) {
            float* As2 = pool + ar*36 + akq + i*4;
            float* Bs2 = pool + 4608 + ar*36 + akq + i*4;
            As2[0]=tf32r(av[i].x); As2[1]=tf32r(av[i].y); As2[2]=tf32r(av[i].z); As2[3]=tf32r(av[i].w);
            Bs2[0]=tf32r(bv[i].x); Bs2[1]=tf32r(bv[i].y); Bs2[2]=tf32r(bv[i].z); Bs2[3]=tf32r(bv[i].w);
        }
        __syncthreads();
        #pragma unroll
        for (int kk = 0; kk < 4; kk++) {
            const int k0 = kk*8;
            float a[2][4];
            #pragma unroll
            for (int mi = 0; mi < 2; mi++) {
                const int m0 = warp_m*32 + mi*16;
                a[mi][0] = pool[(m0+g8  )*36 + k0+tig];
                a[mi][1] = pool[(m0+g8+8)*36 + k0+tig];
                a[mi][2] = pool[(m0+g8  )*36 + k0+tig+4];
                a[mi][3] = pool[(m0+g8+8)*36 + k0+tig+4];
            }
            #pragma unroll
            for (int ni = 0; ni < 8; ni++) {
                const int nn = warp_n*64 + ni*8 + g8;
                float bf[2] = {pool[4608 + nn*36 + k0+tig], pool[4608 + nn*36 + k0+tig+4]};
                #pragma unroll
                for (int mi = 0; mi < 2; mi++) mma8(acc[mi][ni], a[mi], bf);
            }
        }
    }
    #pragma unroll
    for (int mi = 0; mi < 2; mi++)
        #pragma unroll
        for (int ni = 0; ni < 8; ni++) {
            const int m = warp_m*32 + mi*16 + g8;
            const int n = c0 + warp_n*64 + ni*8 + tig*2;
            *(float2*)(O + (size_t)m*Cc + n)     = make_float2(acc[mi][ni][0], acc[mi][ni][1]);
            *(float2*)(O + (size_t)(m+8)*Cc + n) = make_float2(acc[mi][ni][2], acc[mi][ni][3]);
        }
}

// final: out = gamma*(oH + oW) + x (NCHW). grid (4,8,1024), block 256.
__global__ __launch_bounds__(256) void final_kernel(
    const float* __restrict__ x, const float* __restrict__ gamma,
    float* __restrict__ out)
{
    __shared__ float sm[32][33];
    const int bh = blockIdx.z, b = bh >> 7, h = bh & 127;
    const int c0 = blockIdx.y*32, w0 = blockIdx.x*32;
    const int t = threadIdx.x;
    const float g = gamma[0];
    {
        const int wr = t >> 3, cq = (t & 7)*4;
        float4 a  = *(const float4*)(g_oH + ((size_t)(b*Wn + w0+wr)*Hh + h)*Cc + c0 + cq);
        float4 bb = *(const float4*)(g_oW + ((size_t)(b*Hh + h)*Wn + w0+wr)*Cc + c0 + cq);
        sm[wr][cq+0] = a.x + bb.x; sm[wr][cq+1] = a.y + bb.y;
        sm[wr][cq+2] = a.z + bb.z; sm[wr][cq+3] = a.w + bb.w;
    }
    __syncthreads();
    {
        const int cr = t >> 3, wq = (t & 7)*4;
        const size_t oidx = ((size_t)(b*Cc + c0 + cr)*Hh + h)*Wn + w0 + wq;
        float4 xr = *(const float4*)(x + oidx);
        float4 r;
        r.x = g*sm[wq+0][cr] + xr.x; r.y = g*sm[wq+1][cr] + xr.y;
        r.z = g*sm[wq+2][cr] + xr.z; r.w = g*sm[wq+3][cr] + xr.w;
        *(float4*)(out + oidx) = r;
    }
}

extern "C" void kernel_launch(void* const* d_in, const int* in_sizes, int n_in,
                              void* d_out, int out_size)
{
    const float* x     = (const float*)d_in[0];
    const float* Wq    = (const float*)d_in[1];
    const float* bq    = (const float*)d_in[2];
    const float* Wk    = (const float*)d_in[3];
    const float* bk    = (const float*)d_in[4];
    const float* Wv    = (const float*)d_in[5];
    const float* bv    = (const float*)d_in[6];
    const float* gamma = (const float*)d_in[7];
    float* out = (float*)d_out;

    prep_kernel<<<320, 256>>>(Wq, bq, Wk, bk, Wv, bv);
    xt_kernel<<<dim3(512, 8, 8), 256>>>(x);
    proj_mma<<<dim3(128, 5, 8), 256>>>();
    vb_kernel<<<dim3(4, 4, 2048), 256>>>();
    score_mma<true ><<<1024, 256>>>();
    score_mma<false><<<1024, 256>>>();
    softmax_kernel<<<16384, 256>>>();
    out_mma<true ><<<dim3(2, 1024), 256>>>();
    out_mma<false><<<dim3(2, 1024), 256>>>();
    final_kernel<<<dim3(4, 8, 1024), 256>>>(x, gamma, out);
}

// round 10
// speedup vs baseline: 1.6598x; 1.2026x over previous
#include <cuda_runtime.h>
#include <cuda_bf16.h>
#include <cstdint>

#define Bn 8
#define Cc 256
#define CQn 32
#define Hh 128
#define Wn 128
#define HWn (Hh*Wn)

__device__ __nv_bfloat16 g_Wh[320*256], g_Wl[320*256];
__device__ float g_bs[320];
__device__ __nv_bfloat16 g_xh[(size_t)Bn*HWn*Cc], g_xl[(size_t)Bn*HWn*Cc]; // [b][p][c]
__device__ float g_q_hw[(size_t)Bn*HWn*CQn], g_q_wh[(size_t)Bn*HWn*CQn];
__device__ float g_k_hw[(size_t)Bn*HWn*CQn], g_k_wh[(size_t)Bn*HWn*CQn];
__device__ __nv_bfloat16 g_va[(size_t)Bn*Cc*HWn];   // [b][c][h][w] bf16
__device__ __nv_bfloat16 g_vb[(size_t)Bn*Cc*HWn];   // [b][c][w][h] bf16
__device__ float g_eH[(size_t)Bn*Wn*Hh*Hh];         // raw scores fp32
__device__ float g_eW[(size_t)Bn*Hh*Wn*Wn];
__device__ __nv_bfloat16 g_aH[(size_t)Bn*Wn*Hh*Hh]; // att bf16
__device__ __nv_bfloat16 g_aW[(size_t)Bn*Hh*Wn*Wn];
__device__ float g_oH[(size_t)Bn*HWn*Cc];           // [b][w][h][c]
__device__ float g_oW[(size_t)Bn*HWn*Cc];           // [b][h][w][c]

__device__ __forceinline__ float neg_inf_f() { return __int_as_float(0xff800000); }
__device__ __forceinline__ uint32_t splitf(float f) {
    __nv_bfloat16 h = __float2bfloat16(f);
    __nv_bfloat16 l = __float2bfloat16(f - __bfloat162float(h));
    return (uint32_t)__bfloat16_as_ushort(h) | ((uint32_t)__bfloat16_as_ushort(l) << 16);
}
__device__ __forceinline__ uint32_t pack2(float a, float b) {
    __nv_bfloat162 v = __floats2bfloat162_rn(a, b);
    return *reinterpret_cast<uint32_t*>(&v);
}
__device__ __forceinline__ void unzip(uint2 p, uint32_t& hi, uint32_t& lo) {
    asm("prmt.b32 %0, %1, %2, 0x5410;" : "=r"(hi) : "r"(p.x), "r"(p.y));
    asm("prmt.b32 %0, %1, %2, 0x7632;" : "=r"(lo) : "r"(p.x), "r"(p.y));
}
__device__ __forceinline__ void mma16(float* d, uint32_t a0, uint32_t a1, uint32_t a2,
                                      uint32_t a3, uint32_t b0, uint32_t b1) {
    asm volatile("mma.sync.aligned.m16n8k16.row.col.f32.bf16.bf16.f32 "
                 "{%0,%1,%2,%3},{%4,%5,%6,%7},{%8,%9},{%0,%1,%2,%3};"
                 : "+f"(d[0]), "+f"(d[1]), "+f"(d[2]), "+f"(d[3])
                 : "r"(a0), "r"(a1), "r"(a2), "r"(a3), "r"(b0), "r"(b1));
}
#define MMA3(acc, ah, al, bh, bl) do { \
    mma16(acc, ah[0], ah[1], ah[2], ah[3], bh##0, bh##1); \
    mma16(acc, ah[0], ah[1], ah[2], ah[3], bl##0, bl##1); \
    mma16(acc, al[0], al[1], al[2], al[3], bh##0, bh##1); } while (0)

// prep: split W rows [Wq;Wk;Wv]. grid 320, block 256.
__global__ __launch_bounds__(256) void prep_kernel(
    const float* __restrict__ Wq, const float* __restrict__ bq,
    const float* __restrict__ Wk, const float* __restrict__ bk,
    const float* __restrict__ Wv, const float* __restrict__ bv)
{
    const int r = blockIdx.x, t = threadIdx.x;
    const float* src; const float* bsrc; int o;
    if (r < 32)      { src = Wq; bsrc = bq; o = r; }
    else if (r < 64) { src = Wk; bsrc = bk; o = r - 32; }
    else             { src = Wv; bsrc = bv; o = r - 64; }
    float v = src[o*256 + t];
    __nv_bfloat16 h = __float2bfloat16(v);
    g_Wh[r*256 + t] = h;
    g_Wl[r*256 + t] = __float2bfloat16(v - __bfloat162float(h));
    if (t == 0) g_bs[r] = bsrc[o];
}

// xt: x[b][c][p] -> split bf16 [b][p][c]. grid (512,8,8), block 256.
__global__ __launch_bounds__(256) void xt_kernel(const float* __restrict__ x)
{
    __shared__ float tl[32][33];
    const int b = blockIdx.z, c0 = blockIdx.y*32, p0 = blockIdx.x*32;
    const int tx = threadIdx.x & 31, ty = threadIdx.x >> 5;
    #pragma unroll
    for (int i = 0; i < 4; i++) {
        int c = ty + i*8;
        tl[c][tx] = x[((size_t)(b*Cc + c0 + c))*HWn + p0 + tx];
    }
    __syncthreads();
    #pragma unroll
    for (int i = 0; i < 4; i++) {
        int p = ty + i*8;
        float v = tl[tx][p];
        __nv_bfloat16 h = __float2bfloat16(v);
        size_t idx = ((size_t)b*HWn + p0 + p)*Cc + c0 + tx;
        g_xh[idx] = h;
        g_xl[idx] = __float2bfloat16(v - __bfloat162float(h));
    }
}

// proj: per (b,h,mt): D[128 px x 64 oc]. mt==0 (q,k): 3-pass. mt>=1 (v): 1-pass.
// grid (128, 5, 8), block 256.
__global__ __launch_bounds__(256) void proj_mma()
{
    __shared__ __align__(16) uint32_t pool[8448];
    __shared__ float s_bias[64];
    const int t = threadIdx.x, wid = t >> 5, lane = t & 31;
    const int g8 = lane >> 2, tig = lane & 3;
    const int warp_m = wid & 3, warp_n = wid >> 2;
    const int h = blockIdx.x, mt = blockIdx.y, b = blockIdx.z;
    const int px0 = h * 128;
    const bool hiPrec = (mt == 0);
    if (t < 64) s_bias[t] = g_bs[mt*64 + t];

    const __nv_bfloat16* Xh = g_xh + ((size_t)b*HWn + px0)*Cc;
    const __nv_bfloat16* Xl = g_xl + ((size_t)b*HWn + px0)*Cc;
    const __nv_bfloat16* Wh = g_Wh + (size_t)mt*64*Cc;
    const __nv_bfloat16* Wl = g_Wl + (size_t)mt*64*Cc;

    float acc[2][4][4] = {};
    const int ar = t >> 1, aw = (t & 1)*8;
    const int br = t >> 2, bw = (t & 3)*4;

    for (int kc = 0; kc < 8; kc++) {
        const size_t ae = (size_t)ar*Cc + kc*32 + aw*2;
        const size_t be = (size_t)br*Cc + kc*32 + bw*2;
        uint4 ah0 = *(const uint4*)(Xh + ae), ah1 = *(const uint4*)(Xh + ae + 8);
        uint4 bh  = *(const uint4*)(Wh + be);
        uint4 al0, al1, bl;
        if (hiPrec) {
            al0 = *(const uint4*)(Xl + ae); al1 = *(const uint4*)(Xl + ae + 8);
            bl  = *(const uint4*)(Wl + be);
        }
        __syncthreads();
        *(uint4*)&pool[ar*20 + aw]        = ah0;
        *(uint4*)&pool[ar*20 + aw + 4]    = ah1;
        *(uint4*)&pool[5120 + br*20 + bw] = bh;
        if (hiPrec) {
            *(uint4*)&pool[2560 + ar*20 + aw]   = al0;
            *(uint4*)&pool[2560 + ar*20 + aw+4] = al1;
            *(uint4*)&pool[6400 + br*20 + bw]   = bl;
        }
        __syncthreads();
        #pragma unroll
        for (int ks = 0; ks < 2; ks++) {
            const int kw = ks*8;
            uint32_t ahf[2][4], alf[2][4];
            #pragma unroll
            for (int mi = 0; mi < 2; mi++) {
                const int m0 = warp_m*32 + mi*16;
                ahf[mi][0] = pool[(m0+g8  )*20 + kw + tig];
                ahf[mi][1] = pool[(m0+g8+8)*20 + kw + tig];
                ahf[mi][2] = pool[(m0+g8  )*20 + kw + tig + 4];
                ahf[mi][3] = pool[(m0+g8+8)*20 + kw + tig + 4];
                if (hiPrec) {
                    alf[mi][0] = pool[2560 + (m0+g8  )*20 + kw + tig];
                    alf[mi][1] = pool[2560 + (m0+g8+8)*20 + kw + tig];
                    alf[mi][2] = pool[2560 + (m0+g8  )*20 + kw + tig + 4];
                    alf[mi][3] = pool[2560 + (m0+g8+8)*20 + kw + tig + 4];
                }
            }
            #pragma unroll
            for (int ni = 0; ni < 4; ni++) {
                const int n = warp_n*32 + ni*8 + g8;
                uint32_t bh0 = pool[5120 + n*20 + kw + tig];
                uint32_t bh1 = pool[5120 + n*20 + kw + tig + 4];
                if (hiPrec) {
                    uint32_t bl0 = pool[6400 + n*20 + kw + tig];
                    uint32_t bl1 = pool[6400 + n*20 + kw + tig + 4];
                    #pragma unroll
                    for (int mi = 0; mi < 2; mi++)
                        MMA3(acc[mi][ni], ahf[mi], alf[mi], bh, bl);
                } else {
                    #pragma unroll
                    for (int mi = 0; mi < 2; mi++)
                        mma16(acc[mi][ni], ahf[mi][0], ahf[mi][1], ahf[mi][2], ahf[mi][3], bh0, bh1);
                }
            }
        }
    }

    if (mt == 0) {
        #pragma unroll
        for (int mi = 0; mi < 2; mi++)
            #pragma unroll
            for (int ni = 0; ni < 4; ni++) {
                const int n = warp_n*32 + ni*8 + tig*2;
                const float b0 = s_bias[n], b1 = s_bias[n+1];
                float* hwp = (n < 32 ? g_q_hw : g_k_hw);
                float* whp = (n < 32 ? g_q_wh : g_k_wh);
                const int o = n & 31;
                #pragma unroll
                for (int hf = 0; hf < 2; hf++) {
                    const int w = warp_m*32 + mi*16 + g8 + hf*8;
                    float2 v = {acc[mi][ni][hf*2] + b0, acc[mi][ni][hf*2+1] + b1};
                    *(float2*)(hwp + ((size_t)(b*Hh + h)*Wn + w)*CQn + o) = v;
                    *(float2*)(whp + ((size_t)(b*Wn + w)*Hh + h)*CQn + o) = v;
                }
            }
    } else {
        float* tb = (float*)pool;   // [64 c][132 px]
        __syncthreads();
        #pragma unroll
        for (int mi = 0; mi < 2; mi++)
            #pragma unroll
            for (int ni = 0; ni < 4; ni++) {
                const int n = warp_n*32 + ni*8 + tig*2;
                const float b0 = s_bias[n], b1 = s_bias[n+1];
                #pragma unroll
                for (int hf = 0; hf < 2; hf++) {
                    const int w = warp_m*32 + mi*16 + g8 + hf*8;
                    tb[n*132 + w]     = acc[mi][ni][hf*2]   + b0;
                    tb[(n+1)*132 + w] = acc[mi][ni][hf*2+1] + b1;
                }
            }
        __syncthreads();
        const int c = t >> 2, p4 = (t & 3)*32;
        uint32_t* dst = (uint32_t*)(g_va + ((size_t)(b*Cc + (mt-1)*64 + c))*HWn + px0 + p4);
        #pragma unroll
        for (int i = 0; i < 32; i += 8) {
            uint4 u;
            u.x = pack2(tb[c*132+p4+i  ], tb[c*132+p4+i+1]);
            u.y = pack2(tb[c*132+p4+i+2], tb[c*132+p4+i+3]);
            u.z = pack2(tb[c*132+p4+i+4], tb[c*132+p4+i+5]);
            u.w = pack2(tb[c*132+p4+i+6], tb[c*132+p4+i+7]);
            *(uint4*)(dst + i/2) = u;
        }
    }
}

// vb: bf16 transpose g_va[c][h][w] -> g_vb[c][w][h], uint32 + prmt.
// grid (2, 2, Bn*Cc), block 256, 64x64 tiles.
__global__ __launch_bounds__(256) void vb_kernel()
{
    __shared__ uint32_t sm[64][33];
    const int bc = blockIdx.z, w0 = blockIdx.x*64, h0 = blockIdx.y*64;
    const int t = threadIdx.x;
    const uint32_t* src = (const uint32_t*)g_va + (size_t)bc*(HWn/2);
    uint32_t* dst = (uint32_t*)g_vb + (size_t)bc*(HWn/2);
    #pragma unroll
    for (int i = 0; i < 8; i++) {
        const int idx = i*256 + t, r = idx >> 5, wd = idx & 31;
        sm[r][wd] = src[(size_t)(h0 + r)*64 + w0/2 + wd];
    }
    __syncthreads();
    #pragma unroll
    for (int i = 0; i < 4; i++) {
        const int idx = i*256 + t, wp = idx >> 5, hp = idx & 31;
        uint32_t u1 = sm[2*hp][wp], u2 = sm[2*hp+1][wp];
        uint32_t lo, hi;
        asm("prmt.b32 %0, %1, %2, 0x5410;" : "=r"(lo) : "r"(u1), "r"(u2));
        asm("prmt.b32 %0, %1, %2, 0x7632;" : "=r"(hi) : "r"(u1), "r"(u2));
        dst[(size_t)(w0 + 2*wp  )*64 + h0/2 + hp] = lo;
        dst[(size_t)(w0 + 2*wp+1)*64 + h0/2 + hp] = hi;
    }
}

// score<ISH>: D[128x128] = Q@K^T (K=32), bf16 3-pass; split in loader.
// grid 1024, block 256.
template <bool ISH>
__global__ __launch_bounds__(256) void score_mma()
{
    __shared__ __align__(16) uint32_t Qs[128][36], Ks[128][36];
    const int bs = blockIdx.x, t = threadIdx.x;
    const int wid = t >> 5, lane = t & 31, g8 = lane >> 2, tig = lane & 3;
    const int warp_m = wid & 3, warp_n = wid >> 2;
    const float* Q = (ISH ? g_q_wh : g_q_hw) + (size_t)bs*128*CQn;
    const float* K = (ISH ? g_k_wh : g_k_hw) + (size_t)bs*128*CQn;
    float* O = (ISH ? g_eH : g_eW) + (size_t)bs*128*128;

    #pragma unroll
    for (int i = 0; i < 4; i++) {
        const int idx = i*256 + t, r = idx >> 3, kq = (idx & 7)*4;
        float4 qv = *(const float4*)(Q + (size_t)r*CQn + kq);
        float4 kv = *(const float4*)(K + (size_t)r*CQn + kq);
        uint4 qp = {splitf(qv.x), splitf(qv.y), splitf(qv.z), splitf(qv.w)};
        uint4 kp = {splitf(kv.x), splitf(kv.y), splitf(kv.z), splitf(kv.w)};
        *(uint4*)&Qs[r][kq] = qp;
        *(uint4*)&Ks[r][kq] = kp;
    }
    __syncthreads();

    float acc[2][8][4] = {};
    #pragma unroll
    for (int ks = 0; ks < 2; ks++) {
        const int k0 = ks*16;
        uint32_t ah[2][4], al[2][4];
        #pragma unroll
        for (int mi = 0; mi < 2; mi++) {
            const int m = warp_m*32 + mi*16;
            unzip(*(uint2*)&Qs[m+g8  ][k0 + 2*tig],     ah[mi][0], al[mi][0]);
            unzip(*(uint2*)&Qs[m+g8+8][k0 + 2*tig],     ah[mi][1], al[mi][1]);
            unzip(*(uint2*)&Qs[m+g8  ][k0 + 8 + 2*tig], ah[mi][2], al[mi][2]);
            unzip(*(uint2*)&Qs[m+g8+8][k0 + 8 + 2*tig], ah[mi][3], al[mi][3]);
        }
        #pragma unroll
        for (int ni = 0; ni < 8; ni++) {
            const int n = warp_n*64 + ni*8 + g8;
            uint32_t bh0, bl0, bh1, bl1;
            unzip(*(uint2*)&Ks[n][k0 + 2*tig],     bh0, bl0);
            unzip(*(uint2*)&Ks[n][k0 + 8 + 2*tig], bh1, bl1);
            #pragma unroll
            for (int mi = 0; mi < 2; mi++) MMA3(acc[mi][ni], ah[mi], al[mi], bh, bl);
        }
    }
    #pragma unroll
    for (int mi = 0; mi < 2; mi++)
        #pragma unroll
        for (int ni = 0; ni < 8; ni++) {
            const int n = warp_n*64 + ni*8 + tig*2;
            #pragma unroll
            for (int hf = 0; hf < 2; hf++) {
                const int m = warp_m*32 + mi*16 + g8 + hf*8;
                float d0 = acc[mi][ni][hf*2], d1 = acc[mi][ni][hf*2+1];
                if (ISH) { if (n == m) d0 = neg_inf_f(); if (n+1 == m) d1 = neg_inf_f(); }
                *(float2*)(O + (size_t)m*128 + n) = make_float2(d0, d1);
            }
        }
}

// softmax: reads fp32 scores, writes bf16 att. grid 16384, block 256.
__global__ __launch_bounds__(256) void softmax_kernel()
{
    const int wid = blockIdx.x*8 + (threadIdx.x >> 5), lane = threadIdx.x & 31;
    const int b = wid >> 14, hw = wid & 16383, h = hw >> 7, w = hw & 127;
    const size_t rH = (size_t)(b*Wn + w)*Hh + h;
    const size_t rW = (size_t)(b*Hh + h)*Wn + w;
    const float* pH = g_eH + rH*Hh;
    const float* pW = g_eW + rW*Wn;
    float4 vh = *(const float4*)(pH + lane*4);
    float4 vw = *(const float4*)(pW + lane*4);
    float m = fmaxf(fmaxf(fmaxf(vh.x,vh.y),fmaxf(vh.z,vh.w)),
                    fmaxf(fmaxf(vw.x,vw.y),fmaxf(vw.z,vw.w)));
    #pragma unroll
    for (int off = 16; off; off >>= 1) m = fmaxf(m, __shfl_xor_sync(~0u, m, off));
    vh.x=__expf(vh.x-m); vh.y=__expf(vh.y-m); vh.z=__expf(vh.z-m); vh.w=__expf(vh.w-m);
    vw.x=__expf(vw.x-m); vw.y=__expf(vw.y-m); vw.z=__expf(vw.z-m); vw.w=__expf(vw.w-m);
    float s = vh.x+vh.y+vh.z+vh.w+vw.x+vw.y+vw.z+vw.w;
    #pragma unroll
    for (int off = 16; off; off >>= 1) s += __shfl_xor_sync(~0u, s, off);
    const float inv = 1.f/s;
    uint32_t* aH = (uint32_t*)g_aH + rH*64;
    uint32_t* aW = (uint32_t*)g_aW + rW*64;
    *(uint2*)(aH + lane*2) = make_uint2(pack2(vh.x*inv, vh.y*inv), pack2(vh.z*inv, vh.w*inv));
    *(uint2*)(aW + lane*2) = make_uint2(pack2(vw.x*inv, vw.y*inv), pack2(vw.z*inv, vw.w*inv));
}

// out<ISH>: D[128 spatial x 128 c] = att(bf16) @ v^T(bf16), 1-pass k16.
// grid (2,1024), block 256.
template <bool ISH>
__global__ __launch_bounds__(256) void out_mma()
{
    __shared__ __align__(16) uint32_t sm[5120];   // As[128][20]@0, Bs@2560
    const int t = threadIdx.x, wid = t >> 5, lane = t & 31;
    const int g8 = lane >> 2, tig = lane & 3;
    const int warp_m = wid & 3, warp_n = wid >> 2;
    const int bs = blockIdx.y, b = bs >> 7, s = bs & 127;
    const int c0 = blockIdx.x * 128;
    const uint32_t* A = (const uint32_t*)(ISH ? g_aH : g_aW) + (size_t)bs*128*64;
    const uint32_t* V = (const uint32_t*)(ISH ? g_vb : g_va) + (size_t)b*Cc*(HWn/2) + s*64;
    float* O = (ISH ? g_oH : g_oW) + (size_t)bs*128*Cc;

    float acc[2][8][4] = {};
    const int r2 = t >> 1, wq = (t & 1)*8;
    for (int kc = 0; kc < 4; kc++) {
        uint4 a0 = *(const uint4*)(A + (size_t)r2*64 + kc*16 + wq);
        uint4 a1 = *(const uint4*)(A + (size_t)r2*64 + kc*16 + wq + 4);
        uint4 b0 = *(const uint4*)(V + (size_t)(c0 + r2)*(HWn/2) + kc*16 + wq);
        uint4 b1 = *(const uint4*)(V + (size_t)(c0 + r2)*(HWn/2) + kc*16 + wq + 4);
        __syncthreads();
        *(uint4*)&sm[r2*20 + wq]          = a0;
        *(uint4*)&sm[r2*20 + wq + 4]      = a1;
        *(uint4*)&sm[2560 + r2*20 + wq]   = b0;
        *(uint4*)&sm[2560 + r2*20 + wq+4] = b1;
        __syncthreads();
        #pragma unroll
        for (int ks = 0; ks < 2; ks++) {
            const int kw = ks*8;
            uint32_t af[2][4];
            #pragma unroll
            for (int mi = 0; mi < 2; mi++) {
                const int m0 = warp_m*32 + mi*16;
                af[mi][0] = sm[(m0+g8  )*20 + kw + tig];
                af[mi][1] = sm[(m0+g8+8)*20 + kw + tig];
                af[mi][2] = sm[(m0+g8  )*20 + kw + tig + 4];
                af[mi][3] = sm[(m0+g8+8)*20 + kw + tig + 4];
            }
            #pragma unroll
            for (int ni = 0; ni < 8; ni++) {
                const int n = warp_n*64 + ni*8 + g8;
                uint32_t bf0 = sm[2560 + n*20 + kw + tig];
                uint32_t bf1 = sm[2560 + n*20 + kw + tig + 4];
                #pragma unroll
                for (int mi = 0; mi < 2; mi++)
                    mma16(acc[mi][ni], af[mi][0], af[mi][1], af[mi][2], af[mi][3], bf0, bf1);
            }
        }
    }
    #pragma unroll
    for (int mi = 0; mi < 2; mi++)
        #pragma unroll
        for (int ni = 0; ni < 8; ni++) {
            const int m = warp_m*32 + mi*16 + g8;
            const int n = c0 + warp_n*64 + ni*8 + tig*2;
            *(float2*)(O + (size_t)m*Cc + n)     = make_float2(acc[mi][ni][0], acc[mi][ni][1]);
            *(float2*)(O + (size_t)(m+8)*Cc + n) = make_float2(acc[mi][ni][2], acc[mi][ni][3]);
        }
}

// final: out = gamma*(oH + oW) + x. grid (4,8,1024), block 256.
__global__ __launch_bounds__(256) void final_kernel(
    const float* __restrict__ x, const float* __restrict__ gamma,
    float* __restrict__ out)
{
    __shared__ float sm[32][33];
    const int bh = blockIdx.z, b = bh >> 7, h = bh & 127;
    const int c0 = blockIdx.y*32, w0 = blockIdx.x*32;
    const int t = threadIdx.x;
    const float g = gamma[0];
    {
        const int wr = t >> 3, cq = (t & 7)*4;
        float4 a  = *(const float4*)(g_oH + ((size_t)(b*Wn + w0+wr)*Hh + h)*Cc + c0 + cq);
        float4 bb = *(const float4*)(g_oW + ((size_t)(b*Hh + h)*Wn + w0+wr)*Cc + c0 + cq);
        sm[wr][cq+0] = a.x + bb.x; sm[wr][cq+1] = a.y + bb.y;
        sm[wr][cq+2] = a.z + bb.z; sm[wr][cq+3] = a.w + bb.w;
    }
    __syncthreads();
    {
        const int cr = t >> 3, wq = (t & 7)*4;
        const size_t oidx = ((size_t)(b*Cc + c0 + cr)*Hh + h)*Wn + w0 + wq;
        float4 xr = *(const float4*)(x + oidx);
        float4 r;
        r.x = g*sm[wq+0][cr] + xr.x; r.y = g*sm[wq+1][cr] + xr.y;
        r.z = g*sm[wq+2][cr] + xr.z; r.w = g*sm[wq+3][cr] + xr.w;
        *(float4*)(out + oidx) = r;
    }
}

extern "C" void kernel_launch(void* const* d_in, const int* in_sizes, int n_in,
                              void* d_out, int out_size)
{
    const float* x     = (const float*)d_in[0];
    const float* Wq    = (const float*)d_in[1];
    const float* bq    = (const float*)d_in[2];
    const float* Wk    = (const float*)d_in[3];
    const float* bk    = (const float*)d_in[4];
    const float* Wv    = (const float*)d_in[5];
    const float* bv    = (const float*)d_in[6];
    const float* gamma = (const float*)d_in[7];
    float* out = (float*)d_out;

    prep_kernel<<<320, 256>>>(Wq, bq, Wk, bk, Wv, bv);
    xt_kernel<<<dim3(512, 8, 8), 256>>>(x);
    proj_mma<<<dim3(128, 5, 8), 256>>>();
    vb_kernel<<<dim3(2, 2, Bn*Cc), 256>>>();
    score_mma<true ><<<1024, 256>>>();
    score_mma<false><<<1024, 256>>>();
    softmax_kernel<<<16384, 256>>>();
    out_mma<true ><<<dim3(2, 1024), 256>>>();
    out_mma<false><<<dim3(2, 1024), 256>>>();
    final_kernel<<<dim3(4, 8, 1024), 256>>>(x, gamma, out);
}

// round 11
// speedup vs baseline: 1.7152x; 1.0334x over previous
#include <cuda_runtime.h>
#include <cuda_bf16.h>
#include <cstdint>

#define Bn 8
#define Cc 256
#define CQn 32
#define Hh 128
#define Wn 128
#define HWn (Hh*Wn)

__device__ __nv_bfloat16 g_Wh[320*256], g_Wl[320*256];
__device__ float g_bs[320];
__device__ __nv_bfloat16 g_xh[(size_t)Bn*HWn*Cc], g_xl[(size_t)Bn*HWn*Cc]; // [b][p][c]
__device__ float g_q_hw[(size_t)Bn*HWn*CQn], g_q_wh[(size_t)Bn*HWn*CQn];
__device__ float g_k_hw[(size_t)Bn*HWn*CQn], g_k_wh[(size_t)Bn*HWn*CQn];
__device__ __nv_bfloat16 g_va[(size_t)Bn*Cc*HWn];   // [b][c][h][w] bf16
__device__ __nv_bfloat16 g_vb[(size_t)Bn*Cc*HWn];   // [b][c][w][h] bf16
__device__ float g_eH[(size_t)Bn*Wn*Hh*Hh];         // raw scores fp32
__device__ float g_eW[(size_t)Bn*Hh*Wn*Wn];
__device__ __nv_bfloat16 g_aH[(size_t)Bn*Wn*Hh*Hh]; // att bf16
__device__ __nv_bfloat16 g_aW[(size_t)Bn*Hh*Wn*Wn];
__device__ float g_oH[(size_t)Bn*HWn*Cc];           // [b][h][w][c]  (NEW layout)

__device__ __forceinline__ float neg_inf_f() { return __int_as_float(0xff800000); }
__device__ __forceinline__ uint32_t splitf(float f) {
    __nv_bfloat16 h = __float2bfloat16(f);
    __nv_bfloat16 l = __float2bfloat16(f - __bfloat162float(h));
    return (uint32_t)__bfloat16_as_ushort(h) | ((uint32_t)__bfloat16_as_ushort(l) << 16);
}
__device__ __forceinline__ uint32_t pack2(float a, float b) {
    __nv_bfloat162 v = __floats2bfloat162_rn(a, b);
    return *reinterpret_cast<uint32_t*>(&v);
}
__device__ __forceinline__ void unzip(uint2 p, uint32_t& hi, uint32_t& lo) {
    asm("prmt.b32 %0, %1, %2, 0x5410;" : "=r"(hi) : "r"(p.x), "r"(p.y));
    asm("prmt.b32 %0, %1, %2, 0x7632;" : "=r"(lo) : "r"(p.x), "r"(p.y));
}
__device__ __forceinline__ void mma16(float* d, uint32_t a0, uint32_t a1, uint32_t a2,
                                      uint32_t a3, uint32_t b0, uint32_t b1) {
    asm volatile("mma.sync.aligned.m16n8k16.row.col.f32.bf16.bf16.f32 "
                 "{%0,%1,%2,%3},{%4,%5,%6,%7},{%8,%9},{%0,%1,%2,%3};"
                 : "+f"(d[0]), "+f"(d[1]), "+f"(d[2]), "+f"(d[3])
                 : "r"(a0), "r"(a1), "r"(a2), "r"(a3), "r"(b0), "r"(b1));
}
#define MMA3(acc, ah, al, bh, bl) do { \
    mma16(acc, ah[0], ah[1], ah[2], ah[3], bh##0, bh##1); \
    mma16(acc, ah[0], ah[1], ah[2], ah[3], bl##0, bl##1); \
    mma16(acc, al[0], al[1], al[2], al[3], bh##0, bh##1); } while (0)

// prep: split W rows [Wq;Wk;Wv]. grid 320, block 256.
__global__ __launch_bounds__(256) void prep_kernel(
    const float* __restrict__ Wq, const float* __restrict__ bq,
    const float* __restrict__ Wk, const float* __restrict__ bk,
    const float* __restrict__ Wv, const float* __restrict__ bv)
{
    const int r = blockIdx.x, t = threadIdx.x;
    const float* src; const float* bsrc; int o;
    if (r < 32)      { src = Wq; bsrc = bq; o = r; }
    else if (r < 64) { src = Wk; bsrc = bk; o = r - 32; }
    else             { src = Wv; bsrc = bv; o = r - 64; }
    float v = src[o*256 + t];
    __nv_bfloat16 h = __float2bfloat16(v);
    g_Wh[r*256 + t] = h;
    g_Wl[r*256 + t] = __float2bfloat16(v - __bfloat162float(h));
    if (t == 0) g_bs[r] = bsrc[o];
}

// xt: x[b][c][p] -> split bf16 [b][p][c]. grid (512,8,8), block 256.
__global__ __launch_bounds__(256) void xt_kernel(const float* __restrict__ x)
{
    __shared__ float tl[32][33];
    const int b = blockIdx.z, c0 = blockIdx.y*32, p0 = blockIdx.x*32;
    const int tx = threadIdx.x & 31, ty = threadIdx.x >> 5;
    #pragma unroll
    for (int i = 0; i < 4; i++) {
        int c = ty + i*8;
        tl[c][tx] = x[((size_t)(b*Cc + c0 + c))*HWn + p0 + tx];
    }
    __syncthreads();
    #pragma unroll
    for (int i = 0; i < 4; i++) {
        int p = ty + i*8;
        float v = tl[tx][p];
        __nv_bfloat16 h = __float2bfloat16(v);
        size_t idx = ((size_t)b*HWn + p0 + p)*Cc + c0 + tx;
        g_xh[idx] = h;
        g_xl[idx] = __float2bfloat16(v - __bfloat162float(h));
    }
}

// proj: per (mt,h,b): D[128 px x 64 oc]. mt==0 (q,k): 3-pass. mt>=1 (v): 1-pass.
// grid (5, 128, 8) — mt FASTEST so the 5 blocks sharing an x tile hit L2.
__global__ __launch_bounds__(256) void proj_mma()
{
    __shared__ __align__(16) uint32_t pool[8448];
    __shared__ float s_bias[64];
    const int t = threadIdx.x, wid = t >> 5, lane = t & 31;
    const int g8 = lane >> 2, tig = lane & 3;
    const int warp_m = wid & 3, warp_n = wid >> 2;
    const int mt = blockIdx.x, h = blockIdx.y, b = blockIdx.z;
    const int px0 = h * 128;
    const bool hiPrec = (mt == 0);
    if (t < 64) s_bias[t] = g_bs[mt*64 + t];

    const __nv_bfloat16* Xh = g_xh + ((size_t)b*HWn + px0)*Cc;
    const __nv_bfloat16* Xl = g_xl + ((size_t)b*HWn + px0)*Cc;
    const __nv_bfloat16* Wh = g_Wh + (size_t)mt*64*Cc;
    const __nv_bfloat16* Wl = g_Wl + (size_t)mt*64*Cc;

    float acc[2][4][4] = {};
    const int ar = t >> 1, aw = (t & 1)*8;
    const int br = t >> 2, bw = (t & 3)*4;

    for (int kc = 0; kc < 8; kc++) {
        const size_t ae = (size_t)ar*Cc + kc*32 + aw*2;
        const size_t be = (size_t)br*Cc + kc*32 + bw*2;
        uint4 ah0 = *(const uint4*)(Xh + ae), ah1 = *(const uint4*)(Xh + ae + 8);
        uint4 bh  = *(const uint4*)(Wh + be);
        uint4 al0, al1, bl;
        if (hiPrec) {
            al0 = *(const uint4*)(Xl + ae); al1 = *(const uint4*)(Xl + ae + 8);
            bl  = *(const uint4*)(Wl + be);
        }
        __syncthreads();
        *(uint4*)&pool[ar*20 + aw]        = ah0;
        *(uint4*)&pool[ar*20 + aw + 4]    = ah1;
        *(uint4*)&pool[5120 + br*20 + bw] = bh;
        if (hiPrec) {
            *(uint4*)&pool[2560 + ar*20 + aw]   = al0;
            *(uint4*)&pool[2560 + ar*20 + aw+4] = al1;
            *(uint4*)&pool[6400 + br*20 + bw]   = bl;
        }
        __syncthreads();
        #pragma unroll
        for (int ks = 0; ks < 2; ks++) {
            const int kw = ks*8;
            uint32_t ahf[2][4], alf[2][4];
            #pragma unroll
            for (int mi = 0; mi < 2; mi++) {
                const int m0 = warp_m*32 + mi*16;
                ahf[mi][0] = pool[(m0+g8  )*20 + kw + tig];
                ahf[mi][1] = pool[(m0+g8+8)*20 + kw + tig];
                ahf[mi][2] = pool[(m0+g8  )*20 + kw + tig + 4];
                ahf[mi][3] = pool[(m0+g8+8)*20 + kw + tig + 4];
                if (hiPrec) {
                    alf[mi][0] = pool[2560 + (m0+g8  )*20 + kw + tig];
                    alf[mi][1] = pool[2560 + (m0+g8+8)*20 + kw + tig];
                    alf[mi][2] = pool[2560 + (m0+g8  )*20 + kw + tig + 4];
                    alf[mi][3] = pool[2560 + (m0+g8+8)*20 + kw + tig + 4];
                }
            }
            #pragma unroll
            for (int ni = 0; ni < 4; ni++) {
                const int n = warp_n*32 + ni*8 + g8;
                uint32_t bh0 = pool[5120 + n*20 + kw + tig];
                uint32_t bh1 = pool[5120 + n*20 + kw + tig + 4];
                if (hiPrec) {
                    uint32_t bl0 = pool[6400 + n*20 + kw + tig];
                    uint32_t bl1 = pool[6400 + n*20 + kw + tig + 4];
                    #pragma unroll
                    for (int mi = 0; mi < 2; mi++)
                        MMA3(acc[mi][ni], ahf[mi], alf[mi], bh, bl);
                } else {
                    #pragma unroll
                    for (int mi = 0; mi < 2; mi++)
                        mma16(acc[mi][ni], ahf[mi][0], ahf[mi][1], ahf[mi][2], ahf[mi][3], bh0, bh1);
                }
            }
        }
    }

    if (mt == 0) {
        #pragma unroll
        for (int mi = 0; mi < 2; mi++)
            #pragma unroll
            for (int ni = 0; ni < 4; ni++) {
                const int n = warp_n*32 + ni*8 + tig*2;
                const float b0 = s_bias[n], b1 = s_bias[n+1];
                float* hwp = (n < 32 ? g_q_hw : g_k_hw);
                float* whp = (n < 32 ? g_q_wh : g_k_wh);
                const int o = n & 31;
                #pragma unroll
                for (int hf = 0; hf < 2; hf++) {
                    const int w = warp_m*32 + mi*16 + g8 + hf*8;
                    float2 v = {acc[mi][ni][hf*2] + b0, acc[mi][ni][hf*2+1] + b1};
                    *(float2*)(hwp + ((size_t)(b*Hh + h)*Wn + w)*CQn + o) = v;
                    *(float2*)(whp + ((size_t)(b*Wn + w)*Hh + h)*CQn + o) = v;
                }
            }
    } else {
        float* tb = (float*)pool;   // [64 c][132 px]
        __syncthreads();
        #pragma unroll
        for (int mi = 0; mi < 2; mi++)
            #pragma unroll
            for (int ni = 0; ni < 4; ni++) {
                const int n = warp_n*32 + ni*8 + tig*2;
                const float b0 = s_bias[n], b1 = s_bias[n+1];
                #pragma unroll
                for (int hf = 0; hf < 2; hf++) {
                    const int w = warp_m*32 + mi*16 + g8 + hf*8;
                    tb[n*132 + w]     = acc[mi][ni][hf*2]   + b0;
                    tb[(n+1)*132 + w] = acc[mi][ni][hf*2+1] + b1;
                }
            }
        __syncthreads();
        const int c = t >> 2, p4 = (t & 3)*32;
        uint32_t* dst = (uint32_t*)(g_va + ((size_t)(b*Cc + (mt-1)*64 + c))*HWn + px0 + p4);
        #pragma unroll
        for (int i = 0; i < 32; i += 8) {
            uint4 u;
            u.x = pack2(tb[c*132+p4+i  ], tb[c*132+p4+i+1]);
            u.y = pack2(tb[c*132+p4+i+2], tb[c*132+p4+i+3]);
            u.z = pack2(tb[c*132+p4+i+4], tb[c*132+p4+i+5]);
            u.w = pack2(tb[c*132+p4+i+6], tb[c*132+p4+i+7]);
            *(uint4*)(dst + i/2) = u;
        }
    }
}

// vb: bf16 transpose g_va[c][h][w] -> g_vb[c][w][h]. grid (2,2,Bn*Cc), block 256.
__global__ __launch_bounds__(256) void vb_kernel()
{
    __shared__ uint32_t sm[64][33];
    const int bc = blockIdx.z, w0 = blockIdx.x*64, h0 = blockIdx.y*64;
    const int t = threadIdx.x;
    const uint32_t* src = (const uint32_t*)g_va + (size_t)bc*(HWn/2);
    uint32_t* dst = (uint32_t*)g_vb + (size_t)bc*(HWn/2);
    #pragma unroll
    for (int i = 0; i < 8; i++) {
        const int idx = i*256 + t, r = idx >> 5, wd = idx & 31;
        sm[r][wd] = src[(size_t)(h0 + r)*64 + w0/2 + wd];
    }
    __syncthreads();
    #pragma unroll
    for (int i = 0; i < 4; i++) {
        const int idx = i*256 + t, wp = idx >> 5, hp = idx & 31;
        uint32_t u1 = sm[2*hp][wp], u2 = sm[2*hp+1][wp];
        uint32_t lo, hi;
        asm("prmt.b32 %0, %1, %2, 0x5410;" : "=r"(lo) : "r"(u1), "r"(u2));
        asm("prmt.b32 %0, %1, %2, 0x7632;" : "=r"(hi) : "r"(u1), "r"(u2));
        dst[(size_t)(w0 + 2*wp  )*64 + h0/2 + hp] = lo;
        dst[(size_t)(w0 + 2*wp+1)*64 + h0/2 + hp] = hi;
    }
}

// score<ISH>: D[128x128] = Q@K^T (K=32), bf16 3-pass; split in loader.
// grid 1024, block 256.
template <bool ISH>
__global__ __launch_bounds__(256) void score_mma()
{
    __shared__ __align__(16) uint32_t Qs[128][36], Ks[128][36];
    const int bs = blockIdx.x, t = threadIdx.x;
    const int wid = t >> 5, lane = t & 31, g8 = lane >> 2, tig = lane & 3;
    const int warp_m = wid & 3, warp_n = wid >> 2;
    const float* Q = (ISH ? g_q_wh : g_q_hw) + (size_t)bs*128*CQn;
    const float* K = (ISH ? g_k_wh : g_k_hw) + (size_t)bs*128*CQn;
    float* O = (ISH ? g_eH : g_eW) + (size_t)bs*128*128;

    #pragma unroll
    for (int i = 0; i < 4; i++) {
        const int idx = i*256 + t, r = idx >> 3, kq = (idx & 7)*4;
        float4 qv = *(const float4*)(Q + (size_t)r*CQn + kq);
        float4 kv = *(const float4*)(K + (size_t)r*CQn + kq);
        uint4 qp = {splitf(qv.x), splitf(qv.y), splitf(qv.z), splitf(qv.w)};
        uint4 kp = {splitf(kv.x), splitf(kv.y), splitf(kv.z), splitf(kv.w)};
        *(uint4*)&Qs[r][kq] = qp;
        *(uint4*)&Ks[r][kq] = kp;
    }
    __syncthreads();

    float acc[2][8][4] = {};
    #pragma unroll
    for (int ks = 0; ks < 2; ks++) {
        const int k0 = ks*16;
        uint32_t ah[2][4], al[2][4];
        #pragma unroll
        for (int mi = 0; mi < 2; mi++) {
            const int m = warp_m*32 + mi*16;
            unzip(*(uint2*)&Qs[m+g8  ][k0 + 2*tig],     ah[mi][0], al[mi][0]);
            unzip(*(uint2*)&Qs[m+g8+8][k0 + 2*tig],     ah[mi][1], al[mi][1]);
            unzip(*(uint2*)&Qs[m+g8  ][k0 + 8 + 2*tig], ah[mi][2], al[mi][2]);
            unzip(*(uint2*)&Qs[m+g8+8][k0 + 8 + 2*tig], ah[mi][3], al[mi][3]);
        }
        #pragma unroll
        for (int ni = 0; ni < 8; ni++) {
            const int n = warp_n*64 + ni*8 + g8;
            uint32_t bh0, bl0, bh1, bl1;
            unzip(*(uint2*)&Ks[n][k0 + 2*tig],     bh0, bl0);
            unzip(*(uint2*)&Ks[n][k0 + 8 + 2*tig], bh1, bl1);
            #pragma unroll
            for (int mi = 0; mi < 2; mi++) MMA3(acc[mi][ni], ah[mi], al[mi], bh, bl);
        }
    }
    #pragma unroll
    for (int mi = 0; mi < 2; mi++)
        #pragma unroll
        for (int ni = 0; ni < 8; ni++) {
            const int n = warp_n*64 + ni*8 + tig*2;
            #pragma unroll
            for (int hf = 0; hf < 2; hf++) {
                const int m = warp_m*32 + mi*16 + g8 + hf*8;
                float d0 = acc[mi][ni][hf*2], d1 = acc[mi][ni][hf*2+1];
                if (ISH) { if (n == m) d0 = neg_inf_f(); if (n+1 == m) d1 = neg_inf_f(); }
                *(float2*)(O + (size_t)m*128 + n) = make_float2(d0, d1);
            }
        }
}

// softmax: reads fp32 scores, writes bf16 att. grid 16384, block 256.
__global__ __launch_bounds__(256) void softmax_kernel()
{
    const int wid = blockIdx.x*8 + (threadIdx.x >> 5), lane = threadIdx.x & 31;
    const int b = wid >> 14, hw = wid & 16383, h = hw >> 7, w = hw & 127;
    const size_t rH = (size_t)(b*Wn + w)*Hh + h;
    const size_t rW = (size_t)(b*Hh + h)*Wn + w;
    const float* pH = g_eH + rH*Hh;
    const float* pW = g_eW + rW*Wn;
    float4 vh = *(const float4*)(pH + lane*4);
    float4 vw = *(const float4*)(pW + lane*4);
    float m = fmaxf(fmaxf(fmaxf(vh.x,vh.y),fmaxf(vh.z,vh.w)),
                    fmaxf(fmaxf(vw.x,vw.y),fmaxf(vw.z,vw.w)));
    #pragma unroll
    for (int off = 16; off; off >>= 1) m = fmaxf(m, __shfl_xor_sync(~0u, m, off));
    vh.x=__expf(vh.x-m); vh.y=__expf(vh.y-m); vh.z=__expf(vh.z-m); vh.w=__expf(vh.w-m);
    vw.x=__expf(vw.x-m); vw.y=__expf(vw.y-m); vw.z=__expf(vw.z-m); vw.w=__expf(vw.w-m);
    float s = vh.x+vh.y+vh.z+vh.w+vw.x+vw.y+vw.z+vw.w;
    #pragma unroll
    for (int off = 16; off; off >>= 1) s += __shfl_xor_sync(~0u, s, off);
    const float inv = 1.f/s;
    uint32_t* aH = (uint32_t*)g_aH + rH*64;
    uint32_t* aW = (uint32_t*)g_aW + rW*64;
    *(uint2*)(aH + lane*2) = make_uint2(pack2(vh.x*inv, vh.y*inv), pack2(vh.z*inv, vh.w*inv));
    *(uint2*)(aW + lane*2) = make_uint2(pack2(vw.x*inv, vw.y*inv), pack2(vw.z*inv, vw.w*inv));
}

// out<ISH>: D[128 spatial x 128 c] = att(bf16) @ v^T(bf16), 1-pass k16.
// ISH: writes g_oH[b][h][w][c]. !ISH: adds oH (coalesced) and emits
// gamma*(D+oH)+x -> out via 32-channel smem transposes. grid (2,1024), block 256.
template <bool ISH>
__global__ __launch_bounds__(256) void out_mma(const float* __restrict__ x,
                                               const float* __restrict__ gamma,
                                               float* __restrict__ out)
{
    __shared__ __align__(16) uint32_t sm[5120];   // As[128][20]@0, Bs@2560; tb[32][132] reuse
    const int t = threadIdx.x, wid = t >> 5, lane = t & 31;
    const int g8 = lane >> 2, tig = lane & 3;
    const int warp_m = wid & 3, warp_n = wid >> 2;
    const int bs = blockIdx.y, b = bs >> 7, s = bs & 127;
    const int c0 = blockIdx.x * 128;
    const uint32_t* A = (const uint32_t*)(ISH ? g_aH : g_aW) + (size_t)bs*128*64;
    const uint32_t* V = (const uint32_t*)(ISH ? g_vb : g_va) + (size_t)b*Cc*(HWn/2) + s*64;

    float acc[2][8][4] = {};
    const int r2 = t >> 1, wq = (t & 1)*8;
    for (int kc = 0; kc < 4; kc++) {
        uint4 a0 = *(const uint4*)(A + (size_t)r2*64 + kc*16 + wq);
        uint4 a1 = *(const uint4*)(A + (size_t)r2*64 + kc*16 + wq + 4);
        uint4 b0 = *(const uint4*)(V + (size_t)(c0 + r2)*(HWn/2) + kc*16 + wq);
        uint4 b1 = *(const uint4*)(V + (size_t)(c0 + r2)*(HWn/2) + kc*16 + wq + 4);
        __syncthreads();
        *(uint4*)&sm[r2*20 + wq]          = a0;
        *(uint4*)&sm[r2*20 + wq + 4]      = a1;
        *(uint4*)&sm[2560 + r2*20 + wq]   = b0;
        *(uint4*)&sm[2560 + r2*20 + wq+4] = b1;
        __syncthreads();
        #pragma unroll
        for (int ks = 0; ks < 2; ks++) {
            const int kw = ks*8;
            uint32_t af[2][4];
            #pragma unroll
            for (int mi = 0; mi < 2; mi++) {
                const int m0 = warp_m*32 + mi*16;
                af[mi][0] = sm[(m0+g8  )*20 + kw + tig];
                af[mi][1] = sm[(m0+g8+8)*20 + kw + tig];
                af[mi][2] = sm[(m0+g8  )*20 + kw + tig + 4];
                af[mi][3] = sm[(m0+g8+8)*20 + kw + tig + 4];
            }
            #pragma unroll
            for (int ni = 0; ni < 8; ni++) {
                const int n = warp_n*64 + ni*8 + g8;
                uint32_t bf0 = sm[2560 + n*20 + kw + tig];
                uint32_t bf1 = sm[2560 + n*20 + kw + tig + 4];
                #pragma unroll
                for (int mi = 0; mi < 2; mi++)
                    mma16(acc[mi][ni], af[mi][0], af[mi][1], af[mi][2], af[mi][3], bf0, bf1);
            }
        }
    }

    if (ISH) {
        // oH[b][h=m][w=s][c]
        #pragma unroll
        for (int mi = 0; mi < 2; mi++)
            #pragma unroll
            for (int ni = 0; ni < 8; ni++) {
                const int m = warp_m*32 + mi*16 + g8;
                const int n = c0 + warp_n*64 + ni*8 + tig*2;
                *(float2*)(g_oH + ((size_t)(b*Hh + m)*Wn + s)*Cc + n) =
                    make_float2(acc[mi][ni][0], acc[mi][ni][1]);
                *(float2*)(g_oH + ((size_t)(b*Hh + m+8)*Wn + s)*Cc + n) =
                    make_float2(acc[mi][ni][2], acc[mi][ni][3]);
            }
    } else {
        // Add oH slice [w][c] (contiguous, matches D layout) in-register.
        const float gm = gamma[0];
        const float* o1 = g_oH + (size_t)(b*Hh + s)*Wn*Cc;
        #pragma unroll
        for (int mi = 0; mi < 2; mi++)
            #pragma unroll
            for (int ni = 0; ni < 8; ni++) {
                const int m = warp_m*32 + mi*16 + g8;
                const int n = c0 + warp_n*64 + ni*8 + tig*2;
                float2 p0 = *(const float2*)(o1 + (size_t)m*Cc + n);
                float2 p1 = *(const float2*)(o1 + (size_t)(m+8)*Cc + n);
                acc[mi][ni][0] += p0.x; acc[mi][ni][1] += p0.y;
                acc[mi][ni][2] += p1.x; acc[mi][ni][3] += p1.y;
            }
        // Emit out[b][c][h=s][w] = gm*sum + x, 4 chunks of 32 channels.
        float* tb = (float*)sm;     // [32][132] floats = 16.9KB <= 20KB
        #pragma unroll
        for (int cc = 0; cc < 4; cc++) {
            __syncthreads();
            if (warp_n == (cc >> 1)) {
                const int nib = (cc & 1)*4;
                #pragma unroll
                for (int mi = 0; mi < 2; mi++)
                    #pragma unroll
                    for (int nj = 0; nj < 4; nj++) {
                        const int ni = nib + nj;
                        const int nl = nj*8 + tig*2;
                        const int m = warp_m*32 + mi*16 + g8;
                        tb[nl*132 + m]       = acc[mi][ni][0];
                        tb[(nl+1)*132 + m]   = acc[mi][ni][1];
                        tb[nl*132 + m+8]     = acc[mi][ni][2];
                        tb[(nl+1)*132 + m+8] = acc[mi][ni][3];
                    }
            }
            __syncthreads();
            #pragma unroll
            for (int p = 0; p < 4; p++) {
                const int ci = (t >> 5) + p*8;
                const int w4 = (t & 31)*4;
                const size_t oidx = ((size_t)(b*Cc + c0 + cc*32 + ci)*Hh + s)*Wn + w4;
                float4 xr = *(const float4*)(x + oidx);
                float4 r;
                r.x = gm*tb[ci*132 + w4  ] + xr.x;
                r.y = gm*tb[ci*132 + w4+1] + xr.y;
                r.z = gm*tb[ci*132 + w4+2] + xr.z;
                r.w = gm*tb[ci*132 + w4+3] + xr.w;
                *(float4*)(out + oidx) = r;
            }
        }
    }
}

extern "C" void kernel_launch(void* const* d_in, const int* in_sizes, int n_in,
                              void* d_out, int out_size)
{
    const float* x     = (const float*)d_in[0];
    const float* Wq    = (const float*)d_in[1];
    const float* bq    = (const float*)d_in[2];
    const float* Wk    = (const float*)d_in[3];
    const float* bk    = (const float*)d_in[4];
    const float* Wv    = (const float*)d_in[5];
    const float* bv    = (const float*)d_in[6];
    const float* gamma = (const float*)d_in[7];
    float* out = (float*)d_out;

    prep_kernel<<<320, 256>>>(Wq, bq, Wk, bk, Wv, bv);
    xt_kernel<<<dim3(512, 8, 8), 256>>>(x);
    proj_mma<<<dim3(5, 128, 8), 256>>>();
    vb_kernel<<<dim3(2, 2, Bn*Cc), 256>>>();
    score_mma<true ><<<1024, 256>>>();
    score_mma<false><<<1024, 256>>>();
    softmax_kernel<<<16384, 256>>>();
    out_mma<true ><<<dim3(2, 1024), 256>>>(x, gamma, out);
    out_mma<false><<<dim3(2, 1024), 256>>>(x, gamma, out);
}

// round 12
// speedup vs baseline: 1.7793x; 1.0373x over previous
#include <cuda_runtime.h>
#include <cuda_bf16.h>
#include <cstdint>

#define Bn 8
#define Cc 256
#define CQn 32
#define Hh 128
#define Wn 128
#define HWn (Hh*Wn)

__device__ __nv_bfloat16 g_Wh[320*256], g_Wl[320*256];
__device__ float g_bs[320];
__device__ __nv_bfloat16 g_xh[(size_t)Bn*HWn*Cc], g_xl[(size_t)Bn*HWn*Cc]; // [b][p][c]
__device__ float g_q_hw[(size_t)Bn*HWn*CQn], g_q_wh[(size_t)Bn*HWn*CQn];
__device__ float g_k_hw[(size_t)Bn*HWn*CQn], g_k_wh[(size_t)Bn*HWn*CQn];
__device__ __nv_bfloat16 g_va[(size_t)Bn*Cc*HWn];   // [b][c][h][w] bf16
__device__ __nv_bfloat16 g_vb[(size_t)Bn*Cc*HWn];   // [b][c][w][h] bf16
__device__ __nv_bfloat16 g_aH[(size_t)Bn*Wn*Hh*Hh]; // scores -> att (in place, bf16)
__device__ __nv_bfloat16 g_aW[(size_t)Bn*Hh*Wn*Wn];
__device__ __nv_bfloat16 g_oH[(size_t)Bn*HWn*Cc];   // [b][h][w][c] bf16

__device__ __forceinline__ float neg_inf_f() { return __int_as_float(0xff800000); }
__device__ __forceinline__ uint32_t splitf(float f) {
    __nv_bfloat16 h = __float2bfloat16(f);
    __nv_bfloat16 l = __float2bfloat16(f - __bfloat162float(h));
    return (uint32_t)__bfloat16_as_ushort(h) | ((uint32_t)__bfloat16_as_ushort(l) << 16);
}
__device__ __forceinline__ uint32_t pack2(float a, float b) {
    __nv_bfloat162 v = __floats2bfloat162_rn(a, b);
    return *reinterpret_cast<uint32_t*>(&v);
}
__device__ __forceinline__ float2 unpack2f(uint32_t u) {
    __nv_bfloat162 v = *reinterpret_cast<__nv_bfloat162*>(&u);
    return __bfloat1622float2(v);
}
__device__ __forceinline__ void unzip(uint2 p, uint32_t& hi, uint32_t& lo) {
    asm("prmt.b32 %0, %1, %2, 0x5410;" : "=r"(hi) : "r"(p.x), "r"(p.y));
    asm("prmt.b32 %0, %1, %2, 0x7632;" : "=r"(lo) : "r"(p.x), "r"(p.y));
}
__device__ __forceinline__ void mma16(float* d, uint32_t a0, uint32_t a1, uint32_t a2,
                                      uint32_t a3, uint32_t b0, uint32_t b1) {
    asm volatile("mma.sync.aligned.m16n8k16.row.col.f32.bf16.bf16.f32 "
                 "{%0,%1,%2,%3},{%4,%5,%6,%7},{%8,%9},{%0,%1,%2,%3};"
                 : "+f"(d[0]), "+f"(d[1]), "+f"(d[2]), "+f"(d[3])
                 : "r"(a0), "r"(a1), "r"(a2), "r"(a3), "r"(b0), "r"(b1));
}
#define MMA3(acc, ah, al, bh, bl) do { \
    mma16(acc, ah[0], ah[1], ah[2], ah[3], bh##0, bh##1); \
    mma16(acc, ah[0], ah[1], ah[2], ah[3], bl##0, bl##1); \
    mma16(acc, al[0], al[1], al[2], al[3], bh##0, bh##1); } while (0)

// prep: split W rows [Wq;Wk;Wv]. grid 320, block 256.
__global__ __launch_bounds__(256) void prep_kernel(
    const float* __restrict__ Wq, const float* __restrict__ bq,
    const float* __restrict__ Wk, const float* __restrict__ bk,
    const float* __restrict__ Wv, const float* __restrict__ bv)
{
    const int r = blockIdx.x, t = threadIdx.x;
    const float* src; const float* bsrc; int o;
    if (r < 32)      { src = Wq; bsrc = bq; o = r; }
    else if (r < 64) { src = Wk; bsrc = bk; o = r - 32; }
    else             { src = Wv; bsrc = bv; o = r - 64; }
    float v = src[o*256 + t];
    __nv_bfloat16 h = __float2bfloat16(v);
    g_Wh[r*256 + t] = h;
    g_Wl[r*256 + t] = __float2bfloat16(v - __bfloat162float(h));
    if (t == 0) g_bs[r] = bsrc[o];
}

// xt: x[b][c][p] -> split bf16 [b][p][c]. grid (512,8,8), block 256.
__global__ __launch_bounds__(256) void xt_kernel(const float* __restrict__ x)
{
    __shared__ float tl[32][33];
    const int b = blockIdx.z, c0 = blockIdx.y*32, p0 = blockIdx.x*32;
    const int tx = threadIdx.x & 31, ty = threadIdx.x >> 5;
    #pragma unroll
    for (int i = 0; i < 4; i++) {
        int c = ty + i*8;
        tl[c][tx] = x[((size_t)(b*Cc + c0 + c))*HWn + p0 + tx];
    }
    __syncthreads();
    #pragma unroll
    for (int i = 0; i < 4; i++) {
        int p = ty + i*8;
        float v = tl[tx][p];
        __nv_bfloat16 h = __float2bfloat16(v);
        size_t idx = ((size_t)b*HWn + p0 + p)*Cc + c0 + tx;
        g_xh[idx] = h;
        g_xl[idx] = __float2bfloat16(v - __bfloat162float(h));
    }
}

// proj: per (mt,h,b): D[128 px x 64 oc]. mt==0 (q,k): 3-pass. mt>=1 (v): 1-pass.
// grid (5, 128, 8).
__global__ __launch_bounds__(256) void proj_mma()
{
    __shared__ __align__(16) uint32_t pool[8448];
    __shared__ float s_bias[64];
    const int t = threadIdx.x, wid = t >> 5, lane = t & 31;
    const int g8 = lane >> 2, tig = lane & 3;
    const int warp_m = wid & 3, warp_n = wid >> 2;
    const int mt = blockIdx.x, h = blockIdx.y, b = blockIdx.z;
    const int px0 = h * 128;
    const bool hiPrec = (mt == 0);
    if (t < 64) s_bias[t] = g_bs[mt*64 + t];

    const __nv_bfloat16* Xh = g_xh + ((size_t)b*HWn + px0)*Cc;
    const __nv_bfloat16* Xl = g_xl + ((size_t)b*HWn + px0)*Cc;
    const __nv_bfloat16* Wh = g_Wh + (size_t)mt*64*Cc;
    const __nv_bfloat16* Wl = g_Wl + (size_t)mt*64*Cc;

    float acc[2][4][4] = {};
    const int ar = t >> 1, aw = (t & 1)*8;
    const int br = t >> 2, bw = (t & 3)*4;

    for (int kc = 0; kc < 8; kc++) {
        const size_t ae = (size_t)ar*Cc + kc*32 + aw*2;
        const size_t be = (size_t)br*Cc + kc*32 + bw*2;
        uint4 ah0 = *(const uint4*)(Xh + ae), ah1 = *(const uint4*)(Xh + ae + 8);
        uint4 bh  = *(const uint4*)(Wh + be);
        uint4 al0, al1, bl;
        if (hiPrec) {
            al0 = *(const uint4*)(Xl + ae); al1 = *(const uint4*)(Xl + ae + 8);
            bl  = *(const uint4*)(Wl + be);
        }
        __syncthreads();
        *(uint4*)&pool[ar*20 + aw]        = ah0;
        *(uint4*)&pool[ar*20 + aw + 4]    = ah1;
        *(uint4*)&pool[5120 + br*20 + bw] = bh;
        if (hiPrec) {
            *(uint4*)&pool[2560 + ar*20 + aw]   = al0;
            *(uint4*)&pool[2560 + ar*20 + aw+4] = al1;
            *(uint4*)&pool[6400 + br*20 + bw]   = bl;
        }
        __syncthreads();
        #pragma unroll
        for (int ks = 0; ks < 2; ks++) {
            const int kw = ks*8;
            uint32_t ahf[2][4], alf[2][4];
            #pragma unroll
            for (int mi = 0; mi < 2; mi++) {
                const int m0 = warp_m*32 + mi*16;
                ahf[mi][0] = pool[(m0+g8  )*20 + kw + tig];
                ahf[mi][1] = pool[(m0+g8+8)*20 + kw + tig];
                ahf[mi][2] = pool[(m0+g8  )*20 + kw + tig + 4];
                ahf[mi][3] = pool[(m0+g8+8)*20 + kw + tig + 4];
                if (hiPrec) {
                    alf[mi][0] = pool[2560 + (m0+g8  )*20 + kw + tig];
                    alf[mi][1] = pool[2560 + (m0+g8+8)*20 + kw + tig];
                    alf[mi][2] = pool[2560 + (m0+g8  )*20 + kw + tig + 4];
                    alf[mi][3] = pool[2560 + (m0+g8+8)*20 + kw + tig + 4];
                }
            }
            #pragma unroll
            for (int ni = 0; ni < 4; ni++) {
                const int n = warp_n*32 + ni*8 + g8;
                uint32_t bh0 = pool[5120 + n*20 + kw + tig];
                uint32_t bh1 = pool[5120 + n*20 + kw + tig + 4];
                if (hiPrec) {
                    uint32_t bl0 = pool[6400 + n*20 + kw + tig];
                    uint32_t bl1 = pool[6400 + n*20 + kw + tig + 4];
                    #pragma unroll
                    for (int mi = 0; mi < 2; mi++)
                        MMA3(acc[mi][ni], ahf[mi], alf[mi], bh, bl);
                } else {
                    #pragma unroll
                    for (int mi = 0; mi < 2; mi++)
                        mma16(acc[mi][ni], ahf[mi][0], ahf[mi][1], ahf[mi][2], ahf[mi][3], bh0, bh1);
                }
            }
        }
    }

    if (mt == 0) {
        #pragma unroll
        for (int mi = 0; mi < 2; mi++)
            #pragma unroll
            for (int ni = 0; ni < 4; ni++) {
                const int n = warp_n*32 + ni*8 + tig*2;
                const float b0 = s_bias[n], b1 = s_bias[n+1];
                float* hwp = (n < 32 ? g_q_hw : g_k_hw);
                float* whp = (n < 32 ? g_q_wh : g_k_wh);
                const int o = n & 31;
                #pragma unroll
                for (int hf = 0; hf < 2; hf++) {
                    const int w = warp_m*32 + mi*16 + g8 + hf*8;
                    float2 v = {acc[mi][ni][hf*2] + b0, acc[mi][ni][hf*2+1] + b1};
                    *(float2*)(hwp + ((size_t)(b*Hh + h)*Wn + w)*CQn + o) = v;
                    *(float2*)(whp + ((size_t)(b*Wn + w)*Hh + h)*CQn + o) = v;
                }
            }
    } else {
        float* tb = (float*)pool;   // [64 c][132 px]
        __syncthreads();
        #pragma unroll
        for (int mi = 0; mi < 2; mi++)
            #pragma unroll
            for (int ni = 0; ni < 4; ni++) {
                const int n = warp_n*32 + ni*8 + tig*2;
                const float b0 = s_bias[n], b1 = s_bias[n+1];
                #pragma unroll
                for (int hf = 0; hf < 2; hf++) {
                    const int w = warp_m*32 + mi*16 + g8 + hf*8;
                    tb[n*132 + w]     = acc[mi][ni][hf*2]   + b0;
                    tb[(n+1)*132 + w] = acc[mi][ni][hf*2+1] + b1;
                }
            }
        __syncthreads();
        const int c = t >> 2, p4 = (t & 3)*32;
        uint32_t* dst = (uint32_t*)(g_va + ((size_t)(b*Cc + (mt-1)*64 + c))*HWn + px0 + p4);
        #pragma unroll
        for (int i = 0; i < 32; i += 8) {
            uint4 u;
            u.x = pack2(tb[c*132+p4+i  ], tb[c*132+p4+i+1]);
            u.y = pack2(tb[c*132+p4+i+2], tb[c*132+p4+i+3]);
            u.z = pack2(tb[c*132+p4+i+4], tb[c*132+p4+i+5]);
            u.w = pack2(tb[c*132+p4+i+6], tb[c*132+p4+i+7]);
            *(uint4*)(dst + i/2) = u;
        }
    }
}

// vb: bf16 transpose g_va[c][h][w] -> g_vb[c][w][h]. grid (2,2,Bn*Cc), block 256.
__global__ __launch_bounds__(256) void vb_kernel()
{
    __shared__ uint32_t sm[64][33];
    const int bc = blockIdx.z, w0 = blockIdx.x*64, h0 = blockIdx.y*64;
    const int t = threadIdx.x;
    const uint32_t* src = (const uint32_t*)g_va + (size_t)bc*(HWn/2);
    uint32_t* dst = (uint32_t*)g_vb + (size_t)bc*(HWn/2);
    #pragma unroll
    for (int i = 0; i < 8; i++) {
        const int idx = i*256 + t, r = idx >> 5, wd = idx & 31;
        sm[r][wd] = src[(size_t)(h0 + r)*64 + w0/2 + wd];
    }
    __syncthreads();
    #pragma unroll
    for (int i = 0; i < 4; i++) {
        const int idx = i*256 + t, wp = idx >> 5, hp = idx & 31;
        uint32_t u1 = sm[2*hp][wp], u2 = sm[2*hp+1][wp];
        uint32_t lo, hi;
        asm("prmt.b32 %0, %1, %2, 0x5410;" : "=r"(lo) : "r"(u1), "r"(u2));
        asm("prmt.b32 %0, %1, %2, 0x7632;" : "=r"(hi) : "r"(u1), "r"(u2));
        dst[(size_t)(w0 + 2*wp  )*64 + h0/2 + hp] = lo;
        dst[(size_t)(w0 + 2*wp+1)*64 + h0/2 + hp] = hi;
    }
}

// score<ISH>: logits = Q@K^T (K=32), bf16 3-pass; writes bf16 logits into
// g_aH/g_aW (softmax later overwrites in place). grid 1024, block 256.
template <bool ISH>
__global__ __launch_bounds__(256) void score_mma()
{
    __shared__ __align__(16) uint32_t Qs[128][36], Ks[128][36];
    const int bs = blockIdx.x, t = threadIdx.x;
    const int wid = t >> 5, lane = t & 31, g8 = lane >> 2, tig = lane & 3;
    const int warp_m = wid & 3, warp_n = wid >> 2;
    const float* Q = (ISH ? g_q_wh : g_q_hw) + (size_t)bs*128*CQn;
    const float* K = (ISH ? g_k_wh : g_k_hw) + (size_t)bs*128*CQn;
    uint32_t* O = (uint32_t*)(ISH ? g_aH : g_aW) + (size_t)bs*128*64;

    #pragma unroll
    for (int i = 0; i < 4; i++) {
        const int idx = i*256 + t, r = idx >> 3, kq = (idx & 7)*4;
        float4 qv = *(const float4*)(Q + (size_t)r*CQn + kq);
        float4 kv = *(const float4*)(K + (size_t)r*CQn + kq);
        uint4 qp = {splitf(qv.x), splitf(qv.y), splitf(qv.z), splitf(qv.w)};
        uint4 kp = {splitf(kv.x), splitf(kv.y), splitf(kv.z), splitf(kv.w)};
        *(uint4*)&Qs[r][kq] = qp;
        *(uint4*)&Ks[r][kq] = kp;
    }
    __syncthreads();

    float acc[2][8][4] = {};
    #pragma unroll
    for (int ks = 0; ks < 2; ks++) {
        const int k0 = ks*16;
        uint32_t ah[2][4], al[2][4];
        #pragma unroll
        for (int mi = 0; mi < 2; mi++) {
            const int m = warp_m*32 + mi*16;
            unzip(*(uint2*)&Qs[m+g8  ][k0 + 2*tig],     ah[mi][0], al[mi][0]);
            unzip(*(uint2*)&Qs[m+g8+8][k0 + 2*tig],     ah[mi][1], al[mi][1]);
            unzip(*(uint2*)&Qs[m+g8  ][k0 + 8 + 2*tig], ah[mi][2], al[mi][2]);
            unzip(*(uint2*)&Qs[m+g8+8][k0 + 8 + 2*tig], ah[mi][3], al[mi][3]);
        }
        #pragma unroll
        for (int ni = 0; ni < 8; ni++) {
            const int n = warp_n*64 + ni*8 + g8;
            uint32_t bh0, bl0, bh1, bl1;
            unzip(*(uint2*)&Ks[n][k0 + 2*tig],     bh0, bl0);
            unzip(*(uint2*)&Ks[n][k0 + 8 + 2*tig], bh1, bl1);
            #pragma unroll
            for (int mi = 0; mi < 2; mi++) MMA3(acc[mi][ni], ah[mi], al[mi], bh, bl);
        }
    }
    #pragma unroll
    for (int mi = 0; mi < 2; mi++)
        #pragma unroll
        for (int ni = 0; ni < 8; ni++) {
            const int n = warp_n*64 + ni*8 + tig*2;
            #pragma unroll
            for (int hf = 0; hf < 2; hf++) {
                const int m = warp_m*32 + mi*16 + g8 + hf*8;
                float d0 = acc[mi][ni][hf*2], d1 = acc[mi][ni][hf*2+1];
                if (ISH) { if (n == m) d0 = neg_inf_f(); if (n+1 == m) d1 = neg_inf_f(); }
                O[(size_t)m*64 + n/2] = pack2(d0, d1);
            }
        }
}

// softmax: reads bf16 logits from g_aH/g_aW, writes bf16 att in place.
// grid 16384, block 256.
__global__ __launch_bounds__(256) void softmax_kernel()
{
    const int wid = blockIdx.x*8 + (threadIdx.x >> 5), lane = threadIdx.x & 31;
    const int b = wid >> 14, hw = wid & 16383, h = hw >> 7, w = hw & 127;
    const size_t rH = (size_t)(b*Wn + w)*Hh + h;
    const size_t rW = (size_t)(b*Hh + h)*Wn + w;
    uint32_t* aH = (uint32_t*)g_aH + rH*64;
    uint32_t* aW = (uint32_t*)g_aW + rW*64;
    uint2 uh = *(uint2*)(aH + lane*2);
    uint2 uw = *(uint2*)(aW + lane*2);
    float2 h01 = unpack2f(uh.x), h23 = unpack2f(uh.y);
    float2 w01 = unpack2f(uw.x), w23 = unpack2f(uw.y);
    float m = fmaxf(fmaxf(fmaxf(h01.x,h01.y),fmaxf(h23.x,h23.y)),
                    fmaxf(fmaxf(w01.x,w01.y),fmaxf(w23.x,w23.y)));
    #pragma unroll
    for (int off = 16; off; off >>= 1) m = fmaxf(m, __shfl_xor_sync(~0u, m, off));
    h01.x=__expf(h01.x-m); h01.y=__expf(h01.y-m); h23.x=__expf(h23.x-m); h23.y=__expf(h23.y-m);
    w01.x=__expf(w01.x-m); w01.y=__expf(w01.y-m); w23.x=__expf(w23.x-m); w23.y=__expf(w23.y-m);
    float s = h01.x+h01.y+h23.x+h23.y+w01.x+w01.y+w23.x+w23.y;
    #pragma unroll
    for (int off = 16; off; off >>= 1) s += __shfl_xor_sync(~0u, s, off);
    const float inv = 1.f/s;
    *(uint2*)(aH + lane*2) = make_uint2(pack2(h01.x*inv, h01.y*inv), pack2(h23.x*inv, h23.y*inv));
    *(uint2*)(aW + lane*2) = make_uint2(pack2(w01.x*inv, w01.y*inv), pack2(w23.x*inv, w23.y*inv));
}

// out<ISH>: D[128 spatial x 128 c] = att(bf16) @ v^T(bf16), 1-pass k16.
// ISH: writes g_oH[b][h][w][c] (bf16). !ISH: adds oH (coalesced bf16 reads) and
// emits gamma*(D+oH)+x -> out via 32-channel smem transposes. grid (2,1024).
template <bool ISH>
__global__ __launch_bounds__(256) void out_mma(const float* __restrict__ x,
                                               const float* __restrict__ gamma,
                                               float* __restrict__ out)
{
    __shared__ __align__(16) uint32_t sm[5120];   // As[128][20]@0, Bs@2560; tb[32][132] reuse
    const int t = threadIdx.x, wid = t >> 5, lane = t & 31;
    const int g8 = lane >> 2, tig = lane & 3;
    const int warp_m = wid & 3, warp_n = wid >> 2;
    const int bs = blockIdx.y, b = bs >> 7, s = bs & 127;
    const int c0 = blockIdx.x * 128;
    const uint32_t* A = (const uint32_t*)(ISH ? g_aH : g_aW) + (size_t)bs*128*64;
    const uint32_t* V = (const uint32_t*)(ISH ? g_vb : g_va) + (size_t)b*Cc*(HWn/2) + s*64;

    float acc[2][8][4] = {};
    const int r2 = t >> 1, wq = (t & 1)*8;
    for (int kc = 0; kc < 4; kc++) {
        uint4 a0 = *(const uint4*)(A + (size_t)r2*64 + kc*16 + wq);
        uint4 a1 = *(const uint4*)(A + (size_t)r2*64 + kc*16 + wq + 4);
        uint4 b0 = *(const uint4*)(V + (size_t)(c0 + r2)*(HWn/2) + kc*16 + wq);
        uint4 b1 = *(const uint4*)(V + (size_t)(c0 + r2)*(HWn/2) + kc*16 + wq + 4);
        __syncthreads();
        *(uint4*)&sm[r2*20 + wq]          = a0;
        *(uint4*)&sm[r2*20 + wq + 4]      = a1;
        *(uint4*)&sm[2560 + r2*20 + wq]   = b0;
        *(uint4*)&sm[2560 + r2*20 + wq+4] = b1;
        __syncthreads();
        #pragma unroll
        for (int ks = 0; ks < 2; ks++) {
            const int kw = ks*8;
            uint32_t af[2][4];
            #pragma unroll
            for (int mi = 0; mi < 2; mi++) {
                const int m0 = warp_m*32 + mi*16;
                af[mi][0] = sm[(m0+g8  )*20 + kw + tig];
                af[mi][1] = sm[(m0+g8+8)*20 + kw + tig];
                af[mi][2] = sm[(m0+g8  )*20 + kw + tig + 4];
                af[mi][3] = sm[(m0+g8+8)*20 + kw + tig + 4];
            }
            #pragma unroll
            for (int ni = 0; ni < 8; ni++) {
                const int n = warp_n*64 + ni*8 + g8;
                uint32_t bf0 = sm[2560 + n*20 + kw + tig];
                uint32_t bf1 = sm[2560 + n*20 + kw + tig + 4];
                #pragma unroll
                for (int mi = 0; mi < 2; mi++)
                    mma16(acc[mi][ni], af[mi][0], af[mi][1], af[mi][2], af[mi][3], bf0, bf1);
            }
        }
    }

    if (ISH) {
        // oH[b][h=m][w=s][c], bf16 packed pairs.
        uint32_t* Ob = (uint32_t*)g_oH;
        #pragma unroll
        for (int mi = 0; mi < 2; mi++)
            #pragma unroll
            for (int ni = 0; ni < 8; ni++) {
                const int m = warp_m*32 + mi*16 + g8;
                const int n = c0 + warp_n*64 + ni*8 + tig*2;
                Ob[((size_t)(b*Hh + m)*Wn + s)*128 + n/2]   = pack2(acc[mi][ni][0], acc[mi][ni][1]);
                Ob[((size_t)(b*Hh + m+8)*Wn + s)*128 + n/2] = pack2(acc[mi][ni][2], acc[mi][ni][3]);
            }
    } else {
        // Add oH slice [w][c] (contiguous bf16) in-register.
        const float gm = gamma[0];
        const uint32_t* o1 = (const uint32_t*)g_oH + (size_t)(b*Hh + s)*Wn*128;
        #pragma unroll
        for (int mi = 0; mi < 2; mi++)
            #pragma unroll
            for (int ni = 0; ni < 8; ni++) {
                const int m = warp_m*32 + mi*16 + g8;
                const int n = c0 + warp_n*64 + ni*8 + tig*2;
                float2 p0 = unpack2f(o1[(size_t)m*128 + n/2]);
                float2 p1 = unpack2f(o1[(size_t)(m+8)*128 + n/2]);
                acc[mi][ni][0] += p0.x; acc[mi][ni][1] += p0.y;
                acc[mi][ni][2] += p1.x; acc[mi][ni][3] += p1.y;
            }
        // Emit out[b][c][h=s][w] = gm*sum + x, 4 chunks of 32 channels.
        float* tb = (float*)sm;     // [32][132] floats
        #pragma unroll
        for (int cc = 0; cc < 4; cc++) {
            __syncthreads();
            if (warp_n == (cc >> 1)) {
                const int nib = (cc & 1)*4;
                #pragma unroll
                for (int mi = 0; mi < 2; mi++)
                    #pragma unroll
                    for (int nj = 0; nj < 4; nj++) {
                        const int ni = nib + nj;
                        const int nl = nj*8 + tig*2;
                        const int m = warp_m*32 + mi*16 + g8;
                        tb[nl*132 + m]       = acc[mi][ni][0];
                        tb[(nl+1)*132 + m]   = acc[mi][ni][1];
                        tb[nl*132 + m+8]     = acc[mi][ni][2];
                        tb[(nl+1)*132 + m+8] = acc[mi][ni][3];
                    }
            }
            __syncthreads();
            #pragma unroll
            for (int p = 0; p < 4; p++) {
                const int ci = (t >> 5) + p*8;
                const int w4 = (t & 31)*4;
                const size_t oidx = ((size_t)(b*Cc + c0 + cc*32 + ci)*Hh + s)*Wn + w4;
                float4 xr = *(const float4*)(x + oidx);
                float4 r;
                r.x = gm*tb[ci*132 + w4  ] + xr.x;
                r.y = gm*tb[ci*132 + w4+1] + xr.y;
                r.z = gm*tb[ci*132 + w4+2] + xr.z;
                r.w = gm*tb[ci*132 + w4+3] + xr.w;
                *(float4*)(out + oidx) = r;
            }
        }
    }
}

extern "C" void kernel_launch(void* const* d_in, const int* in_sizes, int n_in,
                              void* d_out, int out_size)
{
    const float* x     = (const float*)d_in[0];
    const float* Wq    = (const float*)d_in[1];
    const float* bq    = (const float*)d_in[2];
    const float* Wk    = (const float*)d_in[3];
    const float* bk    = (const float*)d_in[4];
    const float* Wv    = (const float*)d_in[5];
    const float* bv    = (const float*)d_in[6];
    const float* gamma = (const float*)d_in[7];
    float* out = (float*)d_out;

    prep_kernel<<<320, 256>>>(Wq, bq, Wk, bk, Wv, bv);
    xt_kernel<<<dim3(512, 8, 8), 256>>>(x);
    proj_mma<<<dim3(5, 128, 8), 256>>>();
    vb_kernel<<<dim3(2, 2, Bn*Cc), 256>>>();
    score_mma<true ><<<1024, 256>>>();
    score_mma<false><<<1024, 256>>>();
    softmax_kernel<<<16384, 256>>>();
    out_mma<true ><<<dim3(2, 1024), 256>>>(x, gamma, out);
    out_mma<false><<<dim3(2, 1024), 256>>>(x, gamma, out);
}

// round 13
// speedup vs baseline: 1.9312x; 1.0854x over previous
#include <cuda_runtime.h>
#include <cuda_bf16.h>
#include <cstdint>

#define Bn 8
#define Cc 256
#define CQn 32
#define Hh 128
#define Wn 128
#define HWn (Hh*Wn)

__device__ __nv_bfloat16 g_Wh[320*256], g_Wl[320*256];
__device__ float g_bs[320];
__device__ __nv_bfloat16 g_xh[(size_t)Bn*HWn*Cc], g_xl[(size_t)Bn*HWn*Cc]; // [b][p][c]
__device__ float g_q_hw[(size_t)Bn*HWn*CQn];        // [b][h][w][o]
__device__ float g_k_hw[(size_t)Bn*HWn*CQn];
__device__ __nv_bfloat16 g_va[(size_t)Bn*Cc*HWn];   // [b][c][h][w] bf16
__device__ __nv_bfloat16 g_vb[(size_t)Bn*Cc*HWn];   // [b][c][w][h] bf16
__device__ __nv_bfloat16 g_aH[(size_t)Bn*Wn*Hh*Hh]; // logits -> att (in place, bf16)
__device__ __nv_bfloat16 g_aW[(size_t)Bn*Hh*Wn*Wn];
__device__ __nv_bfloat16 g_oH[(size_t)Bn*HWn*Cc];   // [b][h][w][c] bf16

__device__ __forceinline__ float neg_inf_f() { return __int_as_float(0xff800000); }
__device__ __forceinline__ uint32_t splitf(float f) {
    __nv_bfloat16 h = __float2bfloat16(f);
    __nv_bfloat16 l = __float2bfloat16(f - __bfloat162float(h));
    return (uint32_t)__bfloat16_as_ushort(h) | ((uint32_t)__bfloat16_as_ushort(l) << 16);
}
__device__ __forceinline__ uint32_t pack2(float a, float b) {
    __nv_bfloat162 v = __floats2bfloat162_rn(a, b);
    return *reinterpret_cast<uint32_t*>(&v);
}
__device__ __forceinline__ float2 unpack2f(uint32_t u) {
    __nv_bfloat162 v = *reinterpret_cast<__nv_bfloat162*>(&u);
    return __bfloat1622float2(v);
}
__device__ __forceinline__ void unzip(uint2 p, uint32_t& hi, uint32_t& lo) {
    asm("prmt.b32 %0, %1, %2, 0x5410;" : "=r"(hi) : "r"(p.x), "r"(p.y));
    asm("prmt.b32 %0, %1, %2, 0x7632;" : "=r"(lo) : "r"(p.x), "r"(p.y));
}
__device__ __forceinline__ void mma16(float* d, uint32_t a0, uint32_t a1, uint32_t a2,
                                      uint32_t a3, uint32_t b0, uint32_t b1) {
    asm volatile("mma.sync.aligned.m16n8k16.row.col.f32.bf16.bf16.f32 "
                 "{%0,%1,%2,%3},{%4,%5,%6,%7},{%8,%9},{%0,%1,%2,%3};"
                 : "+f"(d[0]), "+f"(d[1]), "+f"(d[2]), "+f"(d[3])
                 : "r"(a0), "r"(a1), "r"(a2), "r"(a3), "r"(b0), "r"(b1));
}

// prep: split W rows [Wq;Wk;Wv]. grid 320, block 256.
__global__ __launch_bounds__(256) void prep_kernel(
    const float* __restrict__ Wq, const float* __restrict__ bq,
    const float* __restrict__ Wk, const float* __restrict__ bk,
    const float* __restrict__ Wv, const float* __restrict__ bv)
{
    const int r = blockIdx.x, t = threadIdx.x;
    const float* src; const float* bsrc; int o;
    if (r < 32)      { src = Wq; bsrc = bq; o = r; }
    else if (r < 64) { src = Wk; bsrc = bk; o = r - 32; }
    else             { src = Wv; bsrc = bv; o = r - 64; }
    float v = src[o*256 + t];
    __nv_bfloat16 h = __float2bfloat16(v);
    g_Wh[r*256 + t] = h;
    g_Wl[r*256 + t] = __float2bfloat16(v - __bfloat162float(h));
    if (t == 0) g_bs[r] = bsrc[o];
}

// xt: x[b][c][p] -> split bf16 [b][p][c]. grid (512,8,8), block 256.
__global__ __launch_bounds__(256) void xt_kernel(const float* __restrict__ x)
{
    __shared__ float tl[32][33];
    const int b = blockIdx.z, c0 = blockIdx.y*32, p0 = blockIdx.x*32;
    const int tx = threadIdx.x & 31, ty = threadIdx.x >> 5;
    #pragma unroll
    for (int i = 0; i < 4; i++) {
        int c = ty + i*8;
        tl[c][tx] = x[((size_t)(b*Cc + c0 + c))*HWn + p0 + tx];
    }
    __syncthreads();
    #pragma unroll
    for (int i = 0; i < 4; i++) {
        int p = ty + i*8;
        float v = tl[tx][p];
        __nv_bfloat16 h = __float2bfloat16(v);
        size_t idx = ((size_t)b*HWn + p0 + p)*Cc + c0 + tx;
        g_xh[idx] = h;
        g_xl[idx] = __float2bfloat16(v - __bfloat162float(h));
    }
}

// proj: per (mt,h,b): D[128 px x 64 oc].
// mt==0 (q,k): 2-pass (xh*Wh + xl*Wh). mt>=1 (v): 1-pass (xh*Wh).
// grid (5, 128, 8), block 256.
__global__ __launch_bounds__(256) void proj_mma()
{
    __shared__ __align__(16) uint32_t pool[8448];  // AHI@0 ALO@2560 BHI@5120; tb reuse
    __shared__ float s_bias[64];
    const int t = threadIdx.x, wid = t >> 5, lane = t & 31;
    const int g8 = lane >> 2, tig = lane & 3;
    const int warp_m = wid & 3, warp_n = wid >> 2;
    const int mt = blockIdx.x, h = blockIdx.y, b = blockIdx.z;
    const int px0 = h * 128;
    const bool hiPrec = (mt == 0);
    if (t < 64) s_bias[t] = g_bs[mt*64 + t];

    const __nv_bfloat16* Xh = g_xh + ((size_t)b*HWn + px0)*Cc;
    const __nv_bfloat16* Xl = g_xl + ((size_t)b*HWn + px0)*Cc;
    const __nv_bfloat16* Wh = g_Wh + (size_t)mt*64*Cc;

    float acc[2][4][4] = {};
    const int ar = t >> 1, aw = (t & 1)*8;
    const int br = t >> 2, bw = (t & 3)*4;

    for (int kc = 0; kc < 8; kc++) {
        const size_t ae = (size_t)ar*Cc + kc*32 + aw*2;
        const size_t be = (size_t)br*Cc + kc*32 + bw*2;
        uint4 ah0 = *(const uint4*)(Xh + ae), ah1 = *(const uint4*)(Xh + ae + 8);
        uint4 bh  = *(const uint4*)(Wh + be);
        uint4 al0, al1;
        if (hiPrec) {
            al0 = *(const uint4*)(Xl + ae); al1 = *(const uint4*)(Xl + ae + 8);
        }
        __syncthreads();
        *(uint4*)&pool[ar*20 + aw]        = ah0;
        *(uint4*)&pool[ar*20 + aw + 4]    = ah1;
        *(uint4*)&pool[5120 + br*20 + bw] = bh;
        if (hiPrec) {
            *(uint4*)&pool[2560 + ar*20 + aw]   = al0;
            *(uint4*)&pool[2560 + ar*20 + aw+4] = al1;
        }
        __syncthreads();
        #pragma unroll
        for (int ks = 0; ks < 2; ks++) {
            const int kw = ks*8;
            uint32_t ahf[2][4], alf[2][4];
            #pragma unroll
            for (int mi = 0; mi < 2; mi++) {
                const int m0 = warp_m*32 + mi*16;
                ahf[mi][0] = pool[(m0+g8  )*20 + kw + tig];
                ahf[mi][1] = pool[(m0+g8+8)*20 + kw + tig];
                ahf[mi][2] = pool[(m0+g8  )*20 + kw + tig + 4];
                ahf[mi][3] = pool[(m0+g8+8)*20 + kw + tig + 4];
                if (hiPrec) {
                    alf[mi][0] = pool[2560 + (m0+g8  )*20 + kw + tig];
                    alf[mi][1] = pool[2560 + (m0+g8+8)*20 + kw + tig];
                    alf[mi][2] = pool[2560 + (m0+g8  )*20 + kw + tig + 4];
                    alf[mi][3] = pool[2560 + (m0+g8+8)*20 + kw + tig + 4];
                }
            }
            #pragma unroll
            for (int ni = 0; ni < 4; ni++) {
                const int n = warp_n*32 + ni*8 + g8;
                uint32_t bh0 = pool[5120 + n*20 + kw + tig];
                uint32_t bh1 = pool[5120 + n*20 + kw + tig + 4];
                #pragma unroll
                for (int mi = 0; mi < 2; mi++) {
                    mma16(acc[mi][ni], ahf[mi][0], ahf[mi][1], ahf[mi][2], ahf[mi][3], bh0, bh1);
                    if (hiPrec)
                        mma16(acc[mi][ni], alf[mi][0], alf[mi][1], alf[mi][2], alf[mi][3], bh0, bh1);
                }
            }
        }
    }

    if (mt == 0) {
        // q (oc 0-31) / k (oc 32-63): single hw-layout float2 stores.
        #pragma unroll
        for (int mi = 0; mi < 2; mi++)
            #pragma unroll
            for (int ni = 0; ni < 4; ni++) {
                const int n = warp_n*32 + ni*8 + tig*2;
                const float b0 = s_bias[n], b1 = s_bias[n+1];
                float* hwp = (n < 32 ? g_q_hw : g_k_hw);
                const int o = n & 31;
                #pragma unroll
                for (int hf = 0; hf < 2; hf++) {
                    const int w = warp_m*32 + mi*16 + g8 + hf*8;
                    float2 v = {acc[mi][ni][hf*2] + b0, acc[mi][ni][hf*2+1] + b1};
                    *(float2*)(hwp + ((size_t)(b*Hh + h)*Wn + w)*CQn + o) = v;
                }
            }
    } else {
        float* tb = (float*)pool;   // [64 c][132 px]
        __syncthreads();
        #pragma unroll
        for (int mi = 0; mi < 2; mi++)
            #pragma unroll
            for (int ni = 0; ni < 4; ni++) {
                const int n = warp_n*32 + ni*8 + tig*2;
                const float b0 = s_bias[n], b1 = s_bias[n+1];
                #pragma unroll
                for (int hf = 0; hf < 2; hf++) {
                    const int w = warp_m*32 + mi*16 + g8 + hf*8;
                    tb[n*132 + w]     = acc[mi][ni][hf*2]   + b0;
                    tb[(n+1)*132 + w] = acc[mi][ni][hf*2+1] + b1;
                }
            }
        __syncthreads();
        const int c = t >> 2, p4 = (t & 3)*32;
        uint32_t* dst = (uint32_t*)(g_va + ((size_t)(b*Cc + (mt-1)*64 + c))*HWn + px0 + p4);
        #pragma unroll
        for (int i = 0; i < 32; i += 8) {
            uint4 u;
            u.x = pack2(tb[c*132+p4+i  ], tb[c*132+p4+i+1]);
            u.y = pack2(tb[c*132+p4+i+2], tb[c*132+p4+i+3]);
            u.z = pack2(tb[c*132+p4+i+4], tb[c*132+p4+i+5]);
            u.w = pack2(tb[c*132+p4+i+6], tb[c*132+p4+i+7]);
            *(uint4*)(dst + i/2) = u;
        }
    }
}

// vb: bf16 transpose g_va[c][h][w] -> g_vb[c][w][h]. grid (2,2,Bn*Cc), block 256.
__global__ __launch_bounds__(256) void vb_kernel()
{
    __shared__ uint32_t sm[64][33];
    const int bc = blockIdx.z, w0 = blockIdx.x*64, h0 = blockIdx.y*64;
    const int t = threadIdx.x;
    const uint32_t* src = (const uint32_t*)g_va + (size_t)bc*(HWn/2);
    uint32_t* dst = (uint32_t*)g_vb + (size_t)bc*(HWn/2);
    #pragma unroll
    for (int i = 0; i < 8; i++) {
        const int idx = i*256 + t, r = idx >> 5, wd = idx & 31;
        sm[r][wd] = src[(size_t)(h0 + r)*64 + w0/2 + wd];
    }
    __syncthreads();
    #pragma unroll
    for (int i = 0; i < 4; i++) {
        const int idx = i*256 + t, wp = idx >> 5, hp = idx & 31;
        uint32_t u1 = sm[2*hp][wp], u2 = sm[2*hp+1][wp];
        uint32_t lo, hi;
        asm("prmt.b32 %0, %1, %2, 0x5410;" : "=r"(lo) : "r"(u1), "r"(u2));
        asm("prmt.b32 %0, %1, %2, 0x7632;" : "=r"(hi) : "r"(u1), "r"(u2));
        dst[(size_t)(w0 + 2*wp  )*64 + h0/2 + hp] = lo;
        dst[(size_t)(w0 + 2*wp+1)*64 + h0/2 + hp] = hi;
    }
}

// score<ISH>: logits = Q@K^T (K=32), bf16 2-pass; reads q_hw/k_hw only
// (ISH uses strided rows: each row is 128B contiguous). Writes bf16 logits.
// grid 1024, block 256.
template <bool ISH>
__global__ __launch_bounds__(256) void score_mma()
{
    __shared__ __align__(16) uint32_t Qs[128][36], Ks[128][36];
    const int bs = blockIdx.x, t = threadIdx.x;
    const int wid = t >> 5, lane = t & 31, g8 = lane >> 2, tig = lane & 3;
    const int warp_m = wid & 3, warp_n = wid >> 2;
    const int b = bs >> 7, sfix = bs & 127;
    const size_t base = (size_t)b*HWn*CQn +
        (ISH ? (size_t)sfix*CQn : (size_t)sfix*Wn*CQn);
    const size_t rstride = ISH ? (size_t)Wn*CQn : (size_t)CQn;
    const float* Q = g_q_hw + base;
    const float* K = g_k_hw + base;
    uint32_t* O = (uint32_t*)(ISH ? g_aH : g_aW) + (size_t)bs*128*64;

    #pragma unroll
    for (int i = 0; i < 4; i++) {
        const int idx = i*256 + t, r = idx >> 3, kq = (idx & 7)*4;
        float4 qv = *(const float4*)(Q + (size_t)r*rstride + kq);
        float4 kv = *(const float4*)(K + (size_t)r*rstride + kq);
        uint4 qp = {splitf(qv.x), splitf(qv.y), splitf(qv.z), splitf(qv.w)};
        uint4 kp = {splitf(kv.x), splitf(kv.y), splitf(kv.z), splitf(kv.w)};
        *(uint4*)&Qs[r][kq] = qp;
        *(uint4*)&Ks[r][kq] = kp;
    }
    __syncthreads();

    float acc[2][8][4] = {};
    #pragma unroll
    for (int ks = 0; ks < 2; ks++) {
        const int k0 = ks*16;
        uint32_t ah[2][4], al[2][4];
        #pragma unroll
        for (int mi = 0; mi < 2; mi++) {
            const int m = warp_m*32 + mi*16;
            unzip(*(uint2*)&Qs[m+g8  ][k0 + 2*tig],     ah[mi][0], al[mi][0]);
            unzip(*(uint2*)&Qs[m+g8+8][k0 + 2*tig],     ah[mi][1], al[mi][1]);
            unzip(*(uint2*)&Qs[m+g8  ][k0 + 8 + 2*tig], ah[mi][2], al[mi][2]);
            unzip(*(uint2*)&Qs[m+g8+8][k0 + 8 + 2*tig], ah[mi][3], al[mi][3]);
        }
        #pragma unroll
        for (int ni = 0; ni < 8; ni++) {
            const int n = warp_n*64 + ni*8 + g8;
            uint32_t bh0, bl0, bh1, bl1;
            unzip(*(uint2*)&Ks[n][k0 + 2*tig],     bh0, bl0);
            unzip(*(uint2*)&Ks[n][k0 + 8 + 2*tig], bh1, bl1);
            #pragma unroll
            for (int mi = 0; mi < 2; mi++) {
                mma16(acc[mi][ni], ah[mi][0], ah[mi][1], ah[mi][2], ah[mi][3], bh0, bh1);
                mma16(acc[mi][ni], al[mi][0], al[mi][1], al[mi][2], al[mi][3], bh0, bh1);
            }
        }
    }
    #pragma unroll
    for (int mi = 0; mi < 2; mi++)
        #pragma unroll
        for (int ni = 0; ni < 8; ni++) {
            const int n = warp_n*64 + ni*8 + tig*2;
            #pragma unroll
            for (int hf = 0; hf < 2; hf++) {
                const int m = warp_m*32 + mi*16 + g8 + hf*8;
                float d0 = acc[mi][ni][hf*2], d1 = acc[mi][ni][hf*2+1];
                if (ISH) { if (n == m) d0 = neg_inf_f(); if (n+1 == m) d1 = neg_inf_f(); }
                O[(size_t)m*64 + n/2] = pack2(d0, d1);
            }
        }
}

// softmax: reads bf16 logits, writes bf16 att in place. grid 16384, block 256.
__global__ __launch_bounds__(256) void softmax_kernel()
{
    const int wid = blockIdx.x*8 + (threadIdx.x >> 5), lane = threadIdx.x & 31;
    const int b = wid >> 14, hw = wid & 16383, h = hw >> 7, w = hw & 127;
    const size_t rH = (size_t)(b*Wn + w)*Hh + h;
    const size_t rW = (size_t)(b*Hh + h)*Wn + w;
    uint32_t* aH = (uint32_t*)g_aH + rH*64;
    uint32_t* aW = (uint32_t*)g_aW + rW*64;
    uint2 uh = *(uint2*)(aH + lane*2);
    uint2 uw = *(uint2*)(aW + lane*2);
    float2 h01 = unpack2f(uh.x), h23 = unpack2f(uh.y);
    float2 w01 = unpack2f(uw.x), w23 = unpack2f(uw.y);
    float m = fmaxf(fmaxf(fmaxf(h01.x,h01.y),fmaxf(h23.x,h23.y)),
                    fmaxf(fmaxf(w01.x,w01.y),fmaxf(w23.x,w23.y)));
    #pragma unroll
    for (int off = 16; off; off >>= 1) m = fmaxf(m, __shfl_xor_sync(~0u, m, off));
    h01.x=__expf(h01.x-m); h01.y=__expf(h01.y-m); h23.x=__expf(h23.x-m); h23.y=__expf(h23.y-m);
    w01.x=__expf(w01.x-m); w01.y=__expf(w01.y-m); w23.x=__expf(w23.x-m); w23.y=__expf(w23.y-m);
    float s = h01.x+h01.y+h23.x+h23.y+w01.x+w01.y+w23.x+w23.y;
    #pragma unroll
    for (int off = 16; off; off >>= 1) s += __shfl_xor_sync(~0u, s, off);
    const float inv = 1.f/s;
    *(uint2*)(aH + lane*2) = make_uint2(pack2(h01.x*inv, h01.y*inv), pack2(h23.x*inv, h23.y*inv));
    *(uint2*)(aW + lane*2) = make_uint2(pack2(w01.x*inv, w01.y*inv), pack2(w23.x*inv, w23.y*inv));
}

// out<ISH>: D[128 spatial x 128 c] = att(bf16) @ v^T(bf16), 1-pass k16.
// ISH: writes g_oH[b][h][w][c] (bf16). !ISH: adds oH and emits
// gamma*(D+oH)+x -> out via 32-channel smem transposes. grid (2,1024).
template <bool ISH>
__global__ __launch_bounds__(256) void out_mma(const float* __restrict__ x,
                                               const float* __restrict__ gamma,
                                               float* __restrict__ out)
{
    __shared__ __align__(16) uint32_t sm[5120];   // As[128][20]@0, Bs@2560; tb[32][132] reuse
    const int t = threadIdx.x, wid = t >> 5, lane = t & 31;
    const int g8 = lane >> 2, tig = lane & 3;
    const int warp_m = wid & 3, warp_n = wid >> 2;
    const int bs = blockIdx.y, b = bs >> 7, s = bs & 127;
    const int c0 = blockIdx.x * 128;
    const uint32_t* A = (const uint32_t*)(ISH ? g_aH : g_aW) + (size_t)bs*128*64;
    const uint32_t* V = (const uint32_t*)(ISH ? g_vb : g_va) + (size_t)b*Cc*(HWn/2) + s*64;

    float acc[2][8][4] = {};
    const int r2 = t >> 1, wq = (t & 1)*8;
    for (int kc = 0; kc < 4; kc++) {
        uint4 a0 = *(const uint4*)(A + (size_t)r2*64 + kc*16 + wq);
        uint4 a1 = *(const uint4*)(A + (size_t)r2*64 + kc*16 + wq + 4);
        uint4 b0 = *(const uint4*)(V + (size_t)(c0 + r2)*(HWn/2) + kc*16 + wq);
        uint4 b1 = *(const uint4*)(V + (size_t)(c0 + r2)*(HWn/2) + kc*16 + wq + 4);
        __syncthreads();
        *(uint4*)&sm[r2*20 + wq]          = a0;
        *(uint4*)&sm[r2*20 + wq + 4]      = a1;
        *(uint4*)&sm[2560 + r2*20 + wq]   = b0;
        *(uint4*)&sm[2560 + r2*20 + wq+4] = b1;
        __syncthreads();
        #pragma unroll
        for (int ks = 0; ks < 2; ks++) {
            const int kw = ks*8;
            uint32_t af[2][4];
            #pragma unroll
            for (int mi = 0; mi < 2; mi++) {
                const int m0 = warp_m*32 + mi*16;
                af[mi][0] = sm[(m0+g8  )*20 + kw + tig];
                af[mi][1] = sm[(m0+g8+8)*20 + kw + tig];
                af[mi][2] = sm[(m0+g8  )*20 + kw + tig + 4];
                af[mi][3] = sm[(m0+g8+8)*20 + kw + tig + 4];
            }
            #pragma unroll
            for (int ni = 0; ni < 8; ni++) {
                const int n = warp_n*64 + ni*8 + g8;
                uint32_t bf0 = sm[2560 + n*20 + kw + tig];
                uint32_t bf1 = sm[2560 + n*20 + kw + tig + 4];
                #pragma unroll
                for (int mi = 0; mi < 2; mi++)
                    mma16(acc[mi][ni], af[mi][0], af[mi][1], af[mi][2], af[mi][3], bf0, bf1);
            }
        }
    }

    if (ISH) {
        uint32_t* Ob = (uint32_t*)g_oH;
        #pragma unroll
        for (int mi = 0; mi < 2; mi++)
            #pragma unroll
            for (int ni = 0; ni < 8; ni++) {
                const int m = warp_m*32 + mi*16 + g8;
                const int n = c0 + warp_n*64 + ni*8 + tig*2;
                Ob[((size_t)(b*Hh + m)*Wn + s)*128 + n/2]   = pack2(acc[mi][ni][0], acc[mi][ni][1]);
                Ob[((size_t)(b*Hh + m+8)*Wn + s)*128 + n/2] = pack2(acc[mi][ni][2], acc[mi][ni][3]);
            }
    } else {
        const float gm = gamma[0];
        const uint32_t* o1 = (const uint32_t*)g_oH + (size_t)(b*Hh + s)*Wn*128;
        #pragma unroll
        for (int mi = 0; mi < 2; mi++)
            #pragma unroll
            for (int ni = 0; ni < 8; ni++) {
                const int m = warp_m*32 + mi*16 + g8;
                const int n = c0 + warp_n*64 + ni*8 + tig*2;
                float2 p0 = unpack2f(o1[(size_t)m*128 + n/2]);
                float2 p1 = unpack2f(o1[(size_t)(m+8)*128 + n/2]);
                acc[mi][ni][0] += p0.x; acc[mi][ni][1] += p0.y;
                acc[mi][ni][2] += p1.x; acc[mi][ni][3] += p1.y;
            }
        float* tb = (float*)sm;     // [32][132] floats
        #pragma unroll
        for (int cc = 0; cc < 4; cc++) {
            __syncthreads();
            if (warp_n == (cc >> 1)) {
                const int nib = (cc & 1)*4;
                #pragma unroll
                for (int mi = 0; mi < 2; mi++)
                    #pragma unroll
                    for (int nj = 0; nj < 4; nj++) {
                        const int ni = nib + nj;
                        const int nl = nj*8 + tig*2;
                        const int m = warp_m*32 + mi*16 + g8;
                        tb[nl*132 + m]       = acc[mi][ni][0];
                        tb[(nl+1)*132 + m]   = acc[mi][ni][1];
                        tb[nl*132 + m+8]     = acc[mi][ni][2];
                        tb[(nl+1)*132 + m+8] = acc[mi][ni][3];
                    }
            }
            __syncthreads();
            #pragma unroll
            for (int p = 0; p < 4; p++) {
                const int ci = (t >> 5) + p*8;
                const int w4 = (t & 31)*4;
                const size_t oidx = ((size_t)(b*Cc + c0 + cc*32 + ci)*Hh + s)*Wn + w4;
                float4 xr = *(const float4*)(x + oidx);
                float4 r;
                r.x = gm*tb[ci*132 + w4  ] + xr.x;
                r.y = gm*tb[ci*132 + w4+1] + xr.y;
                r.z = gm*tb[ci*132 + w4+2] + xr.z;
                r.w = gm*tb[ci*132 + w4+3] + xr.w;
                *(float4*)(out + oidx) = r;
            }
        }
    }
}

extern "C" void kernel_launch(void* const* d_in, const int* in_sizes, int n_in,
                              void* d_out, int out_size)
{
    const float* x     = (const float*)d_in[0];
    const float* Wq    = (const float*)d_in[1];
    const float* bq    = (const float*)d_in[2];
    const float* Wk    = (const float*)d_in[3];
    const float* bk    = (const float*)d_in[4];
    const float* Wv    = (const float*)d_in[5];
    const float* bv    = (const float*)d_in[6];
    const float* gamma = (const float*)d_in[7];
    float* out = (float*)d_out;

    prep_kernel<<<320, 256>>>(Wq, bq, Wk, bk, Wv, bv);
    xt_kernel<<<dim3(512, 8, 8), 256>>>(x);
    proj_mma<<<dim3(5, 128, 8), 256>>>();
    vb_kernel<<<dim3(2, 2, Bn*Cc), 256>>>();
    score_mma<true ><<<1024, 256>>>();
    score_mma<false><<<1024, 256>>>();
    softmax_kernel<<<16384, 256>>>();
    out_mma<true ><<<dim3(2, 1024), 256>>>(x, gamma, out);
    out_mma<false><<<dim3(2, 1024), 256>>>(x, gamma, out);
}

// round 14
// speedup vs baseline: 2.0474x; 1.0602x over previous
#include <cuda_runtime.h>
#include <cuda_bf16.h>
#include <cstdint>

#define Bn 8
#define Cc 256
#define CQn 32
#define Hh 128
#define Wn 128
#define HWn (Hh*Wn)

__device__ __nv_bfloat16 g_Wh[320*256], g_Wl[320*256];
__device__ float g_bs[320];
__device__ __nv_bfloat16 g_xh[(size_t)Bn*HWn*Cc], g_xl[(size_t)Bn*HWn*Cc]; // [b][p][c]
__device__ float g_q_hw[(size_t)Bn*HWn*CQn];        // [b][h][w][o]
__device__ float g_k_hw[(size_t)Bn*HWn*CQn];
__device__ __nv_bfloat16 g_va[(size_t)Bn*Cc*HWn];   // [b][c][h][w] bf16
__device__ __nv_bfloat16 g_vb[(size_t)Bn*Cc*HWn];   // [b][c][w][h] bf16
__device__ __nv_bfloat16 g_aH[(size_t)Bn*Wn*Hh*Hh]; // logits -> att (in place, bf16)
__device__ __nv_bfloat16 g_aW[(size_t)Bn*Hh*Wn*Wn];
__device__ __nv_bfloat16 g_oH[(size_t)Bn*HWn*Cc];   // [b][h][w][c] bf16

__device__ __forceinline__ float neg_inf_f() { return __int_as_float(0xff800000); }
__device__ __forceinline__ uint32_t splitf(float f) {
    __nv_bfloat16 h = __float2bfloat16(f);
    __nv_bfloat16 l = __float2bfloat16(f - __bfloat162float(h));
    return (uint32_t)__bfloat16_as_ushort(h) | ((uint32_t)__bfloat16_as_ushort(l) << 16);
}
__device__ __forceinline__ uint32_t pack2(float a, float b) {
    __nv_bfloat162 v = __floats2bfloat162_rn(a, b);
    return *reinterpret_cast<uint32_t*>(&v);
}
__device__ __forceinline__ float2 unpack2f(uint32_t u) {
    __nv_bfloat162 v = *reinterpret_cast<__nv_bfloat162*>(&u);
    return __bfloat1622float2(v);
}
__device__ __forceinline__ void unzip(uint2 p, uint32_t& hi, uint32_t& lo) {
    asm("prmt.b32 %0, %1, %2, 0x5410;" : "=r"(hi) : "r"(p.x), "r"(p.y));
    asm("prmt.b32 %0, %1, %2, 0x7632;" : "=r"(lo) : "r"(p.x), "r"(p.y));
}
__device__ __forceinline__ void mma16(float* d, uint32_t a0, uint32_t a1, uint32_t a2,
                                      uint32_t a3, uint32_t b0, uint32_t b1) {
    asm volatile("mma.sync.aligned.m16n8k16.row.col.f32.bf16.bf16.f32 "
                 "{%0,%1,%2,%3},{%4,%5,%6,%7},{%8,%9},{%0,%1,%2,%3};"
                 : "+f"(d[0]), "+f"(d[1]), "+f"(d[2]), "+f"(d[3])
                 : "r"(a0), "r"(a1), "r"(a2), "r"(a3), "r"(b0), "r"(b1));
}
__device__ __forceinline__ void ldm4(uint32_t* r, uint32_t addr) {
    asm volatile("ldmatrix.sync.aligned.m8n8.x4.shared.b16 {%0,%1,%2,%3}, [%4];"
                 : "=r"(r[0]), "=r"(r[1]), "=r"(r[2]), "=r"(r[3]) : "r"(addr));
}
__device__ __forceinline__ uint32_t s2u(const void* p) {
    return (uint32_t)__cvta_generic_to_shared(p);
}

// prep: split W rows [Wq;Wk;Wv]. grid 320, block 256.
__global__ __launch_bounds__(256) void prep_kernel(
    const float* __restrict__ Wq, const float* __restrict__ bq,
    const float* __restrict__ Wk, const float* __restrict__ bk,
    const float* __restrict__ Wv, const float* __restrict__ bv)
{
    const int r = blockIdx.x, t = threadIdx.x;
    const float* src; const float* bsrc; int o;
    if (r < 32)      { src = Wq; bsrc = bq; o = r; }
    else if (r < 64) { src = Wk; bsrc = bk; o = r - 32; }
    else             { src = Wv; bsrc = bv; o = r - 64; }
    float v = src[o*256 + t];
    __nv_bfloat16 h = __float2bfloat16(v);
    g_Wh[r*256 + t] = h;
    g_Wl[r*256 + t] = __float2bfloat16(v - __bfloat162float(h));
    if (t == 0) g_bs[r] = bsrc[o];
}

// xt: x[b][c][p] -> split bf16 [b][p][c]. grid (512,8,8), block 256.
__global__ __launch_bounds__(256) void xt_kernel(const float* __restrict__ x)
{
    __shared__ float tl[32][33];
    const int b = blockIdx.z, c0 = blockIdx.y*32, p0 = blockIdx.x*32;
    const int tx = threadIdx.x & 31, ty = threadIdx.x >> 5;
    #pragma unroll
    for (int i = 0; i < 4; i++) {
        int c = ty + i*8;
        tl[c][tx] = x[((size_t)(b*Cc + c0 + c))*HWn + p0 + tx];
    }
    __syncthreads();
    #pragma unroll
    for (int i = 0; i < 4; i++) {
        int p = ty + i*8;
        float v = tl[tx][p];
        __nv_bfloat16 h = __float2bfloat16(v);
        size_t idx = ((size_t)b*HWn + p0 + p)*Cc + c0 + tx;
        g_xh[idx] = h;
        g_xl[idx] = __float2bfloat16(v - __bfloat162float(h));
    }
}

// proj: per (mt,h,b): D[128 px x 64 oc].
// mt==0 (q,k): 2-pass (xh*Wh + xl*Wh). mt>=1 (v): 1-pass.
// Fragment feeding via ldmatrix.x4. grid (5, 128, 8), block 256.
__global__ __launch_bounds__(256) void proj_mma()
{
    __shared__ __align__(16) uint32_t pool[8448];  // AHI@0 ALO@2560 BHI@5120 (stride 20w); tb reuse
    __shared__ float s_bias[64];
    const int t = threadIdx.x, wid = t >> 5, lane = t & 31;
    const int g8 = lane >> 2, tig = lane & 3;
    const int warp_m = wid & 3, warp_n = wid >> 2;
    const int mt = blockIdx.x, h = blockIdx.y, b = blockIdx.z;
    const int px0 = h * 128;
    const bool hiPrec = (mt == 0);
    if (t < 64) s_bias[t] = g_bs[mt*64 + t];

    const __nv_bfloat16* Xh = g_xh + ((size_t)b*HWn + px0)*Cc;
    const __nv_bfloat16* Xl = g_xl + ((size_t)b*HWn + px0)*Cc;
    const __nv_bfloat16* Wh = g_Wh + (size_t)mt*64*Cc;

    // ldmatrix per-lane address components (row stride 80 B).
    const uint32_t pbase = s2u(pool);
    const uint32_t aRow = (uint32_t)(lane & 15);          // + m0
    const uint32_t aCol = (uint32_t)((lane >> 4) * 16);   // byte
    const uint32_t bRow = (uint32_t)((lane & 7) + ((lane >> 4) << 3));
    const uint32_t bCol = (uint32_t)(((lane >> 3) & 1) * 16);

    float acc[2][4][4] = {};
    const int ar = t >> 1, aw = (t & 1)*8;
    const int br = t >> 2, bw = (t & 3)*4;

    for (int kc = 0; kc < 8; kc++) {
        const size_t ae = (size_t)ar*Cc + kc*32 + aw*2;
        const size_t be = (size_t)br*Cc + kc*32 + bw*2;
        uint4 ah0 = *(const uint4*)(Xh + ae), ah1 = *(const uint4*)(Xh + ae + 8);
        uint4 bh  = *(const uint4*)(Wh + be);
        uint4 al0, al1;
        if (hiPrec) {
            al0 = *(const uint4*)(Xl + ae); al1 = *(const uint4*)(Xl + ae + 8);
        }
        __syncthreads();
        *(uint4*)&pool[ar*20 + aw]        = ah0;
        *(uint4*)&pool[ar*20 + aw + 4]    = ah1;
        *(uint4*)&pool[5120 + br*20 + bw] = bh;
        if (hiPrec) {
            *(uint4*)&pool[2560 + ar*20 + aw]   = al0;
            *(uint4*)&pool[2560 + ar*20 + aw+4] = al1;
        }
        __syncthreads();
        #pragma unroll
        for (int ks = 0; ks < 2; ks++) {
            const uint32_t ksb = ks*32;
            uint32_t ahf[2][4], alf[2][4], bf[2][4];
            #pragma unroll
            for (int mi = 0; mi < 2; mi++) {
                const uint32_t rowm = (warp_m*32 + mi*16 + aRow)*80 + ksb + aCol;
                ldm4(ahf[mi], pbase + rowm);
                if (hiPrec) ldm4(alf[mi], pbase + 10240 + rowm);
            }
            #pragma unroll
            for (int pi = 0; pi < 2; pi++) {
                const uint32_t rown = (warp_n*32 + pi*16 + bRow)*80 + ksb + bCol;
                ldm4(bf[pi], pbase + 20480 + rown);
            }
            #pragma unroll
            for (int pi = 0; pi < 2; pi++)
                #pragma unroll
                for (int half = 0; half < 2; half++) {
                    const int ni = pi*2 + half;
                    const uint32_t b0 = bf[pi][half*2], b1 = bf[pi][half*2 + 1];
                    #pragma unroll
                    for (int mi = 0; mi < 2; mi++) {
                        mma16(acc[mi][ni], ahf[mi][0], ahf[mi][1], ahf[mi][2], ahf[mi][3], b0, b1);
                        if (hiPrec)
                            mma16(acc[mi][ni], alf[mi][0], alf[mi][1], alf[mi][2], alf[mi][3], b0, b1);
                    }
                }
        }
    }

    if (mt == 0) {
        #pragma unroll
        for (int mi = 0; mi < 2; mi++)
            #pragma unroll
            for (int ni = 0; ni < 4; ni++) {
                const int n = warp_n*32 + ni*8 + tig*2;
                const float b0 = s_bias[n], b1 = s_bias[n+1];
                float* hwp = (n < 32 ? g_q_hw : g_k_hw);
                const int o = n & 31;
                #pragma unroll
                for (int hf = 0; hf < 2; hf++) {
                    const int w = warp_m*32 + mi*16 + g8 + hf*8;
                    float2 v = {acc[mi][ni][hf*2] + b0, acc[mi][ni][hf*2+1] + b1};
                    *(float2*)(hwp + ((size_t)(b*Hh + h)*Wn + w)*CQn + o) = v;
                }
            }
    } else {
        float* tb = (float*)pool;   // [64 c][132 px]
        __syncthreads();
        #pragma unroll
        for (int mi = 0; mi < 2; mi++)
            #pragma unroll
            for (int ni = 0; ni < 4; ni++) {
                const int n = warp_n*32 + ni*8 + tig*2;
                const float b0 = s_bias[n], b1 = s_bias[n+1];
                #pragma unroll
                for (int hf = 0; hf < 2; hf++) {
                    const int w = warp_m*32 + mi*16 + g8 + hf*8;
                    tb[n*132 + w]     = acc[mi][ni][hf*2]   + b0;
                    tb[(n+1)*132 + w] = acc[mi][ni][hf*2+1] + b1;
                }
            }
        __syncthreads();
        const int c = t >> 2, p4 = (t & 3)*32;
        uint32_t* dst = (uint32_t*)(g_va + ((size_t)(b*Cc + (mt-1)*64 + c))*HWn + px0 + p4);
        #pragma unroll
        for (int i = 0; i < 32; i += 8) {
            uint4 u;
            u.x = pack2(tb[c*132+p4+i  ], tb[c*132+p4+i+1]);
            u.y = pack2(tb[c*132+p4+i+2], tb[c*132+p4+i+3]);
            u.z = pack2(tb[c*132+p4+i+4], tb[c*132+p4+i+5]);
            u.w = pack2(tb[c*132+p4+i+6], tb[c*132+p4+i+7]);
            *(uint4*)(dst + i/2) = u;
        }
    }
}

// vb: bf16 transpose g_va[c][h][w] -> g_vb[c][w][h]. grid (2,2,Bn*Cc), block 256.
__global__ __launch_bounds__(256) void vb_kernel()
{
    __shared__ uint32_t sm[64][33];
    const int bc = blockIdx.z, w0 = blockIdx.x*64, h0 = blockIdx.y*64;
    const int t = threadIdx.x;
    const uint32_t* src = (const uint32_t*)g_va + (size_t)bc*(HWn/2);
    uint32_t* dst = (uint32_t*)g_vb + (size_t)bc*(HWn/2);
    #pragma unroll
    for (int i = 0; i < 8; i++) {
        const int idx = i*256 + t, r = idx >> 5, wd = idx & 31;
        sm[r][wd] = src[(size_t)(h0 + r)*64 + w0/2 + wd];
    }
    __syncthreads();
    #pragma unroll
    for (int i = 0; i < 4; i++) {
        const int idx = i*256 + t, wp = idx >> 5, hp = idx & 31;
        uint32_t u1 = sm[2*hp][wp], u2 = sm[2*hp+1][wp];
        uint32_t lo, hi;
        asm("prmt.b32 %0, %1, %2, 0x5410;" : "=r"(lo) : "r"(u1), "r"(u2));
        asm("prmt.b32 %0, %1, %2, 0x7632;" : "=r"(hi) : "r"(u1), "r"(u2));
        dst[(size_t)(w0 + 2*wp  )*64 + h0/2 + hp] = lo;
        dst[(size_t)(w0 + 2*wp+1)*64 + h0/2 + hp] = hi;
    }
}

// score<ISH>: logits = Q@K^T (K=32), bf16 2-pass; reads q_hw/k_hw only.
// Writes bf16 logits. grid 1024, block 256.
template <bool ISH>
__global__ __launch_bounds__(256) void score_mma()
{
    __shared__ __align__(16) uint32_t Qs[128][36], Ks[128][36];
    const int bs = blockIdx.x, t = threadIdx.x;
    const int wid = t >> 5, lane = t & 31, g8 = lane >> 2, tig = lane & 3;
    const int warp_m = wid & 3, warp_n = wid >> 2;
    const int b = bs >> 7, sfix = bs & 127;
    const size_t base = (size_t)b*HWn*CQn +
        (ISH ? (size_t)sfix*CQn : (size_t)sfix*Wn*CQn);
    const size_t rstride = ISH ? (size_t)Wn*CQn : (size_t)CQn;
    const float* Q = g_q_hw + base;
    const float* K = g_k_hw + base;
    uint32_t* O = (uint32_t*)(ISH ? g_aH : g_aW) + (size_t)bs*128*64;

    #pragma unroll
    for (int i = 0; i < 4; i++) {
        const int idx = i*256 + t, r = idx >> 3, kq = (idx & 7)*4;
        float4 qv = *(const float4*)(Q + (size_t)r*rstride + kq);
        float4 kv = *(const float4*)(K + (size_t)r*rstride + kq);
        uint4 qp = {splitf(qv.x), splitf(qv.y), splitf(qv.z), splitf(qv.w)};
        uint4 kp = {splitf(kv.x), splitf(kv.y), splitf(kv.z), splitf(kv.w)};
        *(uint4*)&Qs[r][kq] = qp;
        *(uint4*)&Ks[r][kq] = kp;
    }
    __syncthreads();

    float acc[2][8][4] = {};
    #pragma unroll
    for (int ks = 0; ks < 2; ks++) {
        const int k0 = ks*16;
        uint32_t ah[2][4], al[2][4];
        #pragma unroll
        for (int mi = 0; mi < 2; mi++) {
            const int m = warp_m*32 + mi*16;
            unzip(*(uint2*)&Qs[m+g8  ][k0 + 2*tig],     ah[mi][0], al[mi][0]);
            unzip(*(uint2*)&Qs[m+g8+8][k0 + 2*tig],     ah[mi][1], al[mi][1]);
            unzip(*(uint2*)&Qs[m+g8  ][k0 + 8 + 2*tig], ah[mi][2], al[mi][2]);
            unzip(*(uint2*)&Qs[m+g8+8][k0 + 8 + 2*tig], ah[mi][3], al[mi][3]);
        }
        #pragma unroll
        for (int ni = 0; ni < 8; ni++) {
            const int n = warp_n*64 + ni*8 + g8;
            uint32_t bh0, bl0, bh1, bl1;
            unzip(*(uint2*)&Ks[n][k0 + 2*tig],     bh0, bl0);
            unzip(*(uint2*)&Ks[n][k0 + 8 + 2*tig], bh1, bl1);
            #pragma unroll
            for (int mi = 0; mi < 2; mi++) {
                mma16(acc[mi][ni], ah[mi][0], ah[mi][1], ah[mi][2], ah[mi][3], bh0, bh1);
                mma16(acc[mi][ni], al[mi][0], al[mi][1], al[mi][2], al[mi][3], bh0, bh1);
            }
        }
    }
    #pragma unroll
    for (int mi = 0; mi < 2; mi++)
        #pragma unroll
        for (int ni = 0; ni < 8; ni++) {
            const int n = warp_n*64 + ni*8 + tig*2;
            #pragma unroll
            for (int hf = 0; hf < 2; hf++) {
                const int m = warp_m*32 + mi*16 + g8 + hf*8;
                float d0 = acc[mi][ni][hf*2], d1 = acc[mi][ni][hf*2+1];
                if (ISH) { if (n == m) d0 = neg_inf_f(); if (n+1 == m) d1 = neg_inf_f(); }
                O[(size_t)m*64 + n/2] = pack2(d0, d1);
            }
        }
}

// softmax: reads bf16 logits, writes bf16 att in place. grid 16384, block 256.
__global__ __launch_bounds__(256) void softmax_kernel()
{
    const int wid = blockIdx.x*8 + (threadIdx.x >> 5), lane = threadIdx.x & 31;
    const int b = wid >> 14, hw = wid & 16383, h = hw >> 7, w = hw & 127;
    const size_t rH = (size_t)(b*Wn + w)*Hh + h;
    const size_t rW = (size_t)(b*Hh + h)*Wn + w;
    uint32_t* aH = (uint32_t*)g_aH + rH*64;
    uint32_t* aW = (uint32_t*)g_aW + rW*64;
    uint2 uh = *(uint2*)(aH + lane*2);
    uint2 uw = *(uint2*)(aW + lane*2);
    float2 h01 = unpack2f(uh.x), h23 = unpack2f(uh.y);
    float2 w01 = unpack2f(uw.x), w23 = unpack2f(uw.y);
    float m = fmaxf(fmaxf(fmaxf(h01.x,h01.y),fmaxf(h23.x,h23.y)),
                    fmaxf(fmaxf(w01.x,w01.y),fmaxf(w23.x,w23.y)));
    #pragma unroll
    for (int off = 16; off; off >>= 1) m = fmaxf(m, __shfl_xor_sync(~0u, m, off));
    h01.x=__expf(h01.x-m); h01.y=__expf(h01.y-m); h23.x=__expf(h23.x-m); h23.y=__expf(h23.y-m);
    w01.x=__expf(w01.x-m); w01.y=__expf(w01.y-m); w23.x=__expf(w23.x-m); w23.y=__expf(w23.y-m);
    float s = h01.x+h01.y+h23.x+h23.y+w01.x+w01.y+w23.x+w23.y;
    #pragma unroll
    for (int off = 16; off; off >>= 1) s += __shfl_xor_sync(~0u, s, off);
    const float inv = 1.f/s;
    *(uint2*)(aH + lane*2) = make_uint2(pack2(h01.x*inv, h01.y*inv), pack2(h23.x*inv, h23.y*inv));
    *(uint2*)(aW + lane*2) = make_uint2(pack2(w01.x*inv, w01.y*inv), pack2(w23.x*inv, w23.y*inv));
}

// out<ISH>: D[128 spatial x 128 c] = att(bf16) @ v^T(bf16), 1-pass k16,
// ldmatrix fragment feeding. ISH: writes g_oH[b][h][w][c] (bf16).
// !ISH: adds oH and emits gamma*(D+oH)+x -> out. grid (2,1024), block 256.
template <bool ISH>
__global__ __launch_bounds__(256) void out_mma(const float* __restrict__ x,
                                               const float* __restrict__ gamma,
                                               float* __restrict__ out)
{
    __shared__ __align__(16) uint32_t sm[5120];   // As[128][20]@0, Bs@2560; tb[32][132] reuse
    const int t = threadIdx.x, wid = t >> 5, lane = t & 31;
    const int g8 = lane >> 2, tig = lane & 3;
    const int warp_m = wid & 3, warp_n = wid >> 2;
    const int bs = blockIdx.y, b = bs >> 7, s = bs & 127;
    const int c0 = blockIdx.x * 128;
    const uint32_t* A = (const uint32_t*)(ISH ? g_aH : g_aW) + (size_t)bs*128*64;
    const uint32_t* V = (const uint32_t*)(ISH ? g_vb : g_va) + (size_t)b*Cc*(HWn/2) + s*64;

    const uint32_t sbase = s2u(sm);
    const uint32_t aRow = (uint32_t)(lane & 15);
    const uint32_t aCol = (uint32_t)((lane >> 4) * 16);
    const uint32_t bRow = (uint32_t)((lane & 7) + ((lane >> 4) << 3));
    const uint32_t bCol = (uint32_t)(((lane >> 3) & 1) * 16);

    float acc[2][8][4] = {};
    const int r2 = t >> 1, wq = (t & 1)*8;
    for (int kc = 0; kc < 4; kc++) {
        uint4 a0 = *(const uint4*)(A + (size_t)r2*64 + kc*16 + wq);
        uint4 a1 = *(const uint4*)(A + (size_t)r2*64 + kc*16 + wq + 4);
        uint4 b0 = *(const uint4*)(V + (size_t)(c0 + r2)*(HWn/2) + kc*16 + wq);
        uint4 b1 = *(const uint4*)(V + (size_t)(c0 + r2)*(HWn/2) + kc*16 + wq + 4);
        __syncthreads();
        *(uint4*)&sm[r2*20 + wq]          = a0;
        *(uint4*)&sm[r2*20 + wq + 4]      = a1;
        *(uint4*)&sm[2560 + r2*20 + wq]   = b0;
        *(uint4*)&sm[2560 + r2*20 + wq+4] = b1;
        __syncthreads();
        #pragma unroll
        for (int ks = 0; ks < 2; ks++) {
            const uint32_t ksb = ks*32;
            uint32_t af[2][4], bf[4][4];
            #pragma unroll
            for (int mi = 0; mi < 2; mi++)
                ldm4(af[mi], sbase + (warp_m*32 + mi*16 + aRow)*80 + ksb + aCol);
            #pragma unroll
            for (int pi = 0; pi < 4; pi++)
                ldm4(bf[pi], sbase + 10240 + (warp_n*64 + pi*16 + bRow)*80 + ksb + bCol);
            #pragma unroll
            for (int pi = 0; pi < 4; pi++)
                #pragma unroll
                for (int half = 0; half < 2; half++) {
                    const int ni = pi*2 + half;
                    const uint32_t bb0 = bf[pi][half*2], bb1 = bf[pi][half*2 + 1];
                    #pragma unroll
                    for (int mi = 0; mi < 2; mi++)
                        mma16(acc[mi][ni], af[mi][0], af[mi][1], af[mi][2], af[mi][3], bb0, bb1);
                }
        }
    }

    if (ISH) {
        uint32_t* Ob = (uint32_t*)g_oH;
        #pragma unroll
        for (int mi = 0; mi < 2; mi++)
            #pragma unroll
            for (int ni = 0; ni < 8; ni++) {
                const int m = warp_m*32 + mi*16 + g8;
                const int n = c0 + warp_n*64 + ni*8 + tig*2;
                Ob[((size_t)(b*Hh + m)*Wn + s)*128 + n/2]   = pack2(acc[mi][ni][0], acc[mi][ni][1]);
                Ob[((size_t)(b*Hh + m+8)*Wn + s)*128 + n/2] = pack2(acc[mi][ni][2], acc[mi][ni][3]);
            }
    } else {
        const float gm = gamma[0];
        const uint32_t* o1 = (const uint32_t*)g_oH + (size_t)(b*Hh + s)*Wn*128;
        #pragma unroll
        for (int mi = 0; mi < 2; mi++)
            #pragma unroll
            for (int ni = 0; ni < 8; ni++) {
                const int m = warp_m*32 + mi*16 + g8;
                const int n = c0 + warp_n*64 + ni*8 + tig*2;
                float2 p0 = unpack2f(o1[(size_t)m*128 + n/2]);
                float2 p1 = unpack2f(o1[(size_t)(m+8)*128 + n/2]);
                acc[mi][ni][0] += p0.x; acc[mi][ni][1] += p0.y;
                acc[mi][ni][2] += p1.x; acc[mi][ni][3] += p1.y;
            }
        float* tb = (float*)sm;     // [32][132] floats
        #pragma unroll
        for (int cc = 0; cc < 4; cc++) {
            __syncthreads();
            if (warp_n == (cc >> 1)) {
                const int nib = (cc & 1)*4;
                #pragma unroll
                for (int mi = 0; mi < 2; mi++)
                    #pragma unroll
                    for (int nj = 0; nj < 4; nj++) {
                        const int ni = nib + nj;
                        const int nl = nj*8 + tig*2;
                        const int m = warp_m*32 + mi*16 + g8;
                        tb[nl*132 + m]       = acc[mi][ni][0];
                        tb[(nl+1)*132 + m]   = acc[mi][ni][1];
                        tb[nl*132 + m+8]     = acc[mi][ni][2];
                        tb[(nl+1)*132 + m+8] = acc[mi][ni][3];
                    }
            }
            __syncthreads();
            #pragma unroll
            for (int p = 0; p < 4; p++) {
                const int ci = (t >> 5) + p*8;
                const int w4 = (t & 31)*4;
                const size_t oidx = ((size_t)(b*Cc + c0 + cc*32 + ci)*Hh + s)*Wn + w4;
                float4 xr = *(const float4*)(x + oidx);
                float4 r;
                r.x = gm*tb[ci*132 + w4  ] + xr.x;
                r.y = gm*tb[ci*132 + w4+1] + xr.y;
                r.z = gm*tb[ci*132 + w4+2] + xr.z;
                r.w = gm*tb[ci*132 + w4+3] + xr.w;
                *(float4*)(out + oidx) = r;
            }
        }
    }
}

extern "C" void kernel_launch(void* const* d_in, const int* in_sizes, int n_in,
                              void* d_out, int out_size)
{
    const float* x     = (const float*)d_in[0];
    const float* Wq    = (const float*)d_in[1];
    const float* bq    = (const float*)d_in[2];
    const float* Wk    = (const float*)d_in[3];
    const float* bk    = (const float*)d_in[4];
    const float* Wv    = (const float*)d_in[5];
    const float* bv    = (const float*)d_in[6];
    const float* gamma = (const float*)d_in[7];
    float* out = (float*)d_out;

    prep_kernel<<<320, 256>>>(Wq, bq, Wk, bk, Wv, bv);
    xt_kernel<<<dim3(512, 8, 8), 256>>>(x);
    proj_mma<<<dim3(5, 128, 8), 256>>>();
    vb_kernel<<<dim3(2, 2, Bn*Cc), 256>>>();
    score_mma<true ><<<1024, 256>>>();
    score_mma<false><<<1024, 256>>>();
    softmax_kernel<<<16384, 256>>>();
    out_mma<true ><<<dim3(2, 1024), 256>>>(x, gamma, out);
    out_mma<false><<<dim3(2, 1024), 256>>>(x, gamma, out);
}